// round 6
// baseline (speedup 1.0000x reference)
#include <cuda_runtime.h>
#include <cuda_bf16.h>
#include <math.h>

#define Bsz 256
#define Lsz 24
#define Rsz 49
#define Fsz 2048
#define Esz 256
#define Hsz 512
#define Asz 512
#define Vsz 10000
#define STEPS 23
#define G4 2048         // 4*H
#define GK2 2560        // F + H  (gates K after emb hoist)
#define VPAD 10112      // V padded to 128
#define MROWS (STEPS * Bsz)   // 5888
#define NFEAT (Bsz * Rsz * Fsz)

typedef __nv_bfloat16 bf16;

// ---------------- scratch (static device globals) ----------------
__device__ float g_fproj[Bsz * Rsz * Asz];
__device__ bf16  g_featH[NFEAT], g_featL[NFEAT];
__device__ bf16  g_meanH[Bsz * Fsz], g_meanL[Bsz * Fsz];
__device__ bf16  g_WfH[Asz * Fsz],  g_WfL[Asz * Fsz];
__device__ bf16  g_WhH[Asz * Hsz],  g_WhL[Asz * Hsz];
__device__ bf16  g_Wg2H[G4 * GK2],  g_Wg2L[G4 * GK2];     // [W_ih[:,E:] | W_hh]
__device__ bf16  g_WihEH[G4 * Esz], g_WihEL[G4 * Esz];    // W_ih[:, :E]
__device__ bf16  g_WiH[1024 * Fsz], g_WiL[1024 * Fsz];
__device__ float g_bi[1024];
__device__ bf16  g_WfcH[VPAD * Hsz], g_WfcL[VPAD * Hsz];
__device__ float g_h0c0[Bsz * 1024];
__device__ float g_c[Bsz * Hsz];
__device__ bf16  g_xhH[Bsz * GK2], g_xhL[Bsz * GK2];      // [ctx | h]
__device__ bf16  g_embAH[MROWS * Esz], g_embAL[MROWS * Esz];
__device__ float g_embproj[MROWS * G4];
__device__ bf16  g_histH[MROWS * Hsz], g_histL[MROWS * Hsz];
__device__ float g_gpart[4 * Bsz * G4];
__device__ float g_hppart[4 * Bsz * Asz];

__device__ __forceinline__ void split2(float x, bf16& h, bf16& l) {
    h = __float2bfloat16(x);
    l = __float2bfloat16(x - __bfloat162float(h));
}

__device__ __forceinline__ void mma_bf16(float* c, const unsigned* a, const unsigned* b) {
    asm volatile(
        "mma.sync.aligned.m16n8k16.row.col.f32.bf16.bf16.f32 "
        "{%0,%1,%2,%3},{%4,%5,%6,%7},{%8,%9},{%0,%1,%2,%3};\n"
        : "+f"(c[0]), "+f"(c[1]), "+f"(c[2]), "+f"(c[3])
        : "r"(a[0]), "r"(a[1]), "r"(a[2]), "r"(a[3]), "r"(b[0]), "r"(b[1]));
}

__device__ __forceinline__ void ldsm_x4(unsigned& r0, unsigned& r1, unsigned& r2, unsigned& r3,
                                        unsigned addr) {
    asm volatile("ldmatrix.sync.aligned.m8n8.x4.shared.b16 {%0,%1,%2,%3},[%4];"
                 : "=r"(r0), "=r"(r1), "=r"(r2), "=r"(r3) : "r"(addr));
}
__device__ __forceinline__ void ldsm_x2(unsigned& r0, unsigned& r1, unsigned addr) {
    asm volatile("ldmatrix.sync.aligned.m8n8.x2.shared.b16 {%0,%1},[%2];"
                 : "=r"(r0), "=r"(r1) : "r"(addr));
}

// ---------------------------------------------------------------------------
// Tensor-core GEMM: C(M,N) = epi( A(M,K) @ B(N,K)^T ), split-bf16 3-term.
// Block tile 128x128, BK=32, 8 warps (2x4), warp tile 64x32, ldmatrix feeds.
// EPI: 0 = +bias store
//      1 = raw store (split-K partial at z*M*N), optional length-skip (t>=0)
//      2 = final fc: row->(t,b) map, ragged mask, bias, zero fast path
//      3 = tanh(+bias)
// ---------------------------------------------------------------------------
template <int EPI>
__global__ __launch_bounds__(256) void mma_gemm(
    const bf16* __restrict__ Ah, const bf16* __restrict__ Al,
    const bf16* __restrict__ Bh, const bf16* __restrict__ Bl,
    const float* __restrict__ bias, float* __restrict__ C,
    int M, int N, int lda, int ldb, int kspl,
    const int* __restrict__ lengths, int t)
{
    const int m0 = blockIdx.y * 128;
    const int n0 = blockIdx.x * 128;
    const int tid = threadIdx.x;

    if (EPI == 1) {
        if (t >= 0 && lengths[m0] <= t) return;
    }
    if (EPI == 2) {
        int tt = m0 >> 8, b0 = m0 & 255;
        if (lengths[b0] <= tt) {
            for (int i = tid; i < 128 * 128; i += 256) {
                int r = i >> 7, cc = i & 127;
                int n = n0 + cc;
                if (n < Vsz) {
                    int b = b0 + r;
                    C[((size_t)b * STEPS + tt) * Vsz + n] = 0.f;
                }
            }
            return;
        }
    }

    __shared__ __align__(16) bf16 sAh[128 * 40];
    __shared__ __align__(16) bf16 sAl[128 * 40];
    __shared__ __align__(16) bf16 sBh[128 * 40];
    __shared__ __align__(16) bf16 sBl[128 * 40];

    const int lane = tid & 31, warp = tid >> 5;
    const int wm = warp >> 2, wn = warp & 3;   // 2 x 4
    const int grp = lane >> 2, tig = lane & 3;

    float acc[4][4][4] = {};

    const int kbase = (EPI == 1) ? blockIdx.z * kspl : 0;

    uint4* s4Ah = (uint4*)sAh; uint4* s4Al = (uint4*)sAl;
    uint4* s4Bh = (uint4*)sBh; uint4* s4Bl = (uint4*)sBl;
    unsigned bAh = (unsigned)__cvta_generic_to_shared(sAh);
    unsigned bAl = (unsigned)__cvta_generic_to_shared(sAl);
    unsigned bBh = (unsigned)__cvta_generic_to_shared(sBh);
    unsigned bBl = (unsigned)__cvta_generic_to_shared(sBl);

    const int ldr = tid >> 2;          // 0..63 (row, +64 on second pass)
    const int ldc = tid & 3;           // quad within row

    for (int kc = 0; kc < kspl; kc += 32) {
        const int kg = kbase + kc;
        uint4 vah[2], val_[2], vbh[2], vbl[2];
#pragma unroll
        for (int i = 0; i < 2; i++) {
            int r = ldr + i * 64;
            size_t ga = (size_t)(m0 + r) * lda + kg + ldc * 8;
            size_t gb = (size_t)(n0 + r) * ldb + kg + ldc * 8;
            vah[i]  = *(const uint4*)(Ah + ga);
            val_[i] = *(const uint4*)(Al + ga);
            vbh[i]  = *(const uint4*)(Bh + gb);
            vbl[i]  = *(const uint4*)(Bl + gb);
        }
        __syncthreads();
#pragma unroll
        for (int i = 0; i < 2; i++) {
            int r = ldr + i * 64;
            s4Ah[r * 5 + ldc] = vah[i];
            s4Al[r * 5 + ldc] = val_[i];
            s4Bh[r * 5 + ldc] = vbh[i];
            s4Bl[r * 5 + ldc] = vbl[i];
        }
        __syncthreads();

#pragma unroll
        for (int k16 = 0; k16 < 2; k16++) {
            const int aro = wm * 64 + (lane & 15);
            const int aco = k16 * 16 + ((lane >> 4) << 3);
            const int bro = wn * 32 + (lane & 7);
            const int bco = k16 * 16 + (((lane >> 3) & 1) << 3);

            unsigned ah[4][4], al[4][4], bh2[4][2], bl2[4][2];
#pragma unroll
            for (int mt = 0; mt < 4; mt++) {
                unsigned off = (unsigned)(((aro + mt * 16) * 40 + aco) * 2);
                ldsm_x4(ah[mt][0], ah[mt][1], ah[mt][2], ah[mt][3], bAh + off);
                ldsm_x4(al[mt][0], al[mt][1], al[mt][2], al[mt][3], bAl + off);
            }
#pragma unroll
            for (int nt = 0; nt < 4; nt++) {
                unsigned off = (unsigned)(((bro + nt * 8) * 40 + bco) * 2);
                ldsm_x2(bh2[nt][0], bh2[nt][1], bBh + off);
                ldsm_x2(bl2[nt][0], bl2[nt][1], bBl + off);
            }
#pragma unroll
            for (int nt = 0; nt < 4; nt++)
#pragma unroll
                for (int mt = 0; mt < 4; mt++) {
                    mma_bf16(acc[mt][nt], ah[mt], bh2[nt]);
                    mma_bf16(acc[mt][nt], al[mt], bh2[nt]);
                    mma_bf16(acc[mt][nt], ah[mt], bl2[nt]);
                }
        }
    }

    // -------- epilogue --------
    float* Cp = C;
    if (EPI == 1) Cp = C + (size_t)blockIdx.z * M * N;

#pragma unroll
    for (int mt = 0; mt < 4; mt++) {
#pragma unroll
        for (int nt = 0; nt < 4; nt++) {
            int row = m0 + wm * 64 + mt * 16 + grp;
            int col = n0 + wn * 32 + nt * 8 + tig * 2;
            float* a = acc[mt][nt];
            if (EPI == 0) {
                Cp[(size_t)row * N + col]           = a[0] + bias[col];
                Cp[(size_t)row * N + col + 1]       = a[1] + bias[col + 1];
                Cp[(size_t)(row + 8) * N + col]     = a[2] + bias[col];
                Cp[(size_t)(row + 8) * N + col + 1] = a[3] + bias[col + 1];
            } else if (EPI == 3) {
                Cp[(size_t)row * N + col]           = tanhf(a[0] + bias[col]);
                Cp[(size_t)row * N + col + 1]       = tanhf(a[1] + bias[col + 1]);
                Cp[(size_t)(row + 8) * N + col]     = tanhf(a[2] + bias[col]);
                Cp[(size_t)(row + 8) * N + col + 1] = tanhf(a[3] + bias[col + 1]);
            } else if (EPI == 1) {
                Cp[(size_t)row * N + col]           = a[0];
                Cp[(size_t)row * N + col + 1]       = a[1];
                Cp[(size_t)(row + 8) * N + col]     = a[2];
                Cp[(size_t)(row + 8) * N + col + 1] = a[3];
            } else { // EPI == 2
                if (col < Vsz) {
                    int b0r = row & 255, tt0 = row >> 8;
                    int b1r = (row + 8) & 255, tt1 = (row + 8) >> 8;
                    bool act0 = lengths[b0r] > tt0;
                    bool act1 = lengths[b1r] > tt1;
                    float* p0 = C + ((size_t)b0r * STEPS + tt0) * Vsz;
                    float* p1 = C + ((size_t)b1r * STEPS + tt1) * Vsz;
                    p0[col]     = act0 ? (a[0] + bias[col])     : 0.f;
                    p0[col + 1] = act0 ? (a[1] + bias[col + 1]) : 0.f;
                    p1[col]     = act1 ? (a[2] + bias[col])     : 0.f;
                    p1[col + 1] = act1 ? (a[3] + bias[col + 1]) : 0.f;
                }
            }
        }
    }
}

// ---------------------------------------------------------------------------
// conversion / setup kernels
// ---------------------------------------------------------------------------
__global__ void split_arr(const float* __restrict__ src, bf16* __restrict__ h,
                          bf16* __restrict__ l, int n)
{
    for (int i = blockIdx.x * blockDim.x + threadIdx.x; i < n; i += gridDim.x * blockDim.x)
        split2(src[i], h[i], l[i]);
}

__global__ void build_Wg2(const float* __restrict__ Wih, const float* __restrict__ Whh,
                          bf16* __restrict__ h, bf16* __restrict__ l,
                          bf16* __restrict__ eh, bf16* __restrict__ el)
{
    for (int i = blockIdx.x * blockDim.x + threadIdx.x; i < G4 * GK2; i += gridDim.x * blockDim.x) {
        int r = i / GK2, cc = i % GK2;
        float v = (cc < Fsz) ? Wih[(size_t)r * (Esz + Fsz) + Esz + cc]
                             : Whh[(size_t)r * Hsz + cc - Fsz];
        split2(v, h[i], l[i]);
    }
    for (int i = blockIdx.x * blockDim.x + threadIdx.x; i < G4 * Esz; i += gridDim.x * blockDim.x) {
        int r = i / Esz, cc = i % Esz;
        split2(Wih[(size_t)r * (Esz + Fsz) + cc], eh[i], el[i]);
    }
}

__global__ void build_Wi(const float* __restrict__ Wih, const float* __restrict__ Wic,
                         const float* __restrict__ bih, const float* __restrict__ bic,
                         bf16* __restrict__ h, bf16* __restrict__ l, float* __restrict__ bi)
{
    for (int i = blockIdx.x * blockDim.x + threadIdx.x; i < 1024 * Fsz; i += gridDim.x * blockDim.x) {
        int r = i / Fsz, cc = i % Fsz;
        float v = (r < Hsz) ? Wih[(size_t)r * Fsz + cc] : Wic[(size_t)(r - Hsz) * Fsz + cc];
        split2(v, h[i], l[i]);
        if (i < 1024) bi[i] = (i < Hsz) ? bih[i] : bic[i - Hsz];
    }
}

__global__ void build_Wfc(const float* __restrict__ W, bf16* __restrict__ h, bf16* __restrict__ l)
{
    for (int i = blockIdx.x * blockDim.x + threadIdx.x; i < VPAD * Hsz; i += gridDim.x * blockDim.x) {
        int r = i / Hsz;
        float v = (r < Vsz) ? W[i] : 0.f;
        split2(v, h[i], l[i]);
    }
}

__global__ void build_embA(const float* __restrict__ embW, const int* __restrict__ ids,
                           bf16* __restrict__ h, bf16* __restrict__ l)
{
    for (int i = blockIdx.x * blockDim.x + threadIdx.x; i < MROWS * Esz; i += gridDim.x * blockDim.x) {
        int r = i >> 8, e = i & 255;         // Esz == 256
        int tt = r >> 8, b = r & 255;
        int id = ids[b * Lsz + tt];
        split2(embW[(size_t)id * Esz + e], h[i], l[i]);
    }
}

__global__ void mean_split(const float* __restrict__ feats, bf16* __restrict__ mh,
                           bf16* __restrict__ ml)
{
    int b = blockIdx.x;
    for (int f = threadIdx.x; f < Fsz; f += blockDim.x) {
        float s = 0.f;
        for (int r = 0; r < Rsz; r++) s += feats[(size_t)(b * Rsz + r) * Fsz + f];
        split2(s * (1.0f / Rsz), mh[b * Fsz + f], ml[b * Fsz + f]);
    }
}

__global__ void init_state()
{
    int idx = blockIdx.x * blockDim.x + threadIdx.x;   // B*H
    int b = idx >> 9, j = idx & 511;
    float h = g_h0c0[b * 1024 + j];
    float c = g_h0c0[b * 1024 + 512 + j];
    g_c[idx] = c;
    split2(h, g_xhH[b * GK2 + Fsz + j], g_xhL[b * GK2 + Fsz + j]);
}

// ---------------------------------------------------------------------------
// Fused attention: sum hp split-K parts (+bh), scores, softmax, ctx -> xh
// ---------------------------------------------------------------------------
__global__ __launch_bounds__(256) void attn_kernel(
    const float* __restrict__ feats, const float* __restrict__ Ws,
    const float* __restrict__ bs, const float* __restrict__ bh,
    const int* __restrict__ lengths, int t)
{
    int b = blockIdx.x;
    if (lengths[b] <= t) return;

    __shared__ float hp_s[Asz];
    __shared__ float ws_s[Asz];
    __shared__ float sc_s[64];

    const int MN = Bsz * Asz;
    int tid = threadIdx.x;
#pragma unroll
    for (int i = 0; i < 2; i++) {
        int a = tid + i * 256;
        hp_s[a] = g_hppart[b * Asz + a] + g_hppart[MN + b * Asz + a]
                + g_hppart[2 * MN + b * Asz + a] + g_hppart[3 * MN + b * Asz + a]
                + bh[a];
        ws_s[a] = Ws[a];
    }
    __syncthreads();

    int warp = tid >> 5, lane = tid & 31;
    for (int r = warp; r < Rsz; r += 8) {
        const float* fp = &g_fproj[(size_t)(b * Rsz + r) * Asz];
        float s = 0.f;
        for (int a = lane; a < Asz; a += 32)
            s += tanhf(fp[a] + hp_s[a]) * ws_s[a];
#pragma unroll
        for (int o = 16; o; o >>= 1) s += __shfl_down_sync(0xffffffffu, s, o);
        if (lane == 0) sc_s[r] = s + bs[0];
    }
    __syncthreads();

    if (warp == 0) {
        float v1 = (lane < Rsz) ? sc_s[lane] : -INFINITY;
        float v2 = (lane + 32 < Rsz) ? sc_s[lane + 32] : -INFINITY;
        float mx = fmaxf(v1, v2);
#pragma unroll
        for (int o = 16; o; o >>= 1) mx = fmaxf(mx, __shfl_xor_sync(0xffffffffu, mx, o));
        float e1 = (lane < Rsz) ? expf(v1 - mx) : 0.f;
        float e2 = (lane + 32 < Rsz) ? expf(v2 - mx) : 0.f;
        float sm = e1 + e2;
#pragma unroll
        for (int o = 16; o; o >>= 1) sm += __shfl_xor_sync(0xffffffffu, sm, o);
        float inv = 1.f / sm;
        if (lane < Rsz) sc_s[lane] = e1 * inv;
        if (lane + 32 < Rsz) sc_s[lane + 32] = e2 * inv;
    }
    __syncthreads();

    for (int f = tid; f < Fsz; f += 256) {
        float acc = 0.f;
#pragma unroll 7
        for (int r = 0; r < Rsz; r++)
            acc = fmaf(sc_s[r], feats[(size_t)(b * Rsz + r) * Fsz + f], acc);
        split2(acc, g_xhH[b * GK2 + f], g_xhL[b * GK2 + f]);
    }
}

// ---------------------------------------------------------------------------
// LSTM pointwise: 4 gate parts + embproj + biases -> c,h; h to xh + history
// ---------------------------------------------------------------------------
__global__ void lstm_pw(const float* __restrict__ bih, const float* __restrict__ bhh,
                        const int* __restrict__ lengths, int t)
{
    int idx = blockIdx.x * blockDim.x + threadIdx.x;   // B*H
    int b = idx >> 9, j = idx & 511;
    if (lengths[b] <= t) return;
    const int MN = Bsz * G4;
    int base = b * G4;
    const float* ep = &g_embproj[(size_t)(t * Bsz + b) * G4];

    float gv[4];
#pragma unroll
    for (int q = 0; q < 4; q++) {
        int jj = q * 512 + j;
        gv[q] = g_gpart[base + jj] + g_gpart[MN + base + jj]
              + g_gpart[2 * MN + base + jj] + g_gpart[3 * MN + base + jj]
              + ep[jj] + bih[jj] + bhh[jj];
    }
    float ig = 1.f / (1.f + expf(-gv[0]));
    float fg = 1.f / (1.f + expf(-gv[1]));
    float g  = tanhf(gv[2]);
    float og = 1.f / (1.f + expf(-gv[3]));
    float cn = fg * g_c[idx] + ig * g;
    float hn = og * tanhf(cn);
    g_c[idx] = cn;
    split2(hn, g_xhH[b * GK2 + Fsz + j], g_xhL[b * GK2 + Fsz + j]);
    split2(hn, g_histH[(size_t)(t * Bsz + b) * Hsz + j],
               g_histL[(size_t)(t * Bsz + b) * Hsz + j]);
}

// ---------------------------------------------------------------------------
extern "C" void kernel_launch(void* const* d_in, const int* in_sizes, int n_in,
                              void* d_out, int out_size)
{
    const float* feats   = (const float*)d_in[0];
    const int*   ids     = (const int*)  d_in[1];
    const int*   lengths = (const int*)  d_in[2];
    const float* embW    = (const float*)d_in[3];
    const float* Wf      = (const float*)d_in[4];
    const float* bf      = (const float*)d_in[5];
    const float* Wh      = (const float*)d_in[6];
    const float* bh      = (const float*)d_in[7];
    const float* Ws      = (const float*)d_in[8];
    const float* bs      = (const float*)d_in[9];
    const float* W_ih    = (const float*)d_in[10];
    const float* b_ih    = (const float*)d_in[11];
    const float* W_hh    = (const float*)d_in[12];
    const float* b_hh    = (const float*)d_in[13];
    const float* Wfc     = (const float*)d_in[14];
    const float* bfc     = (const float*)d_in[15];
    const float* Wi_h    = (const float*)d_in[16];
    const float* bi_h    = (const float*)d_in[17];
    const float* Wi_c    = (const float*)d_in[18];
    const float* bi_c    = (const float*)d_in[19];
    float* out = (float*)d_out;

    void *pv;
    cudaGetSymbolAddress(&pv, g_featH);  bf16* featH = (bf16*)pv;
    cudaGetSymbolAddress(&pv, g_featL);  bf16* featL = (bf16*)pv;
    cudaGetSymbolAddress(&pv, g_meanH);  bf16* meanH = (bf16*)pv;
    cudaGetSymbolAddress(&pv, g_meanL);  bf16* meanL = (bf16*)pv;
    cudaGetSymbolAddress(&pv, g_WfH);    bf16* WfH = (bf16*)pv;
    cudaGetSymbolAddress(&pv, g_WfL);    bf16* WfL = (bf16*)pv;
    cudaGetSymbolAddress(&pv, g_WhH);    bf16* WhH = (bf16*)pv;
    cudaGetSymbolAddress(&pv, g_WhL);    bf16* WhL = (bf16*)pv;
    cudaGetSymbolAddress(&pv, g_Wg2H);   bf16* Wg2H = (bf16*)pv;
    cudaGetSymbolAddress(&pv, g_Wg2L);   bf16* Wg2L = (bf16*)pv;
    cudaGetSymbolAddress(&pv, g_WihEH);  bf16* WihEH = (bf16*)pv;
    cudaGetSymbolAddress(&pv, g_WihEL);  bf16* WihEL = (bf16*)pv;
    cudaGetSymbolAddress(&pv, g_WiH);    bf16* WiH = (bf16*)pv;
    cudaGetSymbolAddress(&pv, g_WiL);    bf16* WiL = (bf16*)pv;
    cudaGetSymbolAddress(&pv, g_bi);     float* bi = (float*)pv;
    cudaGetSymbolAddress(&pv, g_WfcH);   bf16* WfcH = (bf16*)pv;
    cudaGetSymbolAddress(&pv, g_WfcL);   bf16* WfcL = (bf16*)pv;
    cudaGetSymbolAddress(&pv, g_h0c0);   float* h0c0 = (float*)pv;
    cudaGetSymbolAddress(&pv, g_xhH);    bf16* xhH = (bf16*)pv;
    cudaGetSymbolAddress(&pv, g_xhL);    bf16* xhL = (bf16*)pv;
    cudaGetSymbolAddress(&pv, g_embAH);  bf16* embAH = (bf16*)pv;
    cudaGetSymbolAddress(&pv, g_embAL);  bf16* embAL = (bf16*)pv;
    cudaGetSymbolAddress(&pv, g_embproj);float* embproj = (float*)pv;
    cudaGetSymbolAddress(&pv, g_histH);  bf16* histH = (bf16*)pv;
    cudaGetSymbolAddress(&pv, g_histL);  bf16* histL = (bf16*)pv;
    cudaGetSymbolAddress(&pv, g_fproj);  float* fproj = (float*)pv;
    cudaGetSymbolAddress(&pv, g_gpart);  float* gpart = (float*)pv;
    cudaGetSymbolAddress(&pv, g_hppart); float* hppart = (float*)pv;

    // ---- conversions ----
    split_arr<<<1024, 256>>>(feats, featH, featL, NFEAT);
    split_arr<<<256, 256>>>(Wf, WfH, WfL, Asz * Fsz);
    split_arr<<<128, 256>>>(Wh, WhH, WhL, Asz * Hsz);
    build_Wg2<<<512, 256>>>(W_ih, W_hh, Wg2H, Wg2L, WihEH, WihEL);
    build_Wi<<<256, 256>>>(Wi_h, Wi_c, bi_h, bi_c, WiH, WiL, bi);
    build_Wfc<<<512, 256>>>(Wfc, WfcH, WfcL);
    build_embA<<<256, 256>>>(embW, ids, embAH, embAL);
    mean_split<<<Bsz, 256>>>(feats, meanH, meanL);

    // ---- init state ----
    mma_gemm<3><<<dim3(8, 2, 1), 256>>>(meanH, meanL, WiH, WiL, bi, h0c0,
                                        Bsz, 1024, Fsz, Fsz, Fsz, nullptr, 0);
    init_state<<<(Bsz * Hsz) / 256, 256>>>();

    // ---- f_proj = feats @ Wf^T + bf ----
    mma_gemm<0><<<dim3(4, 98, 1), 256>>>(featH, featL, WfH, WfL, bf, fproj,
                                         Bsz * Rsz, Asz, Fsz, Fsz, Fsz, nullptr, 0);

    // ---- embproj = embAll @ W_ih[:, :E]^T  (all steps at once) ----
    mma_gemm<1><<<dim3(16, 46, 1), 256>>>(embAH, embAL, WihEH, WihEL, nullptr, embproj,
                                          MROWS, G4, Esz, Esz, Esz, lengths, -1);

    // ---- timesteps ----
    for (int t = 0; t < STEPS; t++) {
        // hp partials = h @ Wh^T  (split-K 4)
        mma_gemm<1><<<dim3(4, 2, 4), 256>>>(xhH + Fsz, xhL + Fsz, WhH, WhL, nullptr, hppart,
                                            Bsz, Asz, GK2, Hsz, Hsz / 4, lengths, t);
        attn_kernel<<<Bsz, 256>>>(feats, Ws, bs, bh, lengths, t);
        // gate partials = [ctx|h] @ Wg2^T (split-K 4)
        mma_gemm<1><<<dim3(16, 2, 4), 256>>>(xhH, xhL, Wg2H, Wg2L, nullptr, gpart,
                                             Bsz, G4, GK2, GK2, GK2 / 4, lengths, t);
        lstm_pw<<<(Bsz * Hsz) / 256, 256>>>(b_ih, b_hh, lengths, t);
    }

    // ---- final FC over all (t, b): out = h_hist @ Wfc^T + bfc (ragged) ----
    mma_gemm<2><<<dim3(VPAD / 128, MROWS / 128, 1), 256>>>(
        histH, histL, WfcH, WfcL, bfc, out,
        MROWS, VPAD, Hsz, Hsz, Hsz, lengths, 0);
}

// round 7
// speedup vs baseline: 1.2367x; 1.2367x over previous
#include <cuda_runtime.h>
#include <cuda_bf16.h>
#include <math.h>

#define Bsz 256
#define Lsz 24
#define Rsz 49
#define Fsz 2048
#define Esz 256
#define Hsz 512
#define Asz 512
#define Vsz 10000
#define STEPS 23
#define G4 2048         // 4*H
#define GK2 2560        // F + H  (gates K after emb hoist)
#define VPAD 10112      // V padded to 128
#define MROWS (STEPS * Bsz)   // 5888
#define NFEAT (Bsz * Rsz * Fsz)
#define PGRID 128       // persistent kernel grid (<= SM count: co-resident)

typedef __nv_bfloat16 bf16;

// ---------------- scratch (static device globals) ----------------
__device__ float g_fproj[Bsz * Rsz * Asz];
__device__ bf16  g_featH[NFEAT], g_featL[NFEAT];
__device__ bf16  g_meanH[Bsz * Fsz], g_meanL[Bsz * Fsz];
__device__ bf16  g_WfH[Asz * Fsz],  g_WfL[Asz * Fsz];
__device__ bf16  g_WhH[Asz * Hsz],  g_WhL[Asz * Hsz];
__device__ bf16  g_Wg2H[G4 * GK2],  g_Wg2L[G4 * GK2];     // [W_ih[:,E:] | W_hh]
__device__ bf16  g_WihEH[G4 * Esz], g_WihEL[G4 * Esz];    // W_ih[:, :E]
__device__ bf16  g_WiH[1024 * Fsz], g_WiL[1024 * Fsz];
__device__ float g_bi[1024];
__device__ bf16  g_WfcH[VPAD * Hsz], g_WfcL[VPAD * Hsz];
__device__ float g_h0c0[Bsz * 1024];
__device__ float g_c[Bsz * Hsz];
__device__ bf16  g_xhH[Bsz * GK2], g_xhL[Bsz * GK2];      // [ctx | h]
__device__ bf16  g_embAH[MROWS * Esz], g_embAL[MROWS * Esz];
__device__ float g_embproj[MROWS * G4];
__device__ bf16  g_histH[MROWS * Hsz], g_histL[MROWS * Hsz];
__device__ float g_gpart[4 * Bsz * G4];
__device__ float g_hppart[2 * Bsz * Asz];

// grid barrier state
__device__ unsigned g_bar_count = 0;
__device__ unsigned g_bar_gen = 0;

__device__ __forceinline__ void split2(float x, bf16& h, bf16& l) {
    h = __float2bfloat16(x);
    l = __float2bfloat16(x - __bfloat162float(h));
}

__device__ __forceinline__ void mma_bf16(float* c, const unsigned* a, const unsigned* b) {
    asm volatile(
        "mma.sync.aligned.m16n8k16.row.col.f32.bf16.bf16.f32 "
        "{%0,%1,%2,%3},{%4,%5,%6,%7},{%8,%9},{%0,%1,%2,%3};\n"
        : "+f"(c[0]), "+f"(c[1]), "+f"(c[2]), "+f"(c[3])
        : "r"(a[0]), "r"(a[1]), "r"(a[2]), "r"(a[3]), "r"(b[0]), "r"(b[1]));
}

__device__ __forceinline__ void ldsm_x4(unsigned& r0, unsigned& r1, unsigned& r2, unsigned& r3,
                                        unsigned addr) {
    asm volatile("ldmatrix.sync.aligned.m8n8.x4.shared.b16 {%0,%1,%2,%3},[%4];"
                 : "=r"(r0), "=r"(r1), "=r"(r2), "=r"(r3) : "r"(addr));
}
__device__ __forceinline__ void ldsm_x2(unsigned& r0, unsigned& r1, unsigned addr) {
    asm volatile("ldmatrix.sync.aligned.m8n8.x2.shared.b16 {%0,%1},[%2];"
                 : "=r"(r0), "=r"(r1) : "r"(addr));
}

// sense-reversing grid barrier (all CTAs must call; co-resident grid)
__device__ __forceinline__ void gsync() {
    __syncthreads();
    if (threadIdx.x == 0) {
        __threadfence();
        unsigned gen = *((volatile unsigned*)&g_bar_gen);
        if (atomicAdd(&g_bar_count, 1u) == gridDim.x - 1) {
            *((volatile unsigned*)&g_bar_count) = 0;
            __threadfence();
            atomicAdd(&g_bar_gen, 1u);
        } else {
            while (*((volatile unsigned*)&g_bar_gen) == gen) { }
            __threadfence();
        }
    }
    __syncthreads();
}

// ---------------------------------------------------------------------------
// Device-side 128x128 mma tile, K slice [kbase, kbase+kcnt), raw store to C(N).
// Needs all 256 threads of the CTA; sm = 4 * 5120 bf16 workspace.
// ---------------------------------------------------------------------------
__device__ void mma_tile(
    const bf16* __restrict__ Ah, const bf16* __restrict__ Al,
    const bf16* __restrict__ Bh, const bf16* __restrict__ Bl,
    int m0, int n0, int lda, int ldb, int kbase, int kcnt,
    float* __restrict__ C, int N, bf16* sm)
{
    bf16* sAh = sm;
    bf16* sAl = sm + 5120;
    bf16* sBh = sm + 10240;
    bf16* sBl = sm + 15360;
    uint4* s4Ah = (uint4*)sAh; uint4* s4Al = (uint4*)sAl;
    uint4* s4Bh = (uint4*)sBh; uint4* s4Bl = (uint4*)sBl;
    unsigned bAh = (unsigned)__cvta_generic_to_shared(sAh);
    unsigned bAl = (unsigned)__cvta_generic_to_shared(sAl);
    unsigned bBh = (unsigned)__cvta_generic_to_shared(sBh);
    unsigned bBl = (unsigned)__cvta_generic_to_shared(sBl);

    const int tid = threadIdx.x;
    const int lane = tid & 31, warp = tid >> 5;
    const int wm = warp >> 2, wn = warp & 3;
    const int grp = lane >> 2, tig = lane & 3;
    const int ldr = tid >> 2, ldc = tid & 3;

    float acc[4][4][4] = {};

    for (int kc = 0; kc < kcnt; kc += 32) {
        const int kg = kbase + kc;
        uint4 vah[2], val_[2], vbh[2], vbl[2];
#pragma unroll
        for (int i = 0; i < 2; i++) {
            int r = ldr + i * 64;
            size_t ga = (size_t)(m0 + r) * lda + kg + ldc * 8;
            size_t gb = (size_t)(n0 + r) * ldb + kg + ldc * 8;
            vah[i]  = *(const uint4*)(Ah + ga);
            val_[i] = *(const uint4*)(Al + ga);
            vbh[i]  = *(const uint4*)(Bh + gb);
            vbl[i]  = *(const uint4*)(Bl + gb);
        }
        __syncthreads();
#pragma unroll
        for (int i = 0; i < 2; i++) {
            int r = ldr + i * 64;
            s4Ah[r * 5 + ldc] = vah[i];
            s4Al[r * 5 + ldc] = val_[i];
            s4Bh[r * 5 + ldc] = vbh[i];
            s4Bl[r * 5 + ldc] = vbl[i];
        }
        __syncthreads();

#pragma unroll
        for (int k16 = 0; k16 < 2; k16++) {
            const int aro = wm * 64 + (lane & 15);
            const int aco = k16 * 16 + ((lane >> 4) << 3);
            const int bro = wn * 32 + (lane & 7);
            const int bco = k16 * 16 + (((lane >> 3) & 1) << 3);

            unsigned ah[4][4], al[4][4], bh2[4][2], bl2[4][2];
#pragma unroll
            for (int mt = 0; mt < 4; mt++) {
                unsigned off = (unsigned)(((aro + mt * 16) * 40 + aco) * 2);
                ldsm_x4(ah[mt][0], ah[mt][1], ah[mt][2], ah[mt][3], bAh + off);
                ldsm_x4(al[mt][0], al[mt][1], al[mt][2], al[mt][3], bAl + off);
            }
#pragma unroll
            for (int nt = 0; nt < 4; nt++) {
                unsigned off = (unsigned)(((bro + nt * 8) * 40 + bco) * 2);
                ldsm_x2(bh2[nt][0], bh2[nt][1], bBh + off);
                ldsm_x2(bl2[nt][0], bl2[nt][1], bBl + off);
            }
#pragma unroll
            for (int nt = 0; nt < 4; nt++)
#pragma unroll
                for (int mt = 0; mt < 4; mt++) {
                    mma_bf16(acc[mt][nt], ah[mt], bh2[nt]);
                    mma_bf16(acc[mt][nt], al[mt], bh2[nt]);
                    mma_bf16(acc[mt][nt], ah[mt], bl2[nt]);
                }
        }
    }

#pragma unroll
    for (int mt = 0; mt < 4; mt++) {
#pragma unroll
        for (int nt = 0; nt < 4; nt++) {
            int row = m0 + wm * 64 + mt * 16 + grp;
            int col = n0 + wn * 32 + nt * 8 + tig * 2;
            float* a = acc[mt][nt];
            C[(size_t)row * N + col]           = a[0];
            C[(size_t)row * N + col + 1]       = a[1];
            C[(size_t)(row + 8) * N + col]     = a[2];
            C[(size_t)(row + 8) * N + col + 1] = a[3];
        }
    }
}

// ---------------------------------------------------------------------------
// Per-b attention body (all 256 threads). sbuf: >= 1088 floats.
// ---------------------------------------------------------------------------
__device__ void attn_one(int b, int t, const float* __restrict__ feats,
                         const float* __restrict__ Ws, const float* __restrict__ bs,
                         const float* __restrict__ bh, const int* __restrict__ lengths,
                         float* sbuf)
{
    if (lengths[b] <= t) return;   // uniform across block

    float* hp_s = sbuf;
    float* ws_s = sbuf + 512;
    float* sc_s = sbuf + 1024;
    int tid = threadIdx.x;
#pragma unroll
    for (int i = 0; i < 2; i++) {
        int a = tid + i * 256;
        hp_s[a] = g_hppart[b * Asz + a] + g_hppart[Bsz * Asz + b * Asz + a] + bh[a];
        ws_s[a] = Ws[a];
    }
    __syncthreads();

    int warp = tid >> 5, lane = tid & 31;
    for (int r = warp; r < Rsz; r += 8) {
        const float* fp = &g_fproj[(size_t)(b * Rsz + r) * Asz];
        float s = 0.f;
        for (int a = lane; a < Asz; a += 32)
            s += tanhf(fp[a] + hp_s[a]) * ws_s[a];
#pragma unroll
        for (int o = 16; o; o >>= 1) s += __shfl_down_sync(0xffffffffu, s, o);
        if (lane == 0) sc_s[r] = s + bs[0];
    }
    __syncthreads();

    if (warp == 0) {
        float v1 = (lane < Rsz) ? sc_s[lane] : -INFINITY;
        float v2 = (lane + 32 < Rsz) ? sc_s[lane + 32] : -INFINITY;
        float mx = fmaxf(v1, v2);
#pragma unroll
        for (int o = 16; o; o >>= 1) mx = fmaxf(mx, __shfl_xor_sync(0xffffffffu, mx, o));
        float e1 = (lane < Rsz) ? expf(v1 - mx) : 0.f;
        float e2 = (lane + 32 < Rsz) ? expf(v2 - mx) : 0.f;
        float sm2 = e1 + e2;
#pragma unroll
        for (int o = 16; o; o >>= 1) sm2 += __shfl_xor_sync(0xffffffffu, sm2, o);
        float inv = 1.f / sm2;
        if (lane < Rsz) sc_s[lane] = e1 * inv;
        if (lane + 32 < Rsz) sc_s[lane + 32] = e2 * inv;
    }
    __syncthreads();

    for (int f = tid; f < Fsz; f += 256) {
        float acc = 0.f;
#pragma unroll 7
        for (int r = 0; r < Rsz; r++)
            acc = fmaf(sc_s[r], feats[(size_t)(b * Rsz + r) * Fsz + f], acc);
        split2(acc, g_xhH[b * GK2 + f], g_xhL[b * GK2 + f]);
    }
    __syncthreads();   // protect sbuf before next b
}

// ---------------------------------------------------------------------------
// Persistent kernel: whole 23-step recurrence. grid = PGRID CTAs x 256.
// ---------------------------------------------------------------------------
__global__ __launch_bounds__(256, 1) void decoder_loop(
    const float* __restrict__ feats, const float* __restrict__ Ws,
    const float* __restrict__ bs, const float* __restrict__ bh,
    const float* __restrict__ bih, const float* __restrict__ bhh,
    const int* __restrict__ lengths)
{
    __shared__ __align__(16) bf16 sm[4 * 128 * 40];   // 40 KB
    const int cta = blockIdx.x;
    const int tid = threadIdx.x;

    for (int t = 0; t < STEPS; t++) {
        // ---- Phase 1: hp partials = h @ Wh^T (2m x 4n x 2 split-K) ----
        if (cta < 16) {
            int kp = cta & 1, tile = cta >> 1;
            int m = tile & 1, n = tile >> 1;
            if (lengths[m * 128] > t)
                mma_tile(g_xhH + Fsz, g_xhL + Fsz, g_WhH, g_WhL,
                         m * 128, n * 128, GK2, Hsz, kp * 256, 256,
                         g_hppart + (size_t)kp * Bsz * Asz, Asz, sm);
        }
        gsync();

        // ---- Phase 2: attention (256 rows over PGRID CTAs) ----
        for (int b = cta; b < Bsz; b += gridDim.x)
            attn_one(b, t, feats, Ws, bs, bh, lengths, (float*)sm);
        gsync();

        // ---- Phase 3: gates partials = [ctx|h] @ Wg2^T (2m x 16n x 4 split-K) ----
        if (cta < 128) {
            int kp = cta & 3, tile = cta >> 2;
            int m = tile & 1, n = tile >> 1;
            if (lengths[m * 128] > t)
                mma_tile(g_xhH, g_xhL, g_Wg2H, g_Wg2L,
                         m * 128, n * 128, GK2, GK2, kp * 640, 640,
                         g_gpart + (size_t)kp * Bsz * G4, G4, sm);
        }
        gsync();

        // ---- Phase 4: LSTM pointwise ----
        for (int idx = cta * 256 + tid; idx < Bsz * Hsz; idx += gridDim.x * 256) {
            int b = idx >> 9, j = idx & 511;
            if (lengths[b] > t) {
                const int MN = Bsz * G4;
                int base = b * G4;
                const float* ep = &g_embproj[(size_t)(t * Bsz + b) * G4];
                float gv[4];
#pragma unroll
                for (int q = 0; q < 4; q++) {
                    int jj = q * 512 + j;
                    gv[q] = g_gpart[base + jj] + g_gpart[MN + base + jj]
                          + g_gpart[2 * MN + base + jj] + g_gpart[3 * MN + base + jj]
                          + ep[jj] + bih[jj] + bhh[jj];
                }
                float ig = 1.f / (1.f + expf(-gv[0]));
                float fg = 1.f / (1.f + expf(-gv[1]));
                float gg = tanhf(gv[2]);
                float og = 1.f / (1.f + expf(-gv[3]));
                float cn = fg * g_c[idx] + ig * gg;
                float hn = og * tanhf(cn);
                g_c[idx] = cn;
                split2(hn, g_xhH[b * GK2 + Fsz + j], g_xhL[b * GK2 + Fsz + j]);
                split2(hn, g_histH[(size_t)(t * Bsz + b) * Hsz + j],
                           g_histL[(size_t)(t * Bsz + b) * Hsz + j]);
            }
        }
        gsync();
    }
}

// ---------------------------------------------------------------------------
// Host-launched GEMM (precompute / final FC) — same as R6.
// EPI: 0 = +bias; 1 = raw (split-K partial @ z*M*N); 2 = final fc; 3 = tanh(+bias)
// ---------------------------------------------------------------------------
template <int EPI>
__global__ __launch_bounds__(256) void mma_gemm(
    const bf16* __restrict__ Ah, const bf16* __restrict__ Al,
    const bf16* __restrict__ Bh, const bf16* __restrict__ Bl,
    const float* __restrict__ bias, float* __restrict__ C,
    int M, int N, int lda, int ldb, int kspl,
    const int* __restrict__ lengths, int t)
{
    const int m0 = blockIdx.y * 128;
    const int n0 = blockIdx.x * 128;
    const int tid = threadIdx.x;

    if (EPI == 2) {
        int tt = m0 >> 8, b0 = m0 & 255;
        if (lengths[b0] <= tt) {
            for (int i = tid; i < 128 * 128; i += 256) {
                int r = i >> 7, cc = i & 127;
                int n = n0 + cc;
                if (n < Vsz)
                    C[((size_t)(b0 + r) * STEPS + tt) * Vsz + n] = 0.f;
            }
            return;
        }
    }

    __shared__ __align__(16) bf16 sm[4 * 128 * 40];
    const int lane = tid & 31, warp = tid >> 5;
    const int wm = warp >> 2, wn = warp & 3;
    const int grp = lane >> 2, tig = lane & 3;
    const int kbase = (EPI == 1) ? blockIdx.z * kspl : 0;

    // inline tile (same math as mma_tile but with epilogue variants)
    bf16* sAh = sm; bf16* sAl = sm + 5120; bf16* sBh = sm + 10240; bf16* sBl = sm + 15360;
    uint4* s4Ah = (uint4*)sAh; uint4* s4Al = (uint4*)sAl;
    uint4* s4Bh = (uint4*)sBh; uint4* s4Bl = (uint4*)sBl;
    unsigned bAh = (unsigned)__cvta_generic_to_shared(sAh);
    unsigned bAl = (unsigned)__cvta_generic_to_shared(sAl);
    unsigned bBh = (unsigned)__cvta_generic_to_shared(sBh);
    unsigned bBl = (unsigned)__cvta_generic_to_shared(sBl);
    const int ldr = tid >> 2, ldc = tid & 3;

    float acc[4][4][4] = {};

    for (int kc = 0; kc < kspl; kc += 32) {
        const int kg = kbase + kc;
        uint4 vah[2], val_[2], vbh[2], vbl[2];
#pragma unroll
        for (int i = 0; i < 2; i++) {
            int r = ldr + i * 64;
            size_t ga = (size_t)(m0 + r) * lda + kg + ldc * 8;
            size_t gb = (size_t)(n0 + r) * ldb + kg + ldc * 8;
            vah[i]  = *(const uint4*)(Ah + ga);
            val_[i] = *(const uint4*)(Al + ga);
            vbh[i]  = *(const uint4*)(Bh + gb);
            vbl[i]  = *(const uint4*)(Bl + gb);
        }
        __syncthreads();
#pragma unroll
        for (int i = 0; i < 2; i++) {
            int r = ldr + i * 64;
            s4Ah[r * 5 + ldc] = vah[i];
            s4Al[r * 5 + ldc] = val_[i];
            s4Bh[r * 5 + ldc] = vbh[i];
            s4Bl[r * 5 + ldc] = vbl[i];
        }
        __syncthreads();

#pragma unroll
        for (int k16 = 0; k16 < 2; k16++) {
            const int aro = wm * 64 + (lane & 15);
            const int aco = k16 * 16 + ((lane >> 4) << 3);
            const int bro = wn * 32 + (lane & 7);
            const int bco = k16 * 16 + (((lane >> 3) & 1) << 3);
            unsigned ah[4][4], al[4][4], bh2[4][2], bl2[4][2];
#pragma unroll
            for (int mt = 0; mt < 4; mt++) {
                unsigned off = (unsigned)(((aro + mt * 16) * 40 + aco) * 2);
                ldsm_x4(ah[mt][0], ah[mt][1], ah[mt][2], ah[mt][3], bAh + off);
                ldsm_x4(al[mt][0], al[mt][1], al[mt][2], al[mt][3], bAl + off);
            }
#pragma unroll
            for (int nt = 0; nt < 4; nt++) {
                unsigned off = (unsigned)(((bro + nt * 8) * 40 + bco) * 2);
                ldsm_x2(bh2[nt][0], bh2[nt][1], bBh + off);
                ldsm_x2(bl2[nt][0], bl2[nt][1], bBl + off);
            }
#pragma unroll
            for (int nt = 0; nt < 4; nt++)
#pragma unroll
                for (int mt = 0; mt < 4; mt++) {
                    mma_bf16(acc[mt][nt], ah[mt], bh2[nt]);
                    mma_bf16(acc[mt][nt], al[mt], bh2[nt]);
                    mma_bf16(acc[mt][nt], ah[mt], bl2[nt]);
                }
        }
    }

    float* Cp = C;
    if (EPI == 1) Cp = C + (size_t)blockIdx.z * M * N;

#pragma unroll
    for (int mt = 0; mt < 4; mt++) {
#pragma unroll
        for (int nt = 0; nt < 4; nt++) {
            int row = m0 + wm * 64 + mt * 16 + grp;
            int col = n0 + wn * 32 + nt * 8 + tig * 2;
            float* a = acc[mt][nt];
            if (EPI == 0) {
                Cp[(size_t)row * N + col]           = a[0] + bias[col];
                Cp[(size_t)row * N + col + 1]       = a[1] + bias[col + 1];
                Cp[(size_t)(row + 8) * N + col]     = a[2] + bias[col];
                Cp[(size_t)(row + 8) * N + col + 1] = a[3] + bias[col + 1];
            } else if (EPI == 3) {
                Cp[(size_t)row * N + col]           = tanhf(a[0] + bias[col]);
                Cp[(size_t)row * N + col + 1]       = tanhf(a[1] + bias[col + 1]);
                Cp[(size_t)(row + 8) * N + col]     = tanhf(a[2] + bias[col]);
                Cp[(size_t)(row + 8) * N + col + 1] = tanhf(a[3] + bias[col + 1]);
            } else if (EPI == 1) {
                Cp[(size_t)row * N + col]           = a[0];
                Cp[(size_t)row * N + col + 1]       = a[1];
                Cp[(size_t)(row + 8) * N + col]     = a[2];
                Cp[(size_t)(row + 8) * N + col + 1] = a[3];
            } else {
                if (col < Vsz) {
                    int b0r = row & 255, tt0 = row >> 8;
                    int b1r = (row + 8) & 255, tt1 = (row + 8) >> 8;
                    bool act0 = lengths[b0r] > tt0;
                    bool act1 = lengths[b1r] > tt1;
                    float* p0 = C + ((size_t)b0r * STEPS + tt0) * Vsz;
                    float* p1 = C + ((size_t)b1r * STEPS + tt1) * Vsz;
                    p0[col]     = act0 ? (a[0] + bias[col])     : 0.f;
                    p0[col + 1] = act0 ? (a[1] + bias[col + 1]) : 0.f;
                    p1[col]     = act1 ? (a[2] + bias[col])     : 0.f;
                    p1[col + 1] = act1 ? (a[3] + bias[col + 1]) : 0.f;
                }
            }
        }
    }
}

// ---------------------------------------------------------------------------
// conversion / setup kernels
// ---------------------------------------------------------------------------
__global__ void split_arr(const float* __restrict__ src, bf16* __restrict__ h,
                          bf16* __restrict__ l, int n)
{
    for (int i = blockIdx.x * blockDim.x + threadIdx.x; i < n; i += gridDim.x * blockDim.x)
        split2(src[i], h[i], l[i]);
}

__global__ void build_Wg2(const float* __restrict__ Wih, const float* __restrict__ Whh,
                          bf16* __restrict__ h, bf16* __restrict__ l,
                          bf16* __restrict__ eh, bf16* __restrict__ el)
{
    for (int i = blockIdx.x * blockDim.x + threadIdx.x; i < G4 * GK2; i += gridDim.x * blockDim.x) {
        int r = i / GK2, cc = i % GK2;
        float v = (cc < Fsz) ? Wih[(size_t)r * (Esz + Fsz) + Esz + cc]
                             : Whh[(size_t)r * Hsz + cc - Fsz];
        split2(v, h[i], l[i]);
    }
    for (int i = blockIdx.x * blockDim.x + threadIdx.x; i < G4 * Esz; i += gridDim.x * blockDim.x) {
        int r = i / Esz, cc = i % Esz;
        split2(Wih[(size_t)r * (Esz + Fsz) + cc], eh[i], el[i]);
    }
}

__global__ void build_Wi(const float* __restrict__ Wih, const float* __restrict__ Wic,
                         const float* __restrict__ bih, const float* __restrict__ bic,
                         bf16* __restrict__ h, bf16* __restrict__ l, float* __restrict__ bi)
{
    for (int i = blockIdx.x * blockDim.x + threadIdx.x; i < 1024 * Fsz; i += gridDim.x * blockDim.x) {
        int r = i / Fsz, cc = i % Fsz;
        float v = (r < Hsz) ? Wih[(size_t)r * Fsz + cc] : Wic[(size_t)(r - Hsz) * Fsz + cc];
        split2(v, h[i], l[i]);
        if (i < 1024) bi[i] = (i < Hsz) ? bih[i] : bic[i - Hsz];
    }
}

__global__ void build_Wfc(const float* __restrict__ W, bf16* __restrict__ h, bf16* __restrict__ l)
{
    for (int i = blockIdx.x * blockDim.x + threadIdx.x; i < VPAD * Hsz; i += gridDim.x * blockDim.x) {
        int r = i / Hsz;
        float v = (r < Vsz) ? W[i] : 0.f;
        split2(v, h[i], l[i]);
    }
}

__global__ void build_embA(const float* __restrict__ embW, const int* __restrict__ ids,
                           bf16* __restrict__ h, bf16* __restrict__ l)
{
    for (int i = blockIdx.x * blockDim.x + threadIdx.x; i < MROWS * Esz; i += gridDim.x * blockDim.x) {
        int r = i >> 8, e = i & 255;
        int tt = r >> 8, b = r & 255;
        int id = ids[b * Lsz + tt];
        split2(embW[(size_t)id * Esz + e], h[i], l[i]);
    }
}

__global__ void mean_split(const float* __restrict__ feats, bf16* __restrict__ mh,
                           bf16* __restrict__ ml)
{
    int b = blockIdx.x;
    for (int f = threadIdx.x; f < Fsz; f += blockDim.x) {
        float s = 0.f;
        for (int r = 0; r < Rsz; r++) s += feats[(size_t)(b * Rsz + r) * Fsz + f];
        split2(s * (1.0f / Rsz), mh[b * Fsz + f], ml[b * Fsz + f]);
    }
}

__global__ void init_state()
{
    int idx = blockIdx.x * blockDim.x + threadIdx.x;   // B*H
    int b = idx >> 9, j = idx & 511;
    float h = g_h0c0[b * 1024 + j];
    float c = g_h0c0[b * 1024 + 512 + j];
    g_c[idx] = c;
    split2(h, g_xhH[b * GK2 + Fsz + j], g_xhL[b * GK2 + Fsz + j]);
}

// ---------------------------------------------------------------------------
extern "C" void kernel_launch(void* const* d_in, const int* in_sizes, int n_in,
                              void* d_out, int out_size)
{
    const float* feats   = (const float*)d_in[0];
    const int*   ids     = (const int*)  d_in[1];
    const int*   lengths = (const int*)  d_in[2];
    const float* embW    = (const float*)d_in[3];
    const float* Wf      = (const float*)d_in[4];
    const float* bf      = (const float*)d_in[5];
    const float* Wh      = (const float*)d_in[6];
    const float* bh      = (const float*)d_in[7];
    const float* Ws      = (const float*)d_in[8];
    const float* bs      = (const float*)d_in[9];
    const float* W_ih    = (const float*)d_in[10];
    const float* b_ih    = (const float*)d_in[11];
    const float* W_hh    = (const float*)d_in[12];
    const float* b_hh    = (const float*)d_in[13];
    const float* Wfc     = (const float*)d_in[14];
    const float* bfc     = (const float*)d_in[15];
    const float* Wi_h    = (const float*)d_in[16];
    const float* bi_h    = (const float*)d_in[17];
    const float* Wi_c    = (const float*)d_in[18];
    const float* bi_c    = (const float*)d_in[19];
    float* out = (float*)d_out;

    void *pv;
    cudaGetSymbolAddress(&pv, g_featH);  bf16* featH = (bf16*)pv;
    cudaGetSymbolAddress(&pv, g_featL);  bf16* featL = (bf16*)pv;
    cudaGetSymbolAddress(&pv, g_meanH);  bf16* meanH = (bf16*)pv;
    cudaGetSymbolAddress(&pv, g_meanL);  bf16* meanL = (bf16*)pv;
    cudaGetSymbolAddress(&pv, g_WfH);    bf16* WfH = (bf16*)pv;
    cudaGetSymbolAddress(&pv, g_WfL);    bf16* WfL = (bf16*)pv;
    cudaGetSymbolAddress(&pv, g_Wg2H);   bf16* Wg2H = (bf16*)pv;
    cudaGetSymbolAddress(&pv, g_Wg2L);   bf16* Wg2L = (bf16*)pv;
    cudaGetSymbolAddress(&pv, g_WihEH);  bf16* WihEH = (bf16*)pv;
    cudaGetSymbolAddress(&pv, g_WihEL);  bf16* WihEL = (bf16*)pv;
    cudaGetSymbolAddress(&pv, g_WiH);    bf16* WiH = (bf16*)pv;
    cudaGetSymbolAddress(&pv, g_WiL);    bf16* WiL = (bf16*)pv;
    cudaGetSymbolAddress(&pv, g_bi);     float* bi = (float*)pv;
    cudaGetSymbolAddress(&pv, g_WfcH);   bf16* WfcH = (bf16*)pv;
    cudaGetSymbolAddress(&pv, g_WfcL);   bf16* WfcL = (bf16*)pv;
    cudaGetSymbolAddress(&pv, g_h0c0);   float* h0c0 = (float*)pv;
    cudaGetSymbolAddress(&pv, g_embAH);  bf16* embAH = (bf16*)pv;
    cudaGetSymbolAddress(&pv, g_embAL);  bf16* embAL = (bf16*)pv;
    cudaGetSymbolAddress(&pv, g_embproj);float* embproj = (float*)pv;
    cudaGetSymbolAddress(&pv, g_histH);  bf16* histH = (bf16*)pv;
    cudaGetSymbolAddress(&pv, g_histL);  bf16* histL = (bf16*)pv;
    cudaGetSymbolAddress(&pv, g_fproj);  float* fproj = (float*)pv;

    // ---- conversions ----
    split_arr<<<1024, 256>>>(feats, featH, featL, NFEAT);
    split_arr<<<256, 256>>>(Wf, WfH, WfL, Asz * Fsz);
    {
        void* ph; void* pl;
        cudaGetSymbolAddress(&ph, g_WhH); cudaGetSymbolAddress(&pl, g_WhL);
        split_arr<<<128, 256>>>(Wh, (bf16*)ph, (bf16*)pl, Asz * Hsz);
    }
    build_Wg2<<<512, 256>>>(W_ih, W_hh, Wg2H, Wg2L, WihEH, WihEL);
    build_Wi<<<256, 256>>>(Wi_h, Wi_c, bi_h, bi_c, WiH, WiL, bi);
    build_Wfc<<<512, 256>>>(Wfc, WfcH, WfcL);
    build_embA<<<256, 256>>>(embW, ids, embAH, embAL);
    mean_split<<<Bsz, 256>>>(feats, meanH, meanL);

    // ---- init state ----
    mma_gemm<3><<<dim3(8, 2, 1), 256>>>(meanH, meanL, WiH, WiL, bi, h0c0,
                                        Bsz, 1024, Fsz, Fsz, Fsz, nullptr, 0);
    init_state<<<(Bsz * Hsz) / 256, 256>>>();

    // ---- f_proj = feats @ Wf^T + bf ----
    mma_gemm<0><<<dim3(4, 98, 1), 256>>>(featH, featL, WfH, WfL, bf, fproj,
                                         Bsz * Rsz, Asz, Fsz, Fsz, Fsz, nullptr, 0);

    // ---- embproj = embAll @ W_ih[:, :E]^T ----
    mma_gemm<1><<<dim3(16, 46, 1), 256>>>(embAH, embAL, WihEH, WihEL, nullptr, embproj,
                                          MROWS, G4, Esz, Esz, Esz, nullptr, -1);

    // ---- persistent recurrence: all 23 steps in one launch ----
    decoder_loop<<<PGRID, 256>>>(feats, Ws, bs, bh, b_ih, b_hh, lengths);

    // ---- final FC over all (t, b) ----
    mma_gemm<2><<<dim3(VPAD / 128, MROWS / 128, 1), 256>>>(
        histH, histL, WfcH, WfcL, bfc, out,
        MROWS, VPAD, Hsz, Hsz, Hsz, lengths, 0);
}

// round 9
// speedup vs baseline: 1.3849x; 1.1198x over previous
#include <cuda_runtime.h>
#include <cuda_bf16.h>
#include <math.h>

#define Bsz 256
#define Lsz 24
#define Rsz 49
#define Fsz 2048
#define Esz 256
#define Hsz 512
#define Asz 512
#define Vsz 10000
#define STEPS 23
#define G4 2048         // 4*H
#define GK2 2560        // F + H
#define VPAD 10112
#define MROWS (STEPS * Bsz)   // 5888
#define NFEAT (Bsz * Rsz * Fsz)
#define PGRID 128

#define SST 10240            // bytes per array within one stage (128 rows * 40 bf16 * 2B)
#define STAGE_BYTES 40960    // 4 arrays
#define SMEM_DYN 81920       // 2 stages

typedef __nv_bfloat16 bf16;

// ---------------- scratch ----------------
__device__ float g_fproj[Bsz * Rsz * Asz];
__device__ bf16  g_featH[NFEAT], g_featL[NFEAT];
__device__ bf16  g_meanH[Bsz * Fsz], g_meanL[Bsz * Fsz];
__device__ bf16  g_WfH[Asz * Fsz],  g_WfL[Asz * Fsz];
__device__ bf16  g_WhH[Asz * Hsz],  g_WhL[Asz * Hsz];
__device__ bf16  g_Wg2H[G4 * GK2],  g_Wg2L[G4 * GK2];
__device__ bf16  g_WihEH[G4 * Esz], g_WihEL[G4 * Esz];
__device__ bf16  g_WiH[1024 * Fsz], g_WiL[1024 * Fsz];
__device__ float g_bi[1024];
__device__ bf16  g_WfcH[VPAD * Hsz], g_WfcL[VPAD * Hsz];
__device__ float g_h0c0[Bsz * 1024];
__device__ float g_c[Bsz * Hsz];
__device__ bf16  g_xhH[Bsz * GK2], g_xhL[Bsz * GK2];
__device__ bf16  g_embAH[MROWS * Esz], g_embAL[MROWS * Esz];
__device__ float g_embproj[MROWS * G4];
__device__ bf16  g_histH[MROWS * Hsz], g_histL[MROWS * Hsz];
__device__ float g_gpart[4 * Bsz * G4];
__device__ float g_hppart[8 * Bsz * Asz];

__device__ unsigned g_bar_count = 0;
__device__ unsigned g_bar_gen = 0;

__device__ __forceinline__ void split2(float x, bf16& h, bf16& l) {
    h = __float2bfloat16(x);
    l = __float2bfloat16(x - __bfloat162float(h));
}

__device__ __forceinline__ void mma_bf16(float* c, const unsigned* a, const unsigned* b) {
    asm volatile(
        "mma.sync.aligned.m16n8k16.row.col.f32.bf16.bf16.f32 "
        "{%0,%1,%2,%3},{%4,%5,%6,%7},{%8,%9},{%0,%1,%2,%3};\n"
        : "+f"(c[0]), "+f"(c[1]), "+f"(c[2]), "+f"(c[3])
        : "r"(a[0]), "r"(a[1]), "r"(a[2]), "r"(a[3]), "r"(b[0]), "r"(b[1]));
}

__device__ __forceinline__ void ldsm_x4(unsigned& r0, unsigned& r1, unsigned& r2, unsigned& r3,
                                        unsigned addr) {
    asm volatile("ldmatrix.sync.aligned.m8n8.x4.shared.b16 {%0,%1,%2,%3},[%4];"
                 : "=r"(r0), "=r"(r1), "=r"(r2), "=r"(r3) : "r"(addr));
}
__device__ __forceinline__ void ldsm_x2(unsigned& r0, unsigned& r1, unsigned addr) {
    asm volatile("ldmatrix.sync.aligned.m8n8.x2.shared.b16 {%0,%1},[%2];"
                 : "=r"(r0), "=r"(r1) : "r"(addr));
}

__device__ __forceinline__ void cpa16(unsigned dst, const bf16* src) {
    asm volatile("cp.async.cg.shared.global [%0], [%1], 16;" :: "r"(dst), "l"(src));
}
__device__ __forceinline__ void cpcommit() { asm volatile("cp.async.commit_group;"); }
template <int N> __device__ __forceinline__ void cpwait() {
    asm volatile("cp.async.wait_group %0;" :: "n"(N));
}

// grid barrier (co-resident grid)
__device__ __forceinline__ void gsync() {
    __syncthreads();
    if (threadIdx.x == 0) {
        __threadfence();
        unsigned gen = *((volatile unsigned*)&g_bar_gen);
        if (atomicAdd(&g_bar_count, 1u) == gridDim.x - 1) {
            *((volatile unsigned*)&g_bar_count) = 0;
            __threadfence();
            atomicAdd(&g_bar_gen, 1u);
        } else {
            while (*((volatile unsigned*)&g_bar_gen) == gen) { }
            __threadfence();
        }
    }
    __syncthreads();
}

// ---------------------------------------------------------------------------
// Pipelined MMA tile machinery (128x128 tile, BK=32, 2-stage cp.async)
// ---------------------------------------------------------------------------
__device__ __forceinline__ void load_chunk(
    unsigned sb, const bf16* __restrict__ Ah, const bf16* __restrict__ Al,
    const bf16* __restrict__ Bh, const bf16* __restrict__ Bl,
    int m0, int n0, int lda, int ldb, int kg)
{
    const int tid = threadIdx.x;
    const int ldr = tid >> 2, ldc = tid & 3;
#pragma unroll
    for (int i = 0; i < 2; i++) {
        int r = ldr + i * 64;
        size_t ga = (size_t)(m0 + r) * lda + kg + ldc * 8;
        size_t gb = (size_t)(n0 + r) * ldb + kg + ldc * 8;
        unsigned off = (unsigned)((r * 5 + ldc) * 16);
        cpa16(sb + off,           Ah + ga);
        cpa16(sb + SST + off,     Al + ga);
        cpa16(sb + 2 * SST + off, Bh + gb);
        cpa16(sb + 3 * SST + off, Bl + gb);
    }
}

__device__ __forceinline__ void mma_chunk(unsigned sb, float acc[4][4][4])
{
    const int lane = threadIdx.x & 31, warp = threadIdx.x >> 5;
    const int wm = warp >> 2, wn = warp & 3;
#pragma unroll
    for (int k16 = 0; k16 < 2; k16++) {
        const int aro = wm * 64 + (lane & 15);
        const int aco = k16 * 16 + ((lane >> 4) << 3);
        const int bro = wn * 32 + (lane & 7);
        const int bco = k16 * 16 + (((lane >> 3) & 1) << 3);
        unsigned ah[4][4], al[4][4], bh2[4][2], bl2[4][2];
#pragma unroll
        for (int mt = 0; mt < 4; mt++) {
            unsigned off = (unsigned)(((aro + mt * 16) * 40 + aco) * 2);
            ldsm_x4(ah[mt][0], ah[mt][1], ah[mt][2], ah[mt][3], sb + off);
            ldsm_x4(al[mt][0], al[mt][1], al[mt][2], al[mt][3], sb + SST + off);
        }
#pragma unroll
        for (int nt = 0; nt < 4; nt++) {
            unsigned off = (unsigned)(((bro + nt * 8) * 40 + bco) * 2);
            ldsm_x2(bh2[nt][0], bh2[nt][1], sb + 2 * SST + off);
            ldsm_x2(bl2[nt][0], bl2[nt][1], sb + 3 * SST + off);
        }
#pragma unroll
        for (int nt = 0; nt < 4; nt++)
#pragma unroll
            for (int mt = 0; mt < 4; mt++) {
                mma_bf16(acc[mt][nt], ah[mt], bh2[nt]);
                mma_bf16(acc[mt][nt], al[mt], bh2[nt]);
                mma_bf16(acc[mt][nt], ah[mt], bl2[nt]);
            }
    }
}

__device__ __forceinline__ void mma_tile_pipe(
    const bf16* __restrict__ Ah, const bf16* __restrict__ Al,
    const bf16* __restrict__ Bh, const bf16* __restrict__ Bl,
    int m0, int n0, int lda, int ldb, int kbase, int kcnt,
    float acc[4][4][4], unsigned sm_u)
{
    const int nch = kcnt >> 5;
    load_chunk(sm_u, Ah, Al, Bh, Bl, m0, n0, lda, ldb, kbase);
    cpcommit();
    for (int ic = 0; ic < nch; ic++) {
        if (ic + 1 < nch) {
            load_chunk(sm_u + ((ic + 1) & 1) * STAGE_BYTES, Ah, Al, Bh, Bl,
                       m0, n0, lda, ldb, kbase + (ic + 1) * 32);
            cpcommit();
            cpwait<1>();
        } else {
            cpwait<0>();
        }
        __syncthreads();
        mma_chunk(sm_u + (ic & 1) * STAGE_BYTES, acc);
        __syncthreads();
    }
}

// raw-store tile (device, for persistent kernel phases)
__device__ void mma_tile_raw(
    const bf16* __restrict__ Ah, const bf16* __restrict__ Al,
    const bf16* __restrict__ Bh, const bf16* __restrict__ Bl,
    int m0, int n0, int lda, int ldb, int kbase, int kcnt,
    float* __restrict__ C, int N, unsigned sm_u)
{
    float acc[4][4][4] = {};
    mma_tile_pipe(Ah, Al, Bh, Bl, m0, n0, lda, ldb, kbase, kcnt, acc, sm_u);
    const int lane = threadIdx.x & 31, warp = threadIdx.x >> 5;
    const int wm = warp >> 2, wn = warp & 3;
    const int grp = lane >> 2, tig = lane & 3;
#pragma unroll
    for (int mt = 0; mt < 4; mt++)
#pragma unroll
        for (int nt = 0; nt < 4; nt++) {
            int row = m0 + wm * 64 + mt * 16 + grp;
            int col = n0 + wn * 32 + nt * 8 + tig * 2;
            float* a = acc[mt][nt];
            C[(size_t)row * N + col]           = a[0];
            C[(size_t)row * N + col + 1]       = a[1];
            C[(size_t)(row + 8) * N + col]     = a[2];
            C[(size_t)(row + 8) * N + col + 1] = a[3];
        }
}

// ---------------------------------------------------------------------------
// Per-b attention body (256 threads). sbuf >= 1088 floats.
// ---------------------------------------------------------------------------
__device__ void attn_one(int b, int t, const float* __restrict__ feats,
                         const float* __restrict__ Ws, const float* __restrict__ bs,
                         const float* __restrict__ bh, const int* __restrict__ lengths,
                         float* sbuf)
{
    if (lengths[b] <= t) return;

    float* hp_s = sbuf;
    float* ws_s = sbuf + 512;
    float* sc_s = sbuf + 1024;
    int tid = threadIdx.x;
#pragma unroll
    for (int i = 0; i < 2; i++) {
        int a = tid + i * 256;
        float s = bh[a];
#pragma unroll
        for (int p = 0; p < 8; p++) s += g_hppart[(size_t)p * Bsz * Asz + b * Asz + a];
        hp_s[a] = s;
        ws_s[a] = Ws[a];
    }
    __syncthreads();

    int warp = tid >> 5, lane = tid & 31;
    for (int r = warp; r < Rsz; r += 8) {
        const float* fp = &g_fproj[(size_t)(b * Rsz + r) * Asz];
        float s = 0.f;
        for (int a = lane; a < Asz; a += 32)
            s += tanhf(fp[a] + hp_s[a]) * ws_s[a];
#pragma unroll
        for (int o = 16; o; o >>= 1) s += __shfl_down_sync(0xffffffffu, s, o);
        if (lane == 0) sc_s[r] = s + bs[0];
    }
    __syncthreads();

    if (warp == 0) {
        float v1 = (lane < Rsz) ? sc_s[lane] : -INFINITY;
        float v2 = (lane + 32 < Rsz) ? sc_s[lane + 32] : -INFINITY;
        float mx = fmaxf(v1, v2);
#pragma unroll
        for (int o = 16; o; o >>= 1) mx = fmaxf(mx, __shfl_xor_sync(0xffffffffu, mx, o));
        float e1 = (lane < Rsz) ? expf(v1 - mx) : 0.f;
        float e2 = (lane + 32 < Rsz) ? expf(v2 - mx) : 0.f;
        float sm2 = e1 + e2;
#pragma unroll
        for (int o = 16; o; o >>= 1) sm2 += __shfl_xor_sync(0xffffffffu, sm2, o);
        float inv = 1.f / sm2;
        if (lane < Rsz) sc_s[lane] = e1 * inv;
        if (lane + 32 < Rsz) sc_s[lane + 32] = e2 * inv;
    }
    __syncthreads();

    for (int f = tid; f < Fsz; f += 256) {
        float acc = 0.f;
#pragma unroll 7
        for (int r = 0; r < Rsz; r++)
            acc = fmaf(sc_s[r], feats[(size_t)(b * Rsz + r) * Fsz + f], acc);
        split2(acc, g_xhH[b * GK2 + f], g_xhL[b * GK2 + f]);
    }
    __syncthreads();
}

// ---------------------------------------------------------------------------
// Persistent recurrence kernel
// ---------------------------------------------------------------------------
__global__ __launch_bounds__(256, 1) void decoder_loop(
    const float* __restrict__ feats, const float* __restrict__ Ws,
    const float* __restrict__ bs, const float* __restrict__ bh,
    const float* __restrict__ bih, const float* __restrict__ bhh,
    const int* __restrict__ lengths)
{
    extern __shared__ __align__(16) char dsm[];
    unsigned sm_u = (unsigned)__cvta_generic_to_shared(dsm);
    const int cta = blockIdx.x;
    const int tid = threadIdx.x;

    for (int t = 0; t < STEPS; t++) {
        // Phase 1: hp partials = h @ Wh^T  (2m x 4n x 8 split-K = 64 CTAs)
        if (cta < 64) {
            int kp = cta & 7, tile = cta >> 3;
            int m = tile & 1, n = tile >> 1;
            if (lengths[m * 128] > t)
                mma_tile_raw(g_xhH + Fsz, g_xhL + Fsz, g_WhH, g_WhL,
                             m * 128, n * 128, GK2, Hsz, kp * 64, 64,
                             g_hppart + (size_t)kp * Bsz * Asz, Asz, sm_u);
        }
        gsync();

        // Phase 2: attention
        for (int b = cta; b < Bsz; b += gridDim.x)
            attn_one(b, t, feats, Ws, bs, bh, lengths, (float*)dsm);
        gsync();

        // Phase 3: gates partials = [ctx|h] @ Wg2^T (2m x 16n x 4 split-K = 128 CTAs)
        if (cta < 128) {
            int kp = cta & 3, tile = cta >> 2;
            int m = tile & 1, n = tile >> 1;
            if (lengths[m * 128] > t)
                mma_tile_raw(g_xhH, g_xhL, g_Wg2H, g_Wg2L,
                             m * 128, n * 128, GK2, GK2, kp * 640, 640,
                             g_gpart + (size_t)kp * Bsz * G4, G4, sm_u);
        }
        gsync();

        // Phase 4: LSTM pointwise
        for (int idx = cta * 256 + tid; idx < Bsz * Hsz; idx += gridDim.x * 256) {
            int b = idx >> 9, j = idx & 511;
            if (lengths[b] > t) {
                const int MN = Bsz * G4;
                int base = b * G4;
                const float* ep = &g_embproj[(size_t)(t * Bsz + b) * G4];
                float gv[4];
#pragma unroll
                for (int q = 0; q < 4; q++) {
                    int jj = q * 512 + j;
                    gv[q] = g_gpart[base + jj] + g_gpart[MN + base + jj]
                          + g_gpart[2 * MN + base + jj] + g_gpart[3 * MN + base + jj]
                          + ep[jj] + bih[jj] + bhh[jj];
                }
                float ig = 1.f / (1.f + expf(-gv[0]));
                float fg = 1.f / (1.f + expf(-gv[1]));
                float gg = tanhf(gv[2]);
                float og = 1.f / (1.f + expf(-gv[3]));
                float cn = fg * g_c[idx] + ig * gg;
                float hn = og * tanhf(cn);
                g_c[idx] = cn;
                split2(hn, g_xhH[b * GK2 + Fsz + j], g_xhL[b * GK2 + Fsz + j]);
                split2(hn, g_histH[(size_t)(t * Bsz + b) * Hsz + j],
                           g_histL[(size_t)(t * Bsz + b) * Hsz + j]);
            }
        }
        gsync();
    }
}

// ---------------------------------------------------------------------------
// Host-launched GEMM (precompute / final FC), pipelined.
// EPI: 0 = +bias; 1 = raw; 2 = final fc; 3 = tanh(+bias)
// ---------------------------------------------------------------------------
template <int EPI>
__global__ __launch_bounds__(256) void mma_gemm(
    const bf16* __restrict__ Ah, const bf16* __restrict__ Al,
    const bf16* __restrict__ Bh, const bf16* __restrict__ Bl,
    const float* __restrict__ bias, float* __restrict__ C,
    int M, int N, int lda, int ldb, int kspl,
    const int* __restrict__ lengths, int t)
{
    const int m0 = blockIdx.y * 128;
    const int n0 = blockIdx.x * 128;
    const int tid = threadIdx.x;

    if (EPI == 2) {
        int tt = m0 >> 8, b0 = m0 & 255;
        if (lengths[b0] <= tt) {
            for (int i = tid; i < 128 * 128; i += 256) {
                int r = i >> 7, cc = i & 127;
                int n = n0 + cc;
                if (n < Vsz)
                    C[((size_t)(b0 + r) * STEPS + tt) * Vsz + n] = 0.f;
            }
            return;
        }
    }

    extern __shared__ __align__(16) char dsm[];
    unsigned sm_u = (unsigned)__cvta_generic_to_shared(dsm);

    const int lane = tid & 31, warp = tid >> 5;
    const int wm = warp >> 2, wn = warp & 3;
    const int grp = lane >> 2, tig = lane & 3;
    const int kbase = (EPI == 1) ? blockIdx.z * kspl : 0;

    float acc[4][4][4] = {};
    mma_tile_pipe(Ah, Al, Bh, Bl, m0, n0, lda, ldb, kbase, kspl, acc, sm_u);

    float* Cp = C;
    if (EPI == 1) Cp = C + (size_t)blockIdx.z * M * N;

#pragma unroll
    for (int mt = 0; mt < 4; mt++) {
#pragma unroll
        for (int nt = 0; nt < 4; nt++) {
            int row = m0 + wm * 64 + mt * 16 + grp;
            int col = n0 + wn * 32 + nt * 8 + tig * 2;
            float* a = acc[mt][nt];
            if (EPI == 0) {
                Cp[(size_t)row * N + col]           = a[0] + bias[col];
                Cp[(size_t)row * N + col + 1]       = a[1] + bias[col + 1];
                Cp[(size_t)(row + 8) * N + col]     = a[2] + bias[col];
                Cp[(size_t)(row + 8) * N + col + 1] = a[3] + bias[col + 1];
            } else if (EPI == 3) {
                Cp[(size_t)row * N + col]           = tanhf(a[0] + bias[col]);
                Cp[(size_t)row * N + col + 1]       = tanhf(a[1] + bias[col + 1]);
                Cp[(size_t)(row + 8) * N + col]     = tanhf(a[2] + bias[col]);
                Cp[(size_t)(row + 8) * N + col + 1] = tanhf(a[3] + bias[col + 1]);
            } else if (EPI == 1) {
                Cp[(size_t)row * N + col]           = a[0];
                Cp[(size_t)row * N + col + 1]       = a[1];
                Cp[(size_t)(row + 8) * N + col]     = a[2];
                Cp[(size_t)(row + 8) * N + col + 1] = a[3];
            } else {
                if (col < Vsz) {
                    int b0r = row & 255, tt0 = row >> 8;
                    int b1r = (row + 8) & 255, tt1 = (row + 8) >> 8;
                    bool act0 = lengths[b0r] > tt0;
                    bool act1 = lengths[b1r] > tt1;
                    float* p0 = C + ((size_t)b0r * STEPS + tt0) * Vsz;
                    float* p1 = C + ((size_t)b1r * STEPS + tt1) * Vsz;
                    p0[col]     = act0 ? (a[0] + bias[col])     : 0.f;
                    p0[col + 1] = act0 ? (a[1] + bias[col + 1]) : 0.f;
                    p1[col]     = act1 ? (a[2] + bias[col])     : 0.f;
                    p1[col + 1] = act1 ? (a[3] + bias[col + 1]) : 0.f;
                }
            }
        }
    }
}

// ---------------------------------------------------------------------------
// conversion / setup kernels
// ---------------------------------------------------------------------------
__global__ void split_arr(const float* __restrict__ src, bf16* __restrict__ h,
                          bf16* __restrict__ l, int n)
{
    for (int i = blockIdx.x * blockDim.x + threadIdx.x; i < n; i += gridDim.x * blockDim.x)
        split2(src[i], h[i], l[i]);
}

__global__ void build_Wg2(const float* __restrict__ Wih, const float* __restrict__ Whh,
                          bf16* __restrict__ h, bf16* __restrict__ l,
                          bf16* __restrict__ eh, bf16* __restrict__ el)
{
    for (int i = blockIdx.x * blockDim.x + threadIdx.x; i < G4 * GK2; i += gridDim.x * blockDim.x) {
        int r = i / GK2, cc = i % GK2;
        float v = (cc < Fsz) ? Wih[(size_t)r * (Esz + Fsz) + Esz + cc]
                             : Whh[(size_t)r * Hsz + cc - Fsz];
        split2(v, h[i], l[i]);
    }
    for (int i = blockIdx.x * blockDim.x + threadIdx.x; i < G4 * Esz; i += gridDim.x * blockDim.x) {
        int r = i / Esz, cc = i % Esz;
        split2(Wih[(size_t)r * (Esz + Fsz) + cc], eh[i], el[i]);
    }
}

__global__ void build_Wi(const float* __restrict__ Wih, const float* __restrict__ Wic,
                         const float* __restrict__ bih, const float* __restrict__ bic,
                         bf16* __restrict__ h, bf16* __restrict__ l, float* __restrict__ bi)
{
    for (int i = blockIdx.x * blockDim.x + threadIdx.x; i < 1024 * Fsz; i += gridDim.x * blockDim.x) {
        int r = i / Fsz, cc = i % Fsz;
        float v = (r < Hsz) ? Wih[(size_t)r * Fsz + cc] : Wic[(size_t)(r - Hsz) * Fsz + cc];
        split2(v, h[i], l[i]);
        if (i < 1024) bi[i] = (i < Hsz) ? bih[i] : bic[i - Hsz];
    }
}

__global__ void build_Wfc(const float* __restrict__ W, bf16* __restrict__ h, bf16* __restrict__ l)
{
    for (int i = blockIdx.x * blockDim.x + threadIdx.x; i < VPAD * Hsz; i += gridDim.x * blockDim.x) {
        int r = i / Hsz;
        float v = (r < Vsz) ? W[i] : 0.f;
        split2(v, h[i], l[i]);
    }
}

__global__ void build_embA(const float* __restrict__ embW, const int* __restrict__ ids,
                           bf16* __restrict__ h, bf16* __restrict__ l)
{
    for (int i = blockIdx.x * blockDim.x + threadIdx.x; i < MROWS * Esz; i += gridDim.x * blockDim.x) {
        int r = i >> 8, e = i & 255;
        int tt = r >> 8, b = r & 255;
        int id = ids[b * Lsz + tt];
        split2(embW[(size_t)id * Esz + e], h[i], l[i]);
    }
}

__global__ void mean_split(const float* __restrict__ feats, bf16* __restrict__ mh,
                           bf16* __restrict__ ml)
{
    int b = blockIdx.x;
    for (int f = threadIdx.x; f < Fsz; f += blockDim.x) {
        float s = 0.f;
        for (int r = 0; r < Rsz; r++) s += feats[(size_t)(b * Rsz + r) * Fsz + f];
        split2(s * (1.0f / Rsz), mh[b * Fsz + f], ml[b * Fsz + f]);
    }
}

__global__ void init_state()
{
    int idx = blockIdx.x * blockDim.x + threadIdx.x;
    int b = idx >> 9, j = idx & 511;
    float h = g_h0c0[b * 1024 + j];
    float c = g_h0c0[b * 1024 + 512 + j];
    g_c[idx] = c;
    split2(h, g_xhH[b * GK2 + Fsz + j], g_xhL[b * GK2 + Fsz + j]);
}

// ---------------------------------------------------------------------------
extern "C" void kernel_launch(void* const* d_in, const int* in_sizes, int n_in,
                              void* d_out, int out_size)
{
    const float* feats   = (const float*)d_in[0];
    const int*   ids     = (const int*)  d_in[1];
    const int*   lengths = (const int*)  d_in[2];
    const float* embW    = (const float*)d_in[3];
    const float* Wf      = (const float*)d_in[4];
    const float* bf      = (const float*)d_in[5];
    const float* Wh      = (const float*)d_in[6];
    const float* bh      = (const float*)d_in[7];
    const float* Ws      = (const float*)d_in[8];
    const float* bs      = (const float*)d_in[9];
    const float* W_ih    = (const float*)d_in[10];
    const float* b_ih    = (const float*)d_in[11];
    const float* W_hh    = (const float*)d_in[12];
    const float* b_hh    = (const float*)d_in[13];
    const float* Wfc     = (const float*)d_in[14];
    const float* bfc     = (const float*)d_in[15];
    const float* Wi_h    = (const float*)d_in[16];
    const float* bi_h    = (const float*)d_in[17];
    const float* Wi_c    = (const float*)d_in[18];
    const float* bi_c    = (const float*)d_in[19];
    float* out = (float*)d_out;

    void *pv;
    cudaGetSymbolAddress(&pv, g_featH);  bf16* featH = (bf16*)pv;
    cudaGetSymbolAddress(&pv, g_featL);  bf16* featL = (bf16*)pv;
    cudaGetSymbolAddress(&pv, g_meanH);  bf16* meanH = (bf16*)pv;
    cudaGetSymbolAddress(&pv, g_meanL);  bf16* meanL = (bf16*)pv;
    cudaGetSymbolAddress(&pv, g_WfH);    bf16* WfH = (bf16*)pv;
    cudaGetSymbolAddress(&pv, g_WfL);    bf16* WfL = (bf16*)pv;
    cudaGetSymbolAddress(&pv, g_WhH);    bf16* WhH = (bf16*)pv;
    cudaGetSymbolAddress(&pv, g_WhL);    bf16* WhL = (bf16*)pv;
    cudaGetSymbolAddress(&pv, g_Wg2H);   bf16* Wg2H = (bf16*)pv;
    cudaGetSymbolAddress(&pv, g_Wg2L);   bf16* Wg2L = (bf16*)pv;
    cudaGetSymbolAddress(&pv, g_WihEH);  bf16* WihEH = (bf16*)pv;
    cudaGetSymbolAddress(&pv, g_WihEL);  bf16* WihEL = (bf16*)pv;
    cudaGetSymbolAddress(&pv, g_WiH);    bf16* WiH = (bf16*)pv;
    cudaGetSymbolAddress(&pv, g_WiL);    bf16* WiL = (bf16*)pv;
    cudaGetSymbolAddress(&pv, g_bi);     float* bi = (float*)pv;
    cudaGetSymbolAddress(&pv, g_WfcH);   bf16* WfcH = (bf16*)pv;
    cudaGetSymbolAddress(&pv, g_WfcL);   bf16* WfcL = (bf16*)pv;
    cudaGetSymbolAddress(&pv, g_h0c0);   float* h0c0 = (float*)pv;
    cudaGetSymbolAddress(&pv, g_embAH);  bf16* embAH = (bf16*)pv;
    cudaGetSymbolAddress(&pv, g_embAL);  bf16* embAL = (bf16*)pv;
    cudaGetSymbolAddress(&pv, g_embproj);float* embproj = (float*)pv;
    cudaGetSymbolAddress(&pv, g_histH);  bf16* histH = (bf16*)pv;
    cudaGetSymbolAddress(&pv, g_histL);  bf16* histL = (bf16*)pv;
    cudaGetSymbolAddress(&pv, g_fproj);  float* fproj = (float*)pv;

    // raise dynamic smem limits (idempotent)
    cudaFuncSetAttribute(mma_gemm<0>, cudaFuncAttributeMaxDynamicSharedMemorySize, SMEM_DYN);
    cudaFuncSetAttribute(mma_gemm<1>, cudaFuncAttributeMaxDynamicSharedMemorySize, SMEM_DYN);
    cudaFuncSetAttribute(mma_gemm<2>, cudaFuncAttributeMaxDynamicSharedMemorySize, SMEM_DYN);
    cudaFuncSetAttribute(mma_gemm<3>, cudaFuncAttributeMaxDynamicSharedMemorySize, SMEM_DYN);
    cudaFuncSetAttribute(decoder_loop, cudaFuncAttributeMaxDynamicSharedMemorySize, SMEM_DYN);

    // ---- conversions ----
    split_arr<<<1024, 256>>>(feats, featH, featL, NFEAT);
    split_arr<<<256, 256>>>(Wf, WfH, WfL, Asz * Fsz);
    split_arr<<<128, 256>>>(Wh, WhH, WhL, Asz * Hsz);
    build_Wg2<<<512, 256>>>(W_ih, W_hh, Wg2H, Wg2L, WihEH, WihEL);
    build_Wi<<<256, 256>>>(Wi_h, Wi_c, bi_h, bi_c, WiH, WiL, bi);
    build_Wfc<<<512, 256>>>(Wfc, WfcH, WfcL);
    build_embA<<<256, 256>>>(embW, ids, embAH, embAL);
    mean_split<<<Bsz, 256>>>(feats, meanH, meanL);

    // ---- init state ----
    mma_gemm<3><<<dim3(8, 2, 1), 256, SMEM_DYN>>>(meanH, meanL, WiH, WiL, bi, h0c0,
                                                  Bsz, 1024, Fsz, Fsz, Fsz, nullptr, 0);
    init_state<<<(Bsz * Hsz) / 256, 256>>>();

    // ---- f_proj ----
    mma_gemm<0><<<dim3(4, 98, 1), 256, SMEM_DYN>>>(featH, featL, WfH, WfL, bf, fproj,
                                                   Bsz * Rsz, Asz, Fsz, Fsz, Fsz, nullptr, 0);

    // ---- embproj ----
    mma_gemm<1><<<dim3(16, 46, 1), 256, SMEM_DYN>>>(embAH, embAL, WihEH, WihEL, nullptr,
                                                    embproj, MROWS, G4, Esz, Esz, Esz,
                                                    nullptr, -1);

    // ---- persistent recurrence ----
    decoder_loop<<<PGRID, 256, SMEM_DYN>>>(feats, Ws, bs, bh, b_ih, b_hh, lengths);

    // ---- final FC ----
    mma_gemm<2><<<dim3(VPAD / 128, MROWS / 128, 1), 256, SMEM_DYN>>>(
        histH, histL, WfcH, WfcL, bfc, out,
        MROWS, VPAD, Hsz, Hsz, Hsz, lengths, 0);
}

// round 12
// speedup vs baseline: 1.7476x; 1.2619x over previous
#include <cuda_runtime.h>
#include <cuda_bf16.h>
#include <cstdint>
#include <math.h>

#define Bsz 256
#define Lsz 24
#define Rsz 49
#define Fsz 2048
#define Esz 256
#define Hsz 512
#define Asz 512
#define Vsz 10000
#define STEPS 23
#define G4 2048
#define GK2 2560
#define VPAD 10112
#define MROWS (STEPS * Bsz)
#define NFEAT (Bsz * Rsz * Fsz)

#define LOOPC 128          // loop-participant CTAs (barrier cohort)
#define PALL 148           // total persistent grid (<= SM count)
#define FCM 46             // MROWS/128
#define FCN 79             // VPAD/128
#define FCT (FCM * FCN)

#define SST 10240
#define STAGE_BYTES 40960
#define SMEM_DYN 81920

typedef __nv_bfloat16 bf16;

// ---------------- scratch ----------------
__device__ float g_fproj[Bsz * Rsz * Asz];
__device__ bf16  g_featH[NFEAT], g_featL[NFEAT];
__device__ bf16  g_meanH[Bsz * Fsz], g_meanL[Bsz * Fsz];
__device__ bf16  g_WfH[Asz * Fsz],  g_WfL[Asz * Fsz];
__device__ bf16  g_WhH[Asz * Hsz],  g_WhL[Asz * Hsz];
__device__ bf16  g_Wg2H[G4 * GK2],  g_Wg2L[G4 * GK2];
__device__ bf16  g_WihEH[G4 * Esz], g_WihEL[G4 * Esz];
__device__ bf16  g_WiH[1024 * Fsz], g_WiL[1024 * Fsz];
__device__ float g_bi[1024];
__device__ bf16  g_WfcH[VPAD * Hsz], g_WfcL[VPAD * Hsz];
__device__ float g_h0c0[Bsz * 1024];
__device__ float g_c[Bsz * Hsz];
__device__ bf16  g_xhH[Bsz * GK2], g_xhL[Bsz * GK2];
__device__ bf16  g_embAH[MROWS * Esz], g_embAL[MROWS * Esz];
__device__ float g_embproj[MROWS * G4];
__device__ bf16  g_histH[MROWS * Hsz], g_histL[MROWS * Hsz];
__device__ float g_gpart[4 * Bsz * G4];
__device__ float g_hppart[8 * Bsz * Asz];

// tree barrier state (128 participants: 8 leaves x 16)
__device__ unsigned g_bar_leaf[8 * 32];
__device__ unsigned g_bar_root = 0;
__device__ unsigned g_bar_gen = 0;
// FC overlap state
__device__ unsigned g_step_done = 0;
__device__ unsigned g_fc_ticket = 0;

__device__ __forceinline__ void split2(float x, bf16& h, bf16& l) {
    h = __float2bfloat16(x);
    l = __float2bfloat16(x - __bfloat162float(h));
}

__device__ __forceinline__ void mma_bf16(float* c, const unsigned* a, const unsigned* b) {
    asm volatile(
        "mma.sync.aligned.m16n8k16.row.col.f32.bf16.bf16.f32 "
        "{%0,%1,%2,%3},{%4,%5,%6,%7},{%8,%9},{%0,%1,%2,%3};\n"
        : "+f"(c[0]), "+f"(c[1]), "+f"(c[2]), "+f"(c[3])
        : "r"(a[0]), "r"(a[1]), "r"(a[2]), "r"(a[3]), "r"(b[0]), "r"(b[1]));
}

__device__ __forceinline__ void ldsm_x4(unsigned& r0, unsigned& r1, unsigned& r2, unsigned& r3,
                                        unsigned addr) {
    asm volatile("ldmatrix.sync.aligned.m8n8.x4.shared.b16 {%0,%1,%2,%3},[%4];"
                 : "=r"(r0), "=r"(r1), "=r"(r2), "=r"(r3) : "r"(addr));
}
__device__ __forceinline__ void ldsm_x2(unsigned& r0, unsigned& r1, unsigned addr) {
    asm volatile("ldmatrix.sync.aligned.m8n8.x2.shared.b16 {%0,%1},[%2];"
                 : "=r"(r0), "=r"(r1) : "r"(addr));
}

__device__ __forceinline__ void cpa16(unsigned dst, const bf16* src) {
    asm volatile("cp.async.cg.shared.global [%0], [%1], 16;" :: "r"(dst), "l"(src));
}
__device__ __forceinline__ void cpcommit() { asm volatile("cp.async.commit_group;"); }
template <int N> __device__ __forceinline__ void cpwait() {
    asm volatile("cp.async.wait_group %0;" :: "n"(N));
}

// grid tree barrier among the first LOOPC CTAs only
__device__ __forceinline__ void gsync() {
    __syncthreads();
    if (threadIdx.x == 0) {
        __threadfence();
        unsigned gen = *((volatile unsigned*)&g_bar_gen);
        int leaf = (blockIdx.x >> 4) & 7;
        if (atomicAdd(&g_bar_leaf[leaf * 32], 1u) == 15u) {
            atomicExch(&g_bar_leaf[leaf * 32], 0u);
            if (atomicAdd(&g_bar_root, 1u) == 7u) {
                atomicExch(&g_bar_root, 0u);
                __threadfence();
                atomicAdd(&g_bar_gen, 1u);
            } else {
                while (*((volatile unsigned*)&g_bar_gen) == gen) { }
            }
        } else {
            while (*((volatile unsigned*)&g_bar_gen) == gen) { }
        }
        __threadfence();
    }
    __syncthreads();
}

// ---------------------------------------------------------------------------
// HMMA pipelined tile machinery (128x128 tile, BK=32, 2-stage cp.async)
// ---------------------------------------------------------------------------
__device__ __forceinline__ void load_chunk(
    unsigned sb, const bf16* __restrict__ Ah, const bf16* __restrict__ Al,
    const bf16* __restrict__ Bh, const bf16* __restrict__ Bl,
    int m0, int n0, int lda, int ldb, int kg)
{
    const int tid = threadIdx.x;
    const int ldr = tid >> 2, ldc = tid & 3;
#pragma unroll
    for (int i = 0; i < 2; i++) {
        int r = ldr + i * 64;
        size_t ga = (size_t)(m0 + r) * lda + kg + ldc * 8;
        size_t gb = (size_t)(n0 + r) * ldb + kg + ldc * 8;
        unsigned off = (unsigned)((r * 5 + ldc) * 16);
        cpa16(sb + off,           Ah + ga);
        cpa16(sb + SST + off,     Al + ga);
        cpa16(sb + 2 * SST + off, Bh + gb);
        cpa16(sb + 3 * SST + off, Bl + gb);
    }
}

__device__ __forceinline__ void mma_chunk(unsigned sb, float acc[4][4][4])
{
    const int lane = threadIdx.x & 31, warp = threadIdx.x >> 5;
    const int wm = warp >> 2, wn = warp & 3;
#pragma unroll
    for (int k16 = 0; k16 < 2; k16++) {
        const int aro = wm * 64 + (lane & 15);
        const int aco = k16 * 16 + ((lane >> 4) << 3);
        const int bro = wn * 32 + (lane & 7);
        const int bco = k16 * 16 + (((lane >> 3) & 1) << 3);
        unsigned ah[4][4], al[4][4], bh2[4][2], bl2[4][2];
#pragma unroll
        for (int mt = 0; mt < 4; mt++) {
            unsigned off = (unsigned)(((aro + mt * 16) * 40 + aco) * 2);
            ldsm_x4(ah[mt][0], ah[mt][1], ah[mt][2], ah[mt][3], sb + off);
            ldsm_x4(al[mt][0], al[mt][1], al[mt][2], al[mt][3], sb + SST + off);
        }
#pragma unroll
        for (int nt = 0; nt < 4; nt++) {
            unsigned off = (unsigned)(((bro + nt * 8) * 40 + bco) * 2);
            ldsm_x2(bh2[nt][0], bh2[nt][1], sb + 2 * SST + off);
            ldsm_x2(bl2[nt][0], bl2[nt][1], sb + 3 * SST + off);
        }
#pragma unroll
        for (int nt = 0; nt < 4; nt++)
#pragma unroll
            for (int mt = 0; mt < 4; mt++) {
                mma_bf16(acc[mt][nt], ah[mt], bh2[nt]);
                mma_bf16(acc[mt][nt], al[mt], bh2[nt]);
                mma_bf16(acc[mt][nt], ah[mt], bl2[nt]);
            }
    }
}

__device__ __forceinline__ void mma_tile_pipe(
    const bf16* __restrict__ Ah, const bf16* __restrict__ Al,
    const bf16* __restrict__ Bh, const bf16* __restrict__ Bl,
    int m0, int n0, int lda, int ldb, int kbase, int kcnt,
    float acc[4][4][4], unsigned sm_u)
{
    const int nch = kcnt >> 5;
    load_chunk(sm_u, Ah, Al, Bh, Bl, m0, n0, lda, ldb, kbase);
    cpcommit();
    for (int ic = 0; ic < nch; ic++) {
        if (ic + 1 < nch) {
            load_chunk(sm_u + ((ic + 1) & 1) * STAGE_BYTES, Ah, Al, Bh, Bl,
                       m0, n0, lda, ldb, kbase + (ic + 1) * 32);
            cpcommit();
            cpwait<1>();
        } else {
            cpwait<0>();
        }
        __syncthreads();
        mma_chunk(sm_u + (ic & 1) * STAGE_BYTES, acc);
        __syncthreads();
    }
}

__device__ void mma_tile_raw(
    const bf16* __restrict__ Ah, const bf16* __restrict__ Al,
    const bf16* __restrict__ Bh, const bf16* __restrict__ Bl,
    int m0, int n0, int lda, int ldb, int kbase, int kcnt,
    float* __restrict__ C, int N, unsigned sm_u)
{
    float acc[4][4][4] = {};
    mma_tile_pipe(Ah, Al, Bh, Bl, m0, n0, lda, ldb, kbase, kcnt, acc, sm_u);
    const int lane = threadIdx.x & 31, warp = threadIdx.x >> 5;
    const int wm = warp >> 2, wn = warp & 3;
    const int grp = lane >> 2, tig = lane & 3;
#pragma unroll
    for (int mt = 0; mt < 4; mt++)
#pragma unroll
        for (int nt = 0; nt < 4; nt++) {
            int row = m0 + wm * 64 + mt * 16 + grp;
            int col = n0 + wn * 32 + nt * 8 + tig * 2;
            float* a = acc[mt][nt];
            C[(size_t)row * N + col]           = a[0];
            C[(size_t)row * N + col + 1]       = a[1];
            C[(size_t)(row + 8) * N + col]     = a[2];
            C[(size_t)(row + 8) * N + col + 1] = a[3];
        }
}

// ---------------------------------------------------------------------------
// Attention body
// ---------------------------------------------------------------------------
__device__ void attn_one(int b, int t, const float* __restrict__ feats,
                         const float* __restrict__ Ws, const float* __restrict__ bs,
                         const float* __restrict__ bh, const int* __restrict__ lengths,
                         float* sbuf)
{
    if (lengths[b] <= t) return;

    float* hp_s = sbuf;
    float* ws_s = sbuf + 512;
    float* sc_s = sbuf + 1024;
    int tid = threadIdx.x;
#pragma unroll
    for (int i = 0; i < 2; i++) {
        int a = tid + i * 256;
        float s = bh[a];
#pragma unroll
        for (int p = 0; p < 8; p++) s += g_hppart[(size_t)p * Bsz * Asz + b * Asz + a];
        hp_s[a] = s;
        ws_s[a] = Ws[a];
    }
    __syncthreads();

    int warp = tid >> 5, lane = tid & 31;
    for (int r = warp; r < Rsz; r += 8) {
        const float* fp = &g_fproj[(size_t)(b * Rsz + r) * Asz];
        float s = 0.f;
        for (int a = lane; a < Asz; a += 32)
            s += tanhf(fp[a] + hp_s[a]) * ws_s[a];
#pragma unroll
        for (int o = 16; o; o >>= 1) s += __shfl_down_sync(0xffffffffu, s, o);
        if (lane == 0) sc_s[r] = s + bs[0];
    }
    __syncthreads();

    if (warp == 0) {
        float v1 = (lane < Rsz) ? sc_s[lane] : -INFINITY;
        float v2 = (lane + 32 < Rsz) ? sc_s[lane + 32] : -INFINITY;
        float mx = fmaxf(v1, v2);
#pragma unroll
        for (int o = 16; o; o >>= 1) mx = fmaxf(mx, __shfl_xor_sync(0xffffffffu, mx, o));
        float e1 = (lane < Rsz) ? expf(v1 - mx) : 0.f;
        float e2 = (lane + 32 < Rsz) ? expf(v2 - mx) : 0.f;
        float sm2 = e1 + e2;
#pragma unroll
        for (int o = 16; o; o >>= 1) sm2 += __shfl_xor_sync(0xffffffffu, sm2, o);
        float inv = 1.f / sm2;
        if (lane < Rsz) sc_s[lane] = e1 * inv;
        if (lane + 32 < Rsz) sc_s[lane + 32] = e2 * inv;
    }
    __syncthreads();

    const float4* f4 = reinterpret_cast<const float4*>(feats);
    for (int f = tid; f < Fsz / 4; f += 256) {
        float ax = 0.f, ay = 0.f, az = 0.f, aw = 0.f;
#pragma unroll 7
        for (int r = 0; r < Rsz; r++) {
            float4 v = f4[(size_t)(b * Rsz + r) * (Fsz / 4) + f];
            float al = sc_s[r];
            ax = fmaf(al, v.x, ax); ay = fmaf(al, v.y, ay);
            az = fmaf(al, v.z, az); aw = fmaf(al, v.w, aw);
        }
        int fb = f * 4;
        split2(ax, g_xhH[b * GK2 + fb],     g_xhL[b * GK2 + fb]);
        split2(ay, g_xhH[b * GK2 + fb + 1], g_xhL[b * GK2 + fb + 1]);
        split2(az, g_xhH[b * GK2 + fb + 2], g_xhL[b * GK2 + fb + 2]);
        split2(aw, g_xhH[b * GK2 + fb + 3], g_xhL[b * GK2 + fb + 3]);
    }
    __syncthreads();
}

// ---------------------------------------------------------------------------
// Persistent kernel: step loop (CTAs 0..127) + FC workers (CTAs 128..147),
// then everyone drains the FC tile queue.
// ---------------------------------------------------------------------------
__global__ __launch_bounds__(256, 1) void decoder_loop(
    const float* __restrict__ feats, const float* __restrict__ Ws,
    const float* __restrict__ bs, const float* __restrict__ bh,
    const float* __restrict__ bih, const float* __restrict__ bhh,
    const float* __restrict__ bfc, const int* __restrict__ lengths,
    float* __restrict__ out)
{
    extern __shared__ __align__(16) char dsm[];
    unsigned sm_u = (unsigned)__cvta_generic_to_shared(dsm);
    const int cta = blockIdx.x;
    const int tid = threadIdx.x;
    __shared__ int s_tk;

    if (cta < LOOPC) {
        for (int t = 0; t < STEPS; t++) {
            // Phase 1: hp partials = h @ Wh^T  (2m x 4n x 8 split-K = 64 CTAs)
            if (cta < 64) {
                int kp = cta & 7, tile = cta >> 3;
                int m = tile & 1, n = tile >> 1;
                if (lengths[m * 128] > t)
                    mma_tile_raw(g_xhH + Fsz, g_xhL + Fsz, g_WhH, g_WhL,
                                 m * 128, n * 128, GK2, Hsz, kp * 64, 64,
                                 g_hppart + (size_t)kp * Bsz * Asz, Asz, sm_u);
            }
            gsync();

            // Phase 2: attention
            for (int b = cta; b < Bsz; b += LOOPC)
                attn_one(b, t, feats, Ws, bs, bh, lengths, (float*)dsm);
            gsync();

            // Phase 3: gates partials (2m x 16n x 4 split-K = 128 CTAs)
            {
                int kp = cta & 3, tile = cta >> 2;
                int m = tile & 1, n = tile >> 1;
                if (lengths[m * 128] > t)
                    mma_tile_raw(g_xhH, g_xhL, g_Wg2H, g_Wg2L,
                                 m * 128, n * 128, GK2, GK2, kp * 640, 640,
                                 g_gpart + (size_t)kp * Bsz * G4, G4, sm_u);
            }
            gsync();

            // Phase 4: LSTM pointwise
            for (int idx = cta * 256 + tid; idx < Bsz * Hsz; idx += LOOPC * 256) {
                int b = idx >> 9, j = idx & 511;
                if (lengths[b] > t) {
                    const int MN = Bsz * G4;
                    int base = b * G4;
                    const float* ep = &g_embproj[(size_t)(t * Bsz + b) * G4];
                    float gv[4];
#pragma unroll
                    for (int q = 0; q < 4; q++) {
                        int jj = q * 512 + j;
                        gv[q] = g_gpart[base + jj] + g_gpart[MN + base + jj]
                              + g_gpart[2 * MN + base + jj] + g_gpart[3 * MN + base + jj]
                              + ep[jj] + bih[jj] + bhh[jj];
                    }
                    float ig = 1.f / (1.f + expf(-gv[0]));
                    float fg = 1.f / (1.f + expf(-gv[1]));
                    float gg = tanhf(gv[2]);
                    float og = 1.f / (1.f + expf(-gv[3]));
                    float cn = fg * g_c[idx] + ig * gg;
                    float hn = og * tanhf(cn);
                    g_c[idx] = cn;
                    split2(hn, g_xhH[b * GK2 + Fsz + j], g_xhL[b * GK2 + Fsz + j]);
                    split2(hn, g_histH[(size_t)(t * Bsz + b) * Hsz + j],
                               g_histL[(size_t)(t * Bsz + b) * Hsz + j]);
                }
            }
            gsync();
            // publish step completion (hist writes fenced by gsync)
            if (cta == 0 && tid == 0)
                atomicExch(&g_step_done, (unsigned)(t + 1));
        }
    }

    // ---- FC tile drain (workers start immediately; loop CTAs join at end) ----
    for (;;) {
        if (tid == 0) s_tk = (int)atomicAdd(&g_fc_ticket, 1u);
        __syncthreads();
        int tk = s_tk;
        __syncthreads();
        if (tk >= FCT) break;

        int my = tk / FCN, nx = tk - my * FCN;
        int m0 = my * 128, n0 = nx * 128;
        int tt = m0 >> 8, b0 = m0 & 255;

        if (lengths[b0] <= tt) {
            // dead tile: zeros (no wait needed)
            for (int i = tid; i < 128 * 128; i += 256) {
                int r = i >> 7, cc = i & 127;
                int n = n0 + cc;
                if (n < Vsz)
                    out[((size_t)(b0 + r) * STEPS + tt) * Vsz + n] = 0.f;
            }
            continue;
        }

        // wait for step tt's hist rows
        if (tid == 0) {
            while (*((volatile unsigned*)&g_step_done) <= (unsigned)tt) { }
        }
        __syncthreads();
        __threadfence();

        float acc[4][4][4] = {};
        mma_tile_pipe(g_histH, g_histL, g_WfcH, g_WfcL,
                      m0, n0, Hsz, Hsz, 0, Hsz, acc, sm_u);

        const int lane = tid & 31, warp = tid >> 5;
        const int wm = warp >> 2, wn = warp & 3;
        const int grp = lane >> 2, tig = lane & 3;
#pragma unroll
        for (int mt = 0; mt < 4; mt++)
#pragma unroll
            for (int nt = 0; nt < 4; nt++) {
                int row = m0 + wm * 64 + mt * 16 + grp;
                int col = n0 + wn * 32 + nt * 8 + tig * 2;
                float* a = acc[mt][nt];
                if (col < Vsz) {
                    int b0r = row & 255, tt0 = row >> 8;
                    int b1r = (row + 8) & 255, tt1 = (row + 8) >> 8;
                    bool act0 = lengths[b0r] > tt0;
                    bool act1 = lengths[b1r] > tt1;
                    float* p0 = out + ((size_t)b0r * STEPS + tt0) * Vsz;
                    float* p1 = out + ((size_t)b1r * STEPS + tt1) * Vsz;
                    p0[col]     = act0 ? (a[0] + bfc[col])     : 0.f;
                    p0[col + 1] = act0 ? (a[1] + bfc[col + 1]) : 0.f;
                    p1[col]     = act1 ? (a[2] + bfc[col])     : 0.f;
                    p1[col + 1] = act1 ? (a[3] + bfc[col + 1]) : 0.f;
                }
            }
    }
}

// ---------------------------------------------------------------------------
// Host HMMA GEMM (precompute). EPI: 0 = +bias, 1 = raw, 3 = tanh(+bias)
// ---------------------------------------------------------------------------
template <int EPI>
__global__ __launch_bounds__(256) void mma_gemm(
    const bf16* __restrict__ Ah, const bf16* __restrict__ Al,
    const bf16* __restrict__ Bh, const bf16* __restrict__ Bl,
    const float* __restrict__ bias, float* __restrict__ C,
    int M, int N, int lda, int ldb, int kspl)
{
    const int m0 = blockIdx.y * 128;
    const int n0 = blockIdx.x * 128;
    const int tid = threadIdx.x;

    extern __shared__ __align__(16) char dsm[];
    unsigned sm_u = (unsigned)__cvta_generic_to_shared(dsm);

    const int lane = tid & 31, warp = tid >> 5;
    const int wm = warp >> 2, wn = warp & 3;
    const int grp = lane >> 2, tig = lane & 3;
    const int kbase = (EPI == 1) ? blockIdx.z * kspl : 0;

    float acc[4][4][4] = {};
    mma_tile_pipe(Ah, Al, Bh, Bl, m0, n0, lda, ldb, kbase, kspl, acc, sm_u);

    float* Cp = C;
    if (EPI == 1) Cp = C + (size_t)blockIdx.z * M * N;

#pragma unroll
    for (int mt = 0; mt < 4; mt++)
#pragma unroll
        for (int nt = 0; nt < 4; nt++) {
            int row = m0 + wm * 64 + mt * 16 + grp;
            int col = n0 + wn * 32 + nt * 8 + tig * 2;
            float* a = acc[mt][nt];
            if (EPI == 0) {
                Cp[(size_t)row * N + col]           = a[0] + bias[col];
                Cp[(size_t)row * N + col + 1]       = a[1] + bias[col + 1];
                Cp[(size_t)(row + 8) * N + col]     = a[2] + bias[col];
                Cp[(size_t)(row + 8) * N + col + 1] = a[3] + bias[col + 1];
            } else if (EPI == 3) {
                Cp[(size_t)row * N + col]           = tanhf(a[0] + bias[col]);
                Cp[(size_t)row * N + col + 1]       = tanhf(a[1] + bias[col + 1]);
                Cp[(size_t)(row + 8) * N + col]     = tanhf(a[2] + bias[col]);
                Cp[(size_t)(row + 8) * N + col + 1] = tanhf(a[3] + bias[col + 1]);
            } else {
                Cp[(size_t)row * N + col]           = a[0];
                Cp[(size_t)row * N + col + 1]       = a[1];
                Cp[(size_t)(row + 8) * N + col]     = a[2];
                Cp[(size_t)(row + 8) * N + col + 1] = a[3];
            }
        }
}

// ---------------------------------------------------------------------------
// conversion / setup kernels
// ---------------------------------------------------------------------------
__global__ void split_arr(const float* __restrict__ src, bf16* __restrict__ h,
                          bf16* __restrict__ l, int n)
{
    for (int i = blockIdx.x * blockDim.x + threadIdx.x; i < n; i += gridDim.x * blockDim.x)
        split2(src[i], h[i], l[i]);
}

__global__ void build_Wg2(const float* __restrict__ Wih, const float* __restrict__ Whh,
                          bf16* __restrict__ h, bf16* __restrict__ l,
                          bf16* __restrict__ eh, bf16* __restrict__ el)
{
    for (int i = blockIdx.x * blockDim.x + threadIdx.x; i < G4 * GK2; i += gridDim.x * blockDim.x) {
        int r = i / GK2, cc = i % GK2;
        float v = (cc < Fsz) ? Wih[(size_t)r * (Esz + Fsz) + Esz + cc]
                             : Whh[(size_t)r * Hsz + cc - Fsz];
        split2(v, h[i], l[i]);
    }
    for (int i = blockIdx.x * blockDim.x + threadIdx.x; i < G4 * Esz; i += gridDim.x * blockDim.x) {
        int r = i / Esz, cc = i % Esz;
        split2(Wih[(size_t)r * (Esz + Fsz) + cc], eh[i], el[i]);
    }
}

__global__ void build_Wi(const float* __restrict__ Wih, const float* __restrict__ Wic,
                         const float* __restrict__ bih, const float* __restrict__ bic,
                         bf16* __restrict__ h, bf16* __restrict__ l, float* __restrict__ bi)
{
    for (int i = blockIdx.x * blockDim.x + threadIdx.x; i < 1024 * Fsz; i += gridDim.x * blockDim.x) {
        int r = i / Fsz, cc = i % Fsz;
        float v = (r < Hsz) ? Wih[(size_t)r * Fsz + cc] : Wic[(size_t)(r - Hsz) * Fsz + cc];
        split2(v, h[i], l[i]);
        if (i < 1024) bi[i] = (i < Hsz) ? bih[i] : bic[i - Hsz];
    }
}

__global__ void build_Wfc(const float* __restrict__ W, bf16* __restrict__ h, bf16* __restrict__ l)
{
    for (int i = blockIdx.x * blockDim.x + threadIdx.x; i < VPAD * Hsz; i += gridDim.x * blockDim.x) {
        int r = i >> 9;
        float v = (r < Vsz) ? W[i] : 0.f;
        split2(v, h[i], l[i]);
    }
}

__global__ void build_embA(const float* __restrict__ embW, const int* __restrict__ ids,
                           bf16* __restrict__ h, bf16* __restrict__ l)
{
    for (int i = blockIdx.x * blockDim.x + threadIdx.x; i < MROWS * Esz; i += gridDim.x * blockDim.x) {
        int r = i >> 8, e = i & 255;
        int tt = r >> 8, b = r & 255;
        int id = ids[b * Lsz + tt];
        split2(embW[(size_t)id * Esz + e], h[i], l[i]);
    }
}

// merged: mean + feats hi/lo split (single feats pass)
__global__ void mean_split_feats(const float* __restrict__ feats,
                                 bf16* __restrict__ mh, bf16* __restrict__ ml,
                                 bf16* __restrict__ fh, bf16* __restrict__ fl)
{
    int b = blockIdx.x;
    for (int f = threadIdx.x; f < Fsz; f += blockDim.x) {
        float s = 0.f;
        for (int r = 0; r < Rsz; r++) {
            size_t idx = (size_t)(b * Rsz + r) * Fsz + f;
            float v = feats[idx];
            s += v;
            split2(v, fh[idx], fl[idx]);
        }
        split2(s * (1.0f / Rsz), mh[b * Fsz + f], ml[b * Fsz + f]);
    }
}

__global__ void init_state()
{
    int idx = blockIdx.x * blockDim.x + threadIdx.x;
    int b = idx >> 9, j = idx & 511;
    float h = g_h0c0[b * 1024 + j];
    float c = g_h0c0[b * 1024 + 512 + j];
    g_c[idx] = c;
    split2(h, g_xhH[b * GK2 + Fsz + j], g_xhL[b * GK2 + Fsz + j]);
    if (idx == 0) {
        g_step_done = 0;
        g_fc_ticket = 0;
    }
}

// ---------------------------------------------------------------------------
extern "C" void kernel_launch(void* const* d_in, const int* in_sizes, int n_in,
                              void* d_out, int out_size)
{
    const float* feats   = (const float*)d_in[0];
    const int*   ids     = (const int*)  d_in[1];
    const int*   lengths = (const int*)  d_in[2];
    const float* embW    = (const float*)d_in[3];
    const float* Wf      = (const float*)d_in[4];
    const float* bf      = (const float*)d_in[5];
    const float* Wh      = (const float*)d_in[6];
    const float* bh      = (const float*)d_in[7];
    const float* Ws      = (const float*)d_in[8];
    const float* bs      = (const float*)d_in[9];
    const float* W_ih    = (const float*)d_in[10];
    const float* b_ih    = (const float*)d_in[11];
    const float* W_hh    = (const float*)d_in[12];
    const float* b_hh    = (const float*)d_in[13];
    const float* Wfc     = (const float*)d_in[14];
    const float* bfc     = (const float*)d_in[15];
    const float* Wi_h    = (const float*)d_in[16];
    const float* bi_h    = (const float*)d_in[17];
    const float* Wi_c    = (const float*)d_in[18];
    const float* bi_c    = (const float*)d_in[19];
    float* out = (float*)d_out;

    void *pv;
    cudaGetSymbolAddress(&pv, g_featH);  bf16* featH = (bf16*)pv;
    cudaGetSymbolAddress(&pv, g_featL);  bf16* featL = (bf16*)pv;
    cudaGetSymbolAddress(&pv, g_meanH);  bf16* meanH = (bf16*)pv;
    cudaGetSymbolAddress(&pv, g_meanL);  bf16* meanL = (bf16*)pv;
    cudaGetSymbolAddress(&pv, g_WfH);    bf16* WfH = (bf16*)pv;
    cudaGetSymbolAddress(&pv, g_WfL);    bf16* WfL = (bf16*)pv;
    cudaGetSymbolAddress(&pv, g_WhH);    bf16* WhH = (bf16*)pv;
    cudaGetSymbolAddress(&pv, g_WhL);    bf16* WhL = (bf16*)pv;
    cudaGetSymbolAddress(&pv, g_Wg2H);   bf16* Wg2H = (bf16*)pv;
    cudaGetSymbolAddress(&pv, g_Wg2L);   bf16* Wg2L = (bf16*)pv;
    cudaGetSymbolAddress(&pv, g_WihEH);  bf16* WihEH = (bf16*)pv;
    cudaGetSymbolAddress(&pv, g_WihEL);  bf16* WihEL = (bf16*)pv;
    cudaGetSymbolAddress(&pv, g_WiH);    bf16* WiH = (bf16*)pv;
    cudaGetSymbolAddress(&pv, g_WiL);    bf16* WiL = (bf16*)pv;
    cudaGetSymbolAddress(&pv, g_bi);     float* bi = (float*)pv;
    cudaGetSymbolAddress(&pv, g_WfcH);   bf16* WfcH = (bf16*)pv;
    cudaGetSymbolAddress(&pv, g_WfcL);   bf16* WfcL = (bf16*)pv;
    cudaGetSymbolAddress(&pv, g_h0c0);   float* h0c0 = (float*)pv;
    cudaGetSymbolAddress(&pv, g_embAH);  bf16* embAH = (bf16*)pv;
    cudaGetSymbolAddress(&pv, g_embAL);  bf16* embAL = (bf16*)pv;
    cudaGetSymbolAddress(&pv, g_embproj);float* embproj = (float*)pv;
    cudaGetSymbolAddress(&pv, g_fproj);  float* fproj = (float*)pv;

    cudaFuncSetAttribute(mma_gemm<0>, cudaFuncAttributeMaxDynamicSharedMemorySize, SMEM_DYN);
    cudaFuncSetAttribute(mma_gemm<1>, cudaFuncAttributeMaxDynamicSharedMemorySize, SMEM_DYN);
    cudaFuncSetAttribute(mma_gemm<3>, cudaFuncAttributeMaxDynamicSharedMemorySize, SMEM_DYN);
    cudaFuncSetAttribute(decoder_loop, cudaFuncAttributeMaxDynamicSharedMemorySize, SMEM_DYN);

    // ---- conversions ----
    mean_split_feats<<<Bsz, 256>>>(feats, meanH, meanL, featH, featL);
    split_arr<<<256, 256>>>(Wf, WfH, WfL, Asz * Fsz);
    split_arr<<<128, 256>>>(Wh, WhH, WhL, Asz * Hsz);
    build_Wg2<<<512, 256>>>(W_ih, W_hh, Wg2H, Wg2L, WihEH, WihEL);
    build_Wi<<<256, 256>>>(Wi_h, Wi_c, bi_h, bi_c, WiH, WiL, bi);
    build_Wfc<<<512, 256>>>(Wfc, WfcH, WfcL);
    build_embA<<<256, 256>>>(embW, ids, embAH, embAL);

    // ---- init state ----
    mma_gemm<3><<<dim3(8, 2, 1), 256, SMEM_DYN>>>(meanH, meanL, WiH, WiL, bi, h0c0,
                                                  Bsz, 1024, Fsz, Fsz, Fsz);
    init_state<<<(Bsz * Hsz) / 256, 256>>>();

    // ---- f_proj = feats @ Wf^T + bf ----
    mma_gemm<0><<<dim3(4, 98, 1), 256, SMEM_DYN>>>(featH, featL, WfH, WfL, bf, fproj,
                                                   Bsz * Rsz, Asz, Fsz, Fsz, Fsz);

    // ---- embproj = embAll @ W_ih[:, :E]^T ----
    mma_gemm<1><<<dim3(16, 46, 1), 256, SMEM_DYN>>>(embAH, embAL, WihEH, WihEL, nullptr,
                                                    embproj, MROWS, G4, Esz, Esz, Esz);

    // ---- persistent recurrence + overlapped final FC ----
    decoder_loop<<<PALL, 256, SMEM_DYN>>>(feats, Ws, bs, bh, b_ih, b_hh, bfc,
                                          lengths, out);
}

// round 13
// speedup vs baseline: 1.8905x; 1.0818x over previous
#include <cuda_runtime.h>
#include <cuda_bf16.h>
#include <cstdint>
#include <math.h>

#define Bsz 256
#define Lsz 24
#define Rsz 49
#define Fsz 2048
#define Esz 256
#define Hsz 512
#define Asz 512
#define Vsz 10000
#define STEPS 23
#define G4 2048
#define GK2 2560
#define VPAD 10112
#define MROWS (STEPS * Bsz)
#define NFEAT (Bsz * Rsz * Fsz)

#define LOOPC 128          // loop-participant CTAs (barrier cohort)
#define PALL 148           // total persistent grid
#define FCM 46             // MROWS/128
#define FCN 79             // VPAD/128
#define FCT (FCM * FCN)
#define EMBT (STEPS * 32)  // embproj tiles: 23 steps x (2m x 16n) = 736

// BK = 64: per-array stage = 128 rows x 72 bf16 = 18432 B
#define SST 18432
#define STAGE_BYTES 73728
#define SMEM_DYN 147456

typedef __nv_bfloat16 bf16;

// ---------------- scratch ----------------
__device__ float g_fproj[Bsz * Rsz * Asz];
__device__ bf16  g_featH[NFEAT], g_featL[NFEAT];
__device__ bf16  g_meanH[Bsz * Fsz], g_meanL[Bsz * Fsz];
__device__ bf16  g_WfH[Asz * Fsz],  g_WfL[Asz * Fsz];
__device__ bf16  g_WhH[Asz * Hsz],  g_WhL[Asz * Hsz];
__device__ bf16  g_Wg2H[G4 * GK2],  g_Wg2L[G4 * GK2];
__device__ bf16  g_WihEH[G4 * Esz], g_WihEL[G4 * Esz];
__device__ bf16  g_WiH[1024 * Fsz], g_WiL[1024 * Fsz];
__device__ float g_bi[1024];
__device__ bf16  g_WfcH[VPAD * Hsz], g_WfcL[VPAD * Hsz];
__device__ float g_h0c0[Bsz * 1024];
__device__ float g_c[Bsz * Hsz];
__device__ bf16  g_xhH[Bsz * GK2], g_xhL[Bsz * GK2];
__device__ bf16  g_embAH[MROWS * Esz], g_embAL[MROWS * Esz];
__device__ float g_embproj[MROWS * G4];
__device__ bf16  g_histH[MROWS * Hsz], g_histL[MROWS * Hsz];
__device__ float g_gpart[4 * Bsz * G4];
__device__ float g_hppart[8 * Bsz * Asz];

// tree barrier state (128 participants: 8 leaves x 16)
__device__ unsigned g_bar_leaf[8 * 32];
__device__ unsigned g_bar_root = 0;
__device__ unsigned g_bar_gen = 0;
// overlap state
__device__ unsigned g_step_done = 0;
__device__ unsigned g_ticket = 0;
__device__ unsigned g_emb_done[32];

__device__ __forceinline__ void split2(float x, bf16& h, bf16& l) {
    h = __float2bfloat16(x);
    l = __float2bfloat16(x - __bfloat162float(h));
}

__device__ __forceinline__ void mma_bf16(float* c, const unsigned* a, const unsigned* b) {
    asm volatile(
        "mma.sync.aligned.m16n8k16.row.col.f32.bf16.bf16.f32 "
        "{%0,%1,%2,%3},{%4,%5,%6,%7},{%8,%9},{%0,%1,%2,%3};\n"
        : "+f"(c[0]), "+f"(c[1]), "+f"(c[2]), "+f"(c[3])
        : "r"(a[0]), "r"(a[1]), "r"(a[2]), "r"(a[3]), "r"(b[0]), "r"(b[1]));
}

__device__ __forceinline__ void ldsm_x4(unsigned& r0, unsigned& r1, unsigned& r2, unsigned& r3,
                                        unsigned addr) {
    asm volatile("ldmatrix.sync.aligned.m8n8.x4.shared.b16 {%0,%1,%2,%3},[%4];"
                 : "=r"(r0), "=r"(r1), "=r"(r2), "=r"(r3) : "r"(addr));
}
__device__ __forceinline__ void ldsm_x2(unsigned& r0, unsigned& r1, unsigned addr) {
    asm volatile("ldmatrix.sync.aligned.m8n8.x2.shared.b16 {%0,%1},[%2];"
                 : "=r"(r0), "=r"(r1) : "r"(addr));
}

__device__ __forceinline__ void cpa16(unsigned dst, const bf16* src) {
    asm volatile("cp.async.cg.shared.global [%0], [%1], 16;" :: "r"(dst), "l"(src));
}
__device__ __forceinline__ void cpcommit() { asm volatile("cp.async.commit_group;"); }
template <int N> __device__ __forceinline__ void cpwait() {
    asm volatile("cp.async.wait_group %0;" :: "n"(N));
}

// grid tree barrier among the first LOOPC CTAs only
__device__ __forceinline__ void gsync() {
    __syncthreads();
    if (threadIdx.x == 0) {
        __threadfence();
        unsigned gen = *((volatile unsigned*)&g_bar_gen);
        int leaf = (blockIdx.x >> 4) & 7;
        if (atomicAdd(&g_bar_leaf[leaf * 32], 1u) == 15u) {
            atomicExch(&g_bar_leaf[leaf * 32], 0u);
            if (atomicAdd(&g_bar_root, 1u) == 7u) {
                atomicExch(&g_bar_root, 0u);
                __threadfence();
                atomicAdd(&g_bar_gen, 1u);
            } else {
                while (*((volatile unsigned*)&g_bar_gen) == gen) { }
            }
        } else {
            while (*((volatile unsigned*)&g_bar_gen) == gen) { }
        }
        __threadfence();
    }
    __syncthreads();
}

// ---------------------------------------------------------------------------
// HMMA pipelined tile machinery (128x128 tile, BK=64, 2-stage cp.async)
// smem per-array row stride = 72 bf16 (144 B); conflict-free for ldmatrix.
// ---------------------------------------------------------------------------
__device__ __forceinline__ void load_chunk(
    unsigned sb, const bf16* __restrict__ Ah, const bf16* __restrict__ Al,
    const bf16* __restrict__ Bh, const bf16* __restrict__ Bl,
    int m0, int n0, int lda, int ldb, int kg)
{
    const int tid = threadIdx.x;
    const int rr = tid >> 3;          // 0..31
    const int c8 = tid & 7;           // 8 x 16B = 128B = 64 bf16 per row
#pragma unroll
    for (int i = 0; i < 4; i++) {
        int r = rr + i * 32;
        size_t ga = (size_t)(m0 + r) * lda + kg + c8 * 8;
        size_t gb = (size_t)(n0 + r) * ldb + kg + c8 * 8;
        unsigned off = (unsigned)(r * 144 + c8 * 16);
        cpa16(sb + off,           Ah + ga);
        cpa16(sb + SST + off,     Al + ga);
        cpa16(sb + 2 * SST + off, Bh + gb);
        cpa16(sb + 3 * SST + off, Bl + gb);
    }
}

__device__ __forceinline__ void mma_chunk(unsigned sb, float acc[4][4][4])
{
    const int lane = threadIdx.x & 31, warp = threadIdx.x >> 5;
    const int wm = warp >> 2, wn = warp & 3;
#pragma unroll
    for (int k16 = 0; k16 < 4; k16++) {
        const int aro = wm * 64 + (lane & 15);
        const int aco = k16 * 16 + ((lane >> 4) << 3);
        const int bro = wn * 32 + (lane & 7);
        const int bco = k16 * 16 + (((lane >> 3) & 1) << 3);
        unsigned ah[4][4], al[4][4], bh2[4][2], bl2[4][2];
#pragma unroll
        for (int mt = 0; mt < 4; mt++) {
            unsigned off = (unsigned)(((aro + mt * 16) * 72 + aco) * 2);
            ldsm_x4(ah[mt][0], ah[mt][1], ah[mt][2], ah[mt][3], sb + off);
            ldsm_x4(al[mt][0], al[mt][1], al[mt][2], al[mt][3], sb + SST + off);
        }
#pragma unroll
        for (int nt = 0; nt < 4; nt++) {
            unsigned off = (unsigned)(((bro + nt * 8) * 72 + bco) * 2);
            ldsm_x2(bh2[nt][0], bh2[nt][1], sb + 2 * SST + off);
            ldsm_x2(bl2[nt][0], bl2[nt][1], sb + 3 * SST + off);
        }
#pragma unroll
        for (int nt = 0; nt < 4; nt++)
#pragma unroll
            for (int mt = 0; mt < 4; mt++) {
                mma_bf16(acc[mt][nt], ah[mt], bh2[nt]);
                mma_bf16(acc[mt][nt], al[mt], bh2[nt]);
                mma_bf16(acc[mt][nt], ah[mt], bl2[nt]);
            }
    }
}

__device__ __forceinline__ void mma_tile_pipe(
    const bf16* __restrict__ Ah, const bf16* __restrict__ Al,
    const bf16* __restrict__ Bh, const bf16* __restrict__ Bl,
    int m0, int n0, int lda, int ldb, int kbase, int kcnt,
    float acc[4][4][4], unsigned sm_u)
{
    const int nch = kcnt >> 6;        // BK = 64
    load_chunk(sm_u, Ah, Al, Bh, Bl, m0, n0, lda, ldb, kbase);
    cpcommit();
    for (int ic = 0; ic < nch; ic++) {
        if (ic + 1 < nch) {
            load_chunk(sm_u + ((ic + 1) & 1) * STAGE_BYTES, Ah, Al, Bh, Bl,
                       m0, n0, lda, ldb, kbase + (ic + 1) * 64);
            cpcommit();
            cpwait<1>();
        } else {
            cpwait<0>();
        }
        __syncthreads();
        mma_chunk(sm_u + (ic & 1) * STAGE_BYTES, acc);
        __syncthreads();
    }
}

__device__ void mma_tile_raw(
    const bf16* __restrict__ Ah, const bf16* __restrict__ Al,
    const bf16* __restrict__ Bh, const bf16* __restrict__ Bl,
    int m0, int n0, int lda, int ldb, int kbase, int kcnt,
    float* __restrict__ C, int N, unsigned sm_u)
{
    float acc[4][4][4] = {};
    mma_tile_pipe(Ah, Al, Bh, Bl, m0, n0, lda, ldb, kbase, kcnt, acc, sm_u);
    const int lane = threadIdx.x & 31, warp = threadIdx.x >> 5;
    const int wm = warp >> 2, wn = warp & 3;
    const int grp = lane >> 2, tig = lane & 3;
#pragma unroll
    for (int mt = 0; mt < 4; mt++)
#pragma unroll
        for (int nt = 0; nt < 4; nt++) {
            int row = m0 + wm * 64 + mt * 16 + grp;
            int col = n0 + wn * 32 + nt * 8 + tig * 2;
            float* a = acc[mt][nt];
            C[(size_t)row * N + col]           = a[0];
            C[(size_t)row * N + col + 1]       = a[1];
            C[(size_t)(row + 8) * N + col]     = a[2];
            C[(size_t)(row + 8) * N + col + 1] = a[3];
        }
}

// ---------------------------------------------------------------------------
// Attention body
// ---------------------------------------------------------------------------
__device__ void attn_one(int b, int t, const float* __restrict__ feats,
                         const float* __restrict__ Ws, const float* __restrict__ bs,
                         const float* __restrict__ bh, const int* __restrict__ lengths,
                         float* sbuf)
{
    if (lengths[b] <= t) return;

    float* hp_s = sbuf;
    float* ws_s = sbuf + 512;
    float* sc_s = sbuf + 1024;
    int tid = threadIdx.x;
#pragma unroll
    for (int i = 0; i < 2; i++) {
        int a = tid + i * 256;
        float s = bh[a];
#pragma unroll
        for (int p = 0; p < 8; p++) s += g_hppart[(size_t)p * Bsz * Asz + b * Asz + a];
        hp_s[a] = s;
        ws_s[a] = Ws[a];
    }
    __syncthreads();

    int warp = tid >> 5, lane = tid & 31;
    for (int r = warp; r < Rsz; r += 8) {
        const float* fp = &g_fproj[(size_t)(b * Rsz + r) * Asz];
        float s = 0.f;
        for (int a = lane; a < Asz; a += 32)
            s += tanhf(fp[a] + hp_s[a]) * ws_s[a];
#pragma unroll
        for (int o = 16; o; o >>= 1) s += __shfl_down_sync(0xffffffffu, s, o);
        if (lane == 0) sc_s[r] = s + bs[0];
    }
    __syncthreads();

    if (warp == 0) {
        float v1 = (lane < Rsz) ? sc_s[lane] : -INFINITY;
        float v2 = (lane + 32 < Rsz) ? sc_s[lane + 32] : -INFINITY;
        float mx = fmaxf(v1, v2);
#pragma unroll
        for (int o = 16; o; o >>= 1) mx = fmaxf(mx, __shfl_xor_sync(0xffffffffu, mx, o));
        float e1 = (lane < Rsz) ? expf(v1 - mx) : 0.f;
        float e2 = (lane + 32 < Rsz) ? expf(v2 - mx) : 0.f;
        float sm2 = e1 + e2;
#pragma unroll
        for (int o = 16; o; o >>= 1) sm2 += __shfl_xor_sync(0xffffffffu, sm2, o);
        float inv = 1.f / sm2;
        if (lane < Rsz) sc_s[lane] = e1 * inv;
        if (lane + 32 < Rsz) sc_s[lane + 32] = e2 * inv;
    }
    __syncthreads();

    const float4* f4 = reinterpret_cast<const float4*>(feats);
    for (int f = tid; f < Fsz / 4; f += 256) {
        float ax = 0.f, ay = 0.f, az = 0.f, aw = 0.f;
#pragma unroll 7
        for (int r = 0; r < Rsz; r++) {
            float4 v = f4[(size_t)(b * Rsz + r) * (Fsz / 4) + f];
            float al = sc_s[r];
            ax = fmaf(al, v.x, ax); ay = fmaf(al, v.y, ay);
            az = fmaf(al, v.z, az); aw = fmaf(al, v.w, aw);
        }
        int fb = f * 4;
        split2(ax, g_xhH[b * GK2 + fb],     g_xhL[b * GK2 + fb]);
        split2(ay, g_xhH[b * GK2 + fb + 1], g_xhL[b * GK2 + fb + 1]);
        split2(az, g_xhH[b * GK2 + fb + 2], g_xhL[b * GK2 + fb + 2]);
        split2(aw, g_xhH[b * GK2 + fb + 3], g_xhL[b * GK2 + fb + 3]);
    }
    __syncthreads();
}

// ---------------------------------------------------------------------------
// Persistent kernel: step loop (CTAs 0..127) + overlap workers (128..147).
// Worker tickets: [0, EMBT) = embproj tiles, [EMBT, EMBT+FCT) = FC tiles.
// ---------------------------------------------------------------------------
__global__ __launch_bounds__(256, 1) void decoder_loop(
    const float* __restrict__ feats, const float* __restrict__ Ws,
    const float* __restrict__ bs, const float* __restrict__ bh,
    const float* __restrict__ bih, const float* __restrict__ bhh,
    const float* __restrict__ bfc, const int* __restrict__ lengths,
    float* __restrict__ out)
{
    extern __shared__ __align__(16) char dsm[];
    unsigned sm_u = (unsigned)__cvta_generic_to_shared(dsm);
    const int cta = blockIdx.x;
    const int tid = threadIdx.x;
    __shared__ int s_tk;

    if (cta < LOOPC) {
        for (int t = 0; t < STEPS; t++) {
            // Phase 1: hp partials = h @ Wh^T  (2m x 4n x 8 split-K = 64 CTAs)
            if (cta < 64) {
                int kp = cta & 7, tile = cta >> 3;
                int m = tile & 1, n = tile >> 1;
                if (lengths[m * 128] > t)
                    mma_tile_raw(g_xhH + Fsz, g_xhL + Fsz, g_WhH, g_WhL,
                                 m * 128, n * 128, GK2, Hsz, kp * 64, 64,
                                 g_hppart + (size_t)kp * Bsz * Asz, Asz, sm_u);
            }
            gsync();

            // Phase 2: attention
            for (int b = cta; b < Bsz; b += LOOPC)
                attn_one(b, t, feats, Ws, bs, bh, lengths, (float*)dsm);
            gsync();

            // Phase 3: gates partials (2m x 16n x 4 split-K = 128 CTAs)
            {
                int kp = cta & 3, tile = cta >> 2;
                int m = tile & 1, n = tile >> 1;
                if (lengths[m * 128] > t)
                    mma_tile_raw(g_xhH, g_xhL, g_Wg2H, g_Wg2L,
                                 m * 128, n * 128, GK2, GK2, kp * 640, 640,
                                 g_gpart + (size_t)kp * Bsz * G4, G4, sm_u);
            }
            gsync();

            // wait for this step's embproj tiles (produced by workers)
            if (tid == 0) {
                while (*((volatile unsigned*)&g_emb_done[t]) < 32u) { }
            }
            __syncthreads();

            // Phase 4: LSTM pointwise
            for (int idx = cta * 256 + tid; idx < Bsz * Hsz; idx += LOOPC * 256) {
                int b = idx >> 9, j = idx & 511;
                if (lengths[b] > t) {
                    const int MN = Bsz * G4;
                    int base = b * G4;
                    const float* ep = &g_embproj[(size_t)(t * Bsz + b) * G4];
                    float gv[4];
#pragma unroll
                    for (int q = 0; q < 4; q++) {
                        int jj = q * 512 + j;
                        gv[q] = g_gpart[base + jj] + g_gpart[MN + base + jj]
                              + g_gpart[2 * MN + base + jj] + g_gpart[3 * MN + base + jj]
                              + ep[jj] + bih[jj] + bhh[jj];
                    }
                    float ig = 1.f / (1.f + expf(-gv[0]));
                    float fg = 1.f / (1.f + expf(-gv[1]));
                    float gg = tanhf(gv[2]);
                    float og = 1.f / (1.f + expf(-gv[3]));
                    float cn = fg * g_c[idx] + ig * gg;
                    float hn = og * tanhf(cn);
                    g_c[idx] = cn;
                    split2(hn, g_xhH[b * GK2 + Fsz + j], g_xhL[b * GK2 + Fsz + j]);
                    split2(hn, g_histH[(size_t)(t * Bsz + b) * Hsz + j],
                               g_histL[(size_t)(t * Bsz + b) * Hsz + j]);
                }
            }
            gsync();
            if (cta == 0 && tid == 0)
                atomicExch(&g_step_done, (unsigned)(t + 1));
        }
    }

    // ---- ticket drain: embproj tiles then FC tiles ----
    for (;;) {
        if (tid == 0) s_tk = (int)atomicAdd(&g_ticket, 1u);
        __syncthreads();
        int tk = s_tk;
        __syncthreads();
        if (tk >= EMBT + FCT) break;

        if (tk < EMBT) {
            // embproj tile: step = tk/32, unit = tk%32 -> (m2, n)
            int step = tk >> 5, unit = tk & 31;
            int m2 = unit & 1, n = unit >> 1;
            int m0 = step * 256 + m2 * 128, n0 = n * 128;
            mma_tile_raw(g_embAH, g_embAL, g_WihEH, g_WihEL,
                         m0, n0, Esz, Esz, 0, Esz, g_embproj, G4, sm_u);
            if (tid == 0) {
                __threadfence();
                atomicAdd(&g_emb_done[step], 1u);
            }
            continue;
        }

        int ftk = tk - EMBT;
        int my = ftk / FCN, nx = ftk - my * FCN;
        int m0 = my * 128, n0 = nx * 128;
        int tt = m0 >> 8, b0 = m0 & 255;

        if (lengths[b0] <= tt) {
            for (int i = tid; i < 128 * 128; i += 256) {
                int r = i >> 7, cc = i & 127;
                int n = n0 + cc;
                if (n < Vsz)
                    out[((size_t)(b0 + r) * STEPS + tt) * Vsz + n] = 0.f;
            }
            continue;
        }

        if (tid == 0) {
            while (*((volatile unsigned*)&g_step_done) <= (unsigned)tt) { }
        }
        __syncthreads();
        __threadfence();

        float acc[4][4][4] = {};
        mma_tile_pipe(g_histH, g_histL, g_WfcH, g_WfcL,
                      m0, n0, Hsz, Hsz, 0, Hsz, acc, sm_u);

        const int lane = tid & 31, warp = tid >> 5;
        const int wm = warp >> 2, wn = warp & 3;
        const int grp = lane >> 2, tig = lane & 3;
#pragma unroll
        for (int mt = 0; mt < 4; mt++)
#pragma unroll
            for (int nt = 0; nt < 4; nt++) {
                int row = m0 + wm * 64 + mt * 16 + grp;
                int col = n0 + wn * 32 + nt * 8 + tig * 2;
                float* a = acc[mt][nt];
                if (col < Vsz) {
                    int b0r = row & 255, tt0 = row >> 8;
                    int b1r = (row + 8) & 255, tt1 = (row + 8) >> 8;
                    bool act0 = lengths[b0r] > tt0;
                    bool act1 = lengths[b1r] > tt1;
                    float* p0 = out + ((size_t)b0r * STEPS + tt0) * Vsz;
                    float* p1 = out + ((size_t)b1r * STEPS + tt1) * Vsz;
                    p0[col]     = act0 ? (a[0] + bfc[col])     : 0.f;
                    p0[col + 1] = act0 ? (a[1] + bfc[col + 1]) : 0.f;
                    p1[col]     = act1 ? (a[2] + bfc[col])     : 0.f;
                    p1[col + 1] = act1 ? (a[3] + bfc[col + 1]) : 0.f;
                }
            }
    }
}

// ---------------------------------------------------------------------------
// Host HMMA GEMM (precompute). EPI: 0 = +bias, 3 = tanh(+bias)
// ---------------------------------------------------------------------------
template <int EPI>
__global__ __launch_bounds__(256) void mma_gemm(
    const bf16* __restrict__ Ah, const bf16* __restrict__ Al,
    const bf16* __restrict__ Bh, const bf16* __restrict__ Bl,
    const float* __restrict__ bias, float* __restrict__ C,
    int M, int N, int lda, int ldb, int kspl)
{
    const int m0 = blockIdx.y * 128;
    const int n0 = blockIdx.x * 128;
    const int tid = threadIdx.x;

    extern __shared__ __align__(16) char dsm[];
    unsigned sm_u = (unsigned)__cvta_generic_to_shared(dsm);

    const int lane = tid & 31, warp = tid >> 5;
    const int wm = warp >> 2, wn = warp & 3;
    const int grp = lane >> 2, tig = lane & 3;

    float acc[4][4][4] = {};
    mma_tile_pipe(Ah, Al, Bh, Bl, m0, n0, lda, ldb, 0, kspl, acc, sm_u);

#pragma unroll
    for (int mt = 0; mt < 4; mt++)
#pragma unroll
        for (int nt = 0; nt < 4; nt++) {
            int row = m0 + wm * 64 + mt * 16 + grp;
            int col = n0 + wn * 32 + nt * 8 + tig * 2;
            float* a = acc[mt][nt];
            if (EPI == 0) {
                C[(size_t)row * N + col]           = a[0] + bias[col];
                C[(size_t)row * N + col + 1]       = a[1] + bias[col + 1];
                C[(size_t)(row + 8) * N + col]     = a[2] + bias[col];
                C[(size_t)(row + 8) * N + col + 1] = a[3] + bias[col + 1];
            } else {
                C[(size_t)row * N + col]           = tanhf(a[0] + bias[col]);
                C[(size_t)row * N + col + 1]       = tanhf(a[1] + bias[col + 1]);
                C[(size_t)(row + 8) * N + col]     = tanhf(a[2] + bias[col]);
                C[(size_t)(row + 8) * N + col + 1] = tanhf(a[3] + bias[col + 1]);
            }
        }
}

// ---------------------------------------------------------------------------
// conversion / setup kernels
// ---------------------------------------------------------------------------
__global__ void split_arr(const float* __restrict__ src, bf16* __restrict__ h,
                          bf16* __restrict__ l, int n)
{
    for (int i = blockIdx.x * blockDim.x + threadIdx.x; i < n; i += gridDim.x * blockDim.x)
        split2(src[i], h[i], l[i]);
}

__global__ void build_Wg2(const float* __restrict__ Wih, const float* __restrict__ Whh,
                          bf16* __restrict__ h, bf16* __restrict__ l,
                          bf16* __restrict__ eh, bf16* __restrict__ el)
{
    for (int i = blockIdx.x * blockDim.x + threadIdx.x; i < G4 * GK2; i += gridDim.x * blockDim.x) {
        int r = i / GK2, cc = i % GK2;
        float v = (cc < Fsz) ? Wih[(size_t)r * (Esz + Fsz) + Esz + cc]
                             : Whh[(size_t)r * Hsz + cc - Fsz];
        split2(v, h[i], l[i]);
    }
    for (int i = blockIdx.x * blockDim.x + threadIdx.x; i < G4 * Esz; i += gridDim.x * blockDim.x) {
        int r = i / Esz, cc = i % Esz;
        split2(Wih[(size_t)r * (Esz + Fsz) + cc], eh[i], el[i]);
    }
}

__global__ void build_Wi(const float* __restrict__ Wih, const float* __restrict__ Wic,
                         const float* __restrict__ bih, const float* __restrict__ bic,
                         bf16* __restrict__ h, bf16* __restrict__ l, float* __restrict__ bi)
{
    for (int i = blockIdx.x * blockDim.x + threadIdx.x; i < 1024 * Fsz; i += gridDim.x * blockDim.x) {
        int r = i / Fsz, cc = i % Fsz;
        float v = (r < Hsz) ? Wih[(size_t)r * Fsz + cc] : Wic[(size_t)(r - Hsz) * Fsz + cc];
        split2(v, h[i], l[i]);
        if (i < 1024) bi[i] = (i < Hsz) ? bih[i] : bic[i - Hsz];
    }
}

__global__ void build_Wfc(const float* __restrict__ W, bf16* __restrict__ h, bf16* __restrict__ l)
{
    for (int i = blockIdx.x * blockDim.x + threadIdx.x; i < VPAD * Hsz; i += gridDim.x * blockDim.x) {
        int r = i >> 9;
        float v = (r < Vsz) ? W[i] : 0.f;
        split2(v, h[i], l[i]);
    }
}

__global__ void build_embA(const float* __restrict__ embW, const int* __restrict__ ids,
                           bf16* __restrict__ h, bf16* __restrict__ l)
{
    for (int i = blockIdx.x * blockDim.x + threadIdx.x; i < MROWS * Esz; i += gridDim.x * blockDim.x) {
        int r = i >> 8, e = i & 255;
        int tt = r >> 8, b = r & 255;
        int id = ids[b * Lsz + tt];
        split2(embW[(size_t)id * Esz + e], h[i], l[i]);
    }
}

// merged: mean + feats hi/lo split (single feats pass)
__global__ void mean_split_feats(const float* __restrict__ feats,
                                 bf16* __restrict__ mh, bf16* __restrict__ ml,
                                 bf16* __restrict__ fh, bf16* __restrict__ fl)
{
    int b = blockIdx.x;
    for (int f = threadIdx.x; f < Fsz; f += blockDim.x) {
        float s = 0.f;
        for (int r = 0; r < Rsz; r++) {
            size_t idx = (size_t)(b * Rsz + r) * Fsz + f;
            float v = feats[idx];
            s += v;
            split2(v, fh[idx], fl[idx]);
        }
        split2(s * (1.0f / Rsz), mh[b * Fsz + f], ml[b * Fsz + f]);
    }
}

__global__ void init_state()
{
    int idx = blockIdx.x * blockDim.x + threadIdx.x;
    int b = idx >> 9, j = idx & 511;
    float h = g_h0c0[b * 1024 + j];
    float c = g_h0c0[b * 1024 + 512 + j];
    g_c[idx] = c;
    split2(h, g_xhH[b * GK2 + Fsz + j], g_xhL[b * GK2 + Fsz + j]);
    if (idx == 0) {
        g_step_done = 0;
        g_ticket = 0;
    }
    if (idx < 32) g_emb_done[idx] = 0;
}

// ---------------------------------------------------------------------------
extern "C" void kernel_launch(void* const* d_in, const int* in_sizes, int n_in,
                              void* d_out, int out_size)
{
    const float* feats   = (const float*)d_in[0];
    const int*   ids     = (const int*)  d_in[1];
    const int*   lengths = (const int*)  d_in[2];
    const float* embW    = (const float*)d_in[3];
    const float* Wf      = (const float*)d_in[4];
    const float* bf      = (const float*)d_in[5];
    const float* Wh      = (const float*)d_in[6];
    const float* bh      = (const float*)d_in[7];
    const float* Ws      = (const float*)d_in[8];
    const float* bs      = (const float*)d_in[9];
    const float* W_ih    = (const float*)d_in[10];
    const float* b_ih    = (const float*)d_in[11];
    const float* W_hh    = (const float*)d_in[12];
    const float* b_hh    = (const float*)d_in[13];
    const float* Wfc     = (const float*)d_in[14];
    const float* bfc     = (const float*)d_in[15];
    const float* Wi_h    = (const float*)d_in[16];
    const float* bi_h    = (const float*)d_in[17];
    const float* Wi_c    = (const float*)d_in[18];
    const float* bi_c    = (const float*)d_in[19];
    float* out = (float*)d_out;

    void *pv;
    cudaGetSymbolAddress(&pv, g_featH);  bf16* featH = (bf16*)pv;
    cudaGetSymbolAddress(&pv, g_featL);  bf16* featL = (bf16*)pv;
    cudaGetSymbolAddress(&pv, g_meanH);  bf16* meanH = (bf16*)pv;
    cudaGetSymbolAddress(&pv, g_meanL);  bf16* meanL = (bf16*)pv;
    cudaGetSymbolAddress(&pv, g_WfH);    bf16* WfH = (bf16*)pv;
    cudaGetSymbolAddress(&pv, g_WfL);    bf16* WfL = (bf16*)pv;
    cudaGetSymbolAddress(&pv, g_WhH);    bf16* WhH = (bf16*)pv;
    cudaGetSymbolAddress(&pv, g_WhL);    bf16* WhL = (bf16*)pv;
    cudaGetSymbolAddress(&pv, g_Wg2H);   bf16* Wg2H = (bf16*)pv;
    cudaGetSymbolAddress(&pv, g_Wg2L);   bf16* Wg2L = (bf16*)pv;
    cudaGetSymbolAddress(&pv, g_WihEH);  bf16* WihEH = (bf16*)pv;
    cudaGetSymbolAddress(&pv, g_WihEL);  bf16* WihEL = (bf16*)pv;
    cudaGetSymbolAddress(&pv, g_WiH);    bf16* WiH = (bf16*)pv;
    cudaGetSymbolAddress(&pv, g_WiL);    bf16* WiL = (bf16*)pv;
    cudaGetSymbolAddress(&pv, g_bi);     float* bi = (float*)pv;
    cudaGetSymbolAddress(&pv, g_WfcH);   bf16* WfcH = (bf16*)pv;
    cudaGetSymbolAddress(&pv, g_WfcL);   bf16* WfcL = (bf16*)pv;
    cudaGetSymbolAddress(&pv, g_h0c0);   float* h0c0 = (float*)pv;
    cudaGetSymbolAddress(&pv, g_embAH);  bf16* embAH = (bf16*)pv;
    cudaGetSymbolAddress(&pv, g_embAL);  bf16* embAL = (bf16*)pv;
    cudaGetSymbolAddress(&pv, g_fproj);  float* fproj = (float*)pv;

    cudaFuncSetAttribute(mma_gemm<0>, cudaFuncAttributeMaxDynamicSharedMemorySize, SMEM_DYN);
    cudaFuncSetAttribute(mma_gemm<3>, cudaFuncAttributeMaxDynamicSharedMemorySize, SMEM_DYN);
    cudaFuncSetAttribute(decoder_loop, cudaFuncAttributeMaxDynamicSharedMemorySize, SMEM_DYN);

    // ---- conversions ----
    mean_split_feats<<<Bsz, 256>>>(feats, meanH, meanL, featH, featL);
    split_arr<<<256, 256>>>(Wf, WfH, WfL, Asz * Fsz);
    split_arr<<<128, 256>>>(Wh, WhH, WhL, Asz * Hsz);
    build_Wg2<<<512, 256>>>(W_ih, W_hh, Wg2H, Wg2L, WihEH, WihEL);
    build_Wi<<<256, 256>>>(Wi_h, Wi_c, bi_h, bi_c, WiH, WiL, bi);
    build_Wfc<<<512, 256>>>(Wfc, WfcH, WfcL);
    build_embA<<<256, 256>>>(embW, ids, embAH, embAL);

    // ---- init state ----
    mma_gemm<3><<<dim3(8, 2, 1), 256, SMEM_DYN>>>(meanH, meanL, WiH, WiL, bi, h0c0,
                                                  Bsz, 1024, Fsz, Fsz, Fsz);
    init_state<<<(Bsz * Hsz) / 256, 256>>>();

    // ---- f_proj = feats @ Wf^T + bf ----
    mma_gemm<0><<<dim3(4, 98, 1), 256, SMEM_DYN>>>(featH, featL, WfH, WfL, bf, fproj,
                                                   Bsz * Rsz, Asz, Fsz, Fsz, Fsz);

    // ---- persistent recurrence + overlapped embproj & final FC ----
    decoder_loop<<<PALL, 256, SMEM_DYN>>>(feats, Ws, bs, bh, b_ih, b_hh, bfc,
                                          lengths, out);
}

// round 14
// speedup vs baseline: 2.1305x; 1.1269x over previous
#include <cuda_runtime.h>
#include <cuda_fp16.h>
#include <cstdint>
#include <math.h>

#define Bsz 256
#define Lsz 24
#define Rsz 49
#define Fsz 2048
#define Esz 256
#define Hsz 512
#define Asz 512
#define Vsz 10000
#define STEPS 23
#define G4 2048
#define GK2 2560
#define VPAD 10112
#define MROWS (STEPS * Bsz)
#define NFEAT (Bsz * Rsz * Fsz)

#define LOOPC 128
#define PALL 148
#define FCM 46
#define FCN 79
#define FCT (FCM * FCN)
#define EMBT (STEPS * 32)

// BK = 64: per-array stage = 128 rows x 72 half = 18432 B
#define SST 18432
#define SMEM_DYN 147456   // 2 stages x 4 arrays (FC worst case)

typedef __half h16;

// ---------------- scratch ----------------
__device__ float g_fproj[Bsz * Rsz * Asz];
__device__ h16   g_featH[NFEAT], g_featL[NFEAT];
__device__ h16   g_meanH[Bsz * Fsz], g_meanL[Bsz * Fsz];
__device__ h16   g_WfH[Asz * Fsz];
__device__ h16   g_WhH[Asz * Hsz];
__device__ h16   g_Wg2H[G4 * GK2];
__device__ h16   g_WihEH[G4 * Esz];
__device__ h16   g_WiH[1024 * Fsz];
__device__ float g_bi[1024];
__device__ h16   g_WfcH[VPAD * Hsz], g_WfcL[VPAD * Hsz];
__device__ float g_h0c0[Bsz * 1024];
__device__ float g_c[Bsz * Hsz];
__device__ h16   g_xhH[Bsz * GK2], g_xhL[Bsz * GK2];
__device__ h16   g_embAH[MROWS * Esz], g_embAL[MROWS * Esz];
__device__ float g_embproj[MROWS * G4];
__device__ h16   g_histH[MROWS * Hsz], g_histL[MROWS * Hsz];
__device__ float g_gpart[4 * Bsz * G4];
__device__ float g_hppart[8 * Bsz * Asz];

// tree barrier state (128 participants: 8 leaves x 16)
__device__ unsigned g_bar_leaf[8 * 32];
__device__ unsigned g_bar_root = 0;
__device__ unsigned g_bar_gen = 0;
// overlap state
__device__ unsigned g_step_done = 0;
__device__ unsigned g_ticket = 0;
__device__ unsigned g_emb_done[32];

__device__ __forceinline__ void split2(float x, h16& h, h16& l) {
    h = __float2half_rn(x);
    l = __float2half_rn(x - __half2float(h));
}

__device__ __forceinline__ void mma_f16(float* c, const unsigned* a, const unsigned* b) {
    asm volatile(
        "mma.sync.aligned.m16n8k16.row.col.f32.f16.f16.f32 "
        "{%0,%1,%2,%3},{%4,%5,%6,%7},{%8,%9},{%0,%1,%2,%3};\n"
        : "+f"(c[0]), "+f"(c[1]), "+f"(c[2]), "+f"(c[3])
        : "r"(a[0]), "r"(a[1]), "r"(a[2]), "r"(a[3]), "r"(b[0]), "r"(b[1]));
}

__device__ __forceinline__ void ldsm_x4(unsigned& r0, unsigned& r1, unsigned& r2, unsigned& r3,
                                        unsigned addr) {
    asm volatile("ldmatrix.sync.aligned.m8n8.x4.shared.b16 {%0,%1,%2,%3},[%4];"
                 : "=r"(r0), "=r"(r1), "=r"(r2), "=r"(r3) : "r"(addr));
}
__device__ __forceinline__ void ldsm_x2(unsigned& r0, unsigned& r1, unsigned addr) {
    asm volatile("ldmatrix.sync.aligned.m8n8.x2.shared.b16 {%0,%1},[%2];"
                 : "=r"(r0), "=r"(r1) : "r"(addr));
}

__device__ __forceinline__ void cpa16(unsigned dst, const h16* src) {
    asm volatile("cp.async.cg.shared.global [%0], [%1], 16;" :: "r"(dst), "l"(src));
}
__device__ __forceinline__ void cpcommit() { asm volatile("cp.async.commit_group;"); }
template <int N> __device__ __forceinline__ void cpwait() {
    asm volatile("cp.async.wait_group %0;" :: "n"(N));
}

// grid tree barrier among the first LOOPC CTAs only
__device__ __forceinline__ void gsync() {
    __syncthreads();
    if (threadIdx.x == 0) {
        __threadfence();
        unsigned gen = *((volatile unsigned*)&g_bar_gen);
        int leaf = (blockIdx.x >> 4) & 7;
        if (atomicAdd(&g_bar_leaf[leaf * 32], 1u) == 15u) {
            atomicExch(&g_bar_leaf[leaf * 32], 0u);
            if (atomicAdd(&g_bar_root, 1u) == 7u) {
                atomicExch(&g_bar_root, 0u);
                __threadfence();
                atomicAdd(&g_bar_gen, 1u);
            } else {
                while (*((volatile unsigned*)&g_bar_gen) == gen) { }
            }
        } else {
            while (*((volatile unsigned*)&g_bar_gen) == gen) { }
        }
        __threadfence();
    }
    __syncthreads();
}

// ---------------------------------------------------------------------------
// HMMA pipelined tile (128x128, BK=64, 2-stage cp.async).
// T3=false: 2-term (AhBh + AlBh), 3 smem arrays.
// T3=true : 3-term (+ AhBl), 4 smem arrays (used by final FC only).
// ---------------------------------------------------------------------------
template <bool T3>
__device__ __forceinline__ void load_chunk(
    unsigned sb, const h16* __restrict__ Ah, const h16* __restrict__ Al,
    const h16* __restrict__ Bh, const h16* __restrict__ Bl,
    int m0, int n0, int lda, int ldb, int kg)
{
    const int tid = threadIdx.x;
    const int rr = tid >> 3;
    const int c8 = tid & 7;
#pragma unroll
    for (int i = 0; i < 4; i++) {
        int r = rr + i * 32;
        size_t ga = (size_t)(m0 + r) * lda + kg + c8 * 8;
        size_t gb = (size_t)(n0 + r) * ldb + kg + c8 * 8;
        unsigned off = (unsigned)(r * 144 + c8 * 16);
        cpa16(sb + off,           Ah + ga);
        cpa16(sb + SST + off,     Al + ga);
        cpa16(sb + 2 * SST + off, Bh + gb);
        if (T3) cpa16(sb + 3 * SST + off, Bl + gb);
    }
}

template <bool T3>
__device__ __forceinline__ void mma_chunk(unsigned sb, float acc[4][4][4])
{
    const int lane = threadIdx.x & 31, warp = threadIdx.x >> 5;
    const int wm = warp >> 2, wn = warp & 3;
#pragma unroll
    for (int k16 = 0; k16 < 4; k16++) {
        const int aro = wm * 64 + (lane & 15);
        const int aco = k16 * 16 + ((lane >> 4) << 3);
        const int bro = wn * 32 + (lane & 7);
        const int bco = k16 * 16 + (((lane >> 3) & 1) << 3);
        unsigned ah[4][4], al[4][4], bh2[4][2], bl2[4][2];
#pragma unroll
        for (int mt = 0; mt < 4; mt++) {
            unsigned off = (unsigned)(((aro + mt * 16) * 72 + aco) * 2);
            ldsm_x4(ah[mt][0], ah[mt][1], ah[mt][2], ah[mt][3], sb + off);
            ldsm_x4(al[mt][0], al[mt][1], al[mt][2], al[mt][3], sb + SST + off);
        }
#pragma unroll
        for (int nt = 0; nt < 4; nt++) {
            unsigned off = (unsigned)(((bro + nt * 8) * 72 + bco) * 2);
            ldsm_x2(bh2[nt][0], bh2[nt][1], sb + 2 * SST + off);
            if (T3) ldsm_x2(bl2[nt][0], bl2[nt][1], sb + 3 * SST + off);
        }
#pragma unroll
        for (int nt = 0; nt < 4; nt++)
#pragma unroll
            for (int mt = 0; mt < 4; mt++) {
                mma_f16(acc[mt][nt], ah[mt], bh2[nt]);
                mma_f16(acc[mt][nt], al[mt], bh2[nt]);
                if (T3) mma_f16(acc[mt][nt], ah[mt], bl2[nt]);
            }
    }
}

template <bool T3>
__device__ __forceinline__ void mma_tile_pipe(
    const h16* __restrict__ Ah, const h16* __restrict__ Al,
    const h16* __restrict__ Bh, const h16* __restrict__ Bl,
    int m0, int n0, int lda, int ldb, int kbase, int kcnt,
    float acc[4][4][4], unsigned sm_u)
{
    const unsigned STG = (T3 ? 4 : 3) * SST;
    const int nch = kcnt >> 6;
    load_chunk<T3>(sm_u, Ah, Al, Bh, Bl, m0, n0, lda, ldb, kbase);
    cpcommit();
    for (int ic = 0; ic < nch; ic++) {
        if (ic + 1 < nch) {
            load_chunk<T3>(sm_u + ((ic + 1) & 1) * STG, Ah, Al, Bh, Bl,
                           m0, n0, lda, ldb, kbase + (ic + 1) * 64);
            cpcommit();
            cpwait<1>();
        } else {
            cpwait<0>();
        }
        __syncthreads();
        mma_chunk<T3>(sm_u + (ic & 1) * STG, acc);
        __syncthreads();
    }
}

__device__ void mma_tile_raw(
    const h16* __restrict__ Ah, const h16* __restrict__ Al,
    const h16* __restrict__ Bh,
    int m0, int n0, int lda, int ldb, int kbase, int kcnt,
    float* __restrict__ C, int N, unsigned sm_u)
{
    float acc[4][4][4] = {};
    mma_tile_pipe<false>(Ah, Al, Bh, nullptr, m0, n0, lda, ldb, kbase, kcnt, acc, sm_u);
    const int lane = threadIdx.x & 31, warp = threadIdx.x >> 5;
    const int wm = warp >> 2, wn = warp & 3;
    const int grp = lane >> 2, tig = lane & 3;
#pragma unroll
    for (int mt = 0; mt < 4; mt++)
#pragma unroll
        for (int nt = 0; nt < 4; nt++) {
            int row = m0 + wm * 64 + mt * 16 + grp;
            int col = n0 + wn * 32 + nt * 8 + tig * 2;
            float* a = acc[mt][nt];
            C[(size_t)row * N + col]           = a[0];
            C[(size_t)row * N + col + 1]       = a[1];
            C[(size_t)(row + 8) * N + col]     = a[2];
            C[(size_t)(row + 8) * N + col + 1] = a[3];
        }
}

// ---------------------------------------------------------------------------
// Attention body
// ---------------------------------------------------------------------------
__device__ void attn_one(int b, int t, const float* __restrict__ feats,
                         const float* __restrict__ Ws, const float* __restrict__ bs,
                         const float* __restrict__ bh, const int* __restrict__ lengths,
                         float* sbuf)
{
    if (lengths[b] <= t) return;

    float* hp_s = sbuf;
    float* ws_s = sbuf + 512;
    float* sc_s = sbuf + 1024;
    int tid = threadIdx.x;
#pragma unroll
    for (int i = 0; i < 2; i++) {
        int a = tid + i * 256;
        float s = bh[a];
#pragma unroll
        for (int p = 0; p < 8; p++) s += g_hppart[(size_t)p * Bsz * Asz + b * Asz + a];
        hp_s[a] = s;
        ws_s[a] = Ws[a];
    }
    __syncthreads();

    int warp = tid >> 5, lane = tid & 31;
    for (int r = warp; r < Rsz; r += 8) {
        const float* fp = &g_fproj[(size_t)(b * Rsz + r) * Asz];
        float s = 0.f;
        for (int a = lane; a < Asz; a += 32)
            s += tanhf(fp[a] + hp_s[a]) * ws_s[a];
#pragma unroll
        for (int o = 16; o; o >>= 1) s += __shfl_down_sync(0xffffffffu, s, o);
        if (lane == 0) sc_s[r] = s + bs[0];
    }
    __syncthreads();

    if (warp == 0) {
        float v1 = (lane < Rsz) ? sc_s[lane] : -INFINITY;
        float v2 = (lane + 32 < Rsz) ? sc_s[lane + 32] : -INFINITY;
        float mx = fmaxf(v1, v2);
#pragma unroll
        for (int o = 16; o; o >>= 1) mx = fmaxf(mx, __shfl_xor_sync(0xffffffffu, mx, o));
        float e1 = (lane < Rsz) ? expf(v1 - mx) : 0.f;
        float e2 = (lane + 32 < Rsz) ? expf(v2 - mx) : 0.f;
        float sm2 = e1 + e2;
#pragma unroll
        for (int o = 16; o; o >>= 1) sm2 += __shfl_xor_sync(0xffffffffu, sm2, o);
        float inv = 1.f / sm2;
        if (lane < Rsz) sc_s[lane] = e1 * inv;
        if (lane + 32 < Rsz) sc_s[lane + 32] = e2 * inv;
    }
    __syncthreads();

    const float4* f4 = reinterpret_cast<const float4*>(feats);
    for (int f = tid; f < Fsz / 4; f += 256) {
        float ax = 0.f, ay = 0.f, az = 0.f, aw = 0.f;
#pragma unroll 7
        for (int r = 0; r < Rsz; r++) {
            float4 v = f4[(size_t)(b * Rsz + r) * (Fsz / 4) + f];
            float al = sc_s[r];
            ax = fmaf(al, v.x, ax); ay = fmaf(al, v.y, ay);
            az = fmaf(al, v.z, az); aw = fmaf(al, v.w, aw);
        }
        int fb = f * 4;
        split2(ax, g_xhH[b * GK2 + fb],     g_xhL[b * GK2 + fb]);
        split2(ay, g_xhH[b * GK2 + fb + 1], g_xhL[b * GK2 + fb + 1]);
        split2(az, g_xhH[b * GK2 + fb + 2], g_xhL[b * GK2 + fb + 2]);
        split2(aw, g_xhH[b * GK2 + fb + 3], g_xhL[b * GK2 + fb + 3]);
    }
    __syncthreads();
}

// ---------------------------------------------------------------------------
// Persistent kernel: step loop (CTAs 0..127) + overlap workers (128..147).
// ---------------------------------------------------------------------------
__global__ __launch_bounds__(256, 1) void decoder_loop(
    const float* __restrict__ feats, const float* __restrict__ Ws,
    const float* __restrict__ bs, const float* __restrict__ bh,
    const float* __restrict__ bih, const float* __restrict__ bhh,
    const float* __restrict__ bfc, const int* __restrict__ lengths,
    float* __restrict__ out)
{
    extern __shared__ __align__(16) char dsm[];
    unsigned sm_u = (unsigned)__cvta_generic_to_shared(dsm);
    const int cta = blockIdx.x;
    const int tid = threadIdx.x;
    __shared__ int s_tk;

    if (cta < LOOPC) {
        for (int t = 0; t < STEPS; t++) {
            // Phase 1: hp partials = h @ Wh^T  (2m x 4n x 8 split-K = 64 CTAs)
            if (cta < 64) {
                int kp = cta & 7, tile = cta >> 3;
                int m = tile & 1, n = tile >> 1;
                if (lengths[m * 128] > t)
                    mma_tile_raw(g_xhH + Fsz, g_xhL + Fsz, g_WhH,
                                 m * 128, n * 128, GK2, Hsz, kp * 64, 64,
                                 g_hppart + (size_t)kp * Bsz * Asz, Asz, sm_u);
            }
            gsync();

            // Phase 2: attention
            for (int b = cta; b < Bsz; b += LOOPC)
                attn_one(b, t, feats, Ws, bs, bh, lengths, (float*)dsm);
            gsync();

            // Phase 3: gates partials (2m x 16n x 4 split-K = 128 CTAs)
            {
                int kp = cta & 3, tile = cta >> 2;
                int m = tile & 1, n = tile >> 1;
                if (lengths[m * 128] > t)
                    mma_tile_raw(g_xhH, g_xhL, g_Wg2H,
                                 m * 128, n * 128, GK2, GK2, kp * 640, 640,
                                 g_gpart + (size_t)kp * Bsz * G4, G4, sm_u);
            }
            gsync();

            // wait for this step's embproj tiles (produced by workers)
            if (tid == 0) {
                while (*((volatile unsigned*)&g_emb_done[t]) < 32u) { }
            }
            __syncthreads();

            // Phase 4: LSTM pointwise
            for (int idx = cta * 256 + tid; idx < Bsz * Hsz; idx += LOOPC * 256) {
                int b = idx >> 9, j = idx & 511;
                if (lengths[b] > t) {
                    const int MN = Bsz * G4;
                    int base = b * G4;
                    const float* ep = &g_embproj[(size_t)(t * Bsz + b) * G4];
                    float gv[4];
#pragma unroll
                    for (int q = 0; q < 4; q++) {
                        int jj = q * 512 + j;
                        gv[q] = g_gpart[base + jj] + g_gpart[MN + base + jj]
                              + g_gpart[2 * MN + base + jj] + g_gpart[3 * MN + base + jj]
                              + ep[jj] + bih[jj] + bhh[jj];
                    }
                    float ig = 1.f / (1.f + expf(-gv[0]));
                    float fg = 1.f / (1.f + expf(-gv[1]));
                    float gg = tanhf(gv[2]);
                    float og = 1.f / (1.f + expf(-gv[3]));
                    float cn = fg * g_c[idx] + ig * gg;
                    float hn = og * tanhf(cn);
                    g_c[idx] = cn;
                    split2(hn, g_xhH[b * GK2 + Fsz + j], g_xhL[b * GK2 + Fsz + j]);
                    split2(hn, g_histH[(size_t)(t * Bsz + b) * Hsz + j],
                               g_histL[(size_t)(t * Bsz + b) * Hsz + j]);
                }
            }
            gsync();
            if (cta == 0 && tid == 0)
                atomicExch(&g_step_done, (unsigned)(t + 1));
        }
    }

    // ---- ticket drain: embproj tiles then FC tiles ----
    for (;;) {
        if (tid == 0) s_tk = (int)atomicAdd(&g_ticket, 1u);
        __syncthreads();
        int tk = s_tk;
        __syncthreads();
        if (tk >= EMBT + FCT) break;

        if (tk < EMBT) {
            int step = tk >> 5, unit = tk & 31;
            int m2 = unit & 1, n = unit >> 1;
            int m0 = step * 256 + m2 * 128, n0 = n * 128;
            mma_tile_raw(g_embAH, g_embAL, g_WihEH,
                         m0, n0, Esz, Esz, 0, Esz, g_embproj, G4, sm_u);
            if (tid == 0) {
                __threadfence();
                atomicAdd(&g_emb_done[step], 1u);
            }
            continue;
        }

        int ftk = tk - EMBT;
        int my = ftk / FCN, nx = ftk - my * FCN;
        int m0 = my * 128, n0 = nx * 128;
        int tt = m0 >> 8, b0 = m0 & 255;

        if (lengths[b0] <= tt) {
            for (int i = tid; i < 128 * 128; i += 256) {
                int r = i >> 7, cc = i & 127;
                int n = n0 + cc;
                if (n < Vsz)
                    out[((size_t)(b0 + r) * STEPS + tt) * Vsz + n] = 0.f;
            }
            continue;
        }

        if (tid == 0) {
            while (*((volatile unsigned*)&g_step_done) <= (unsigned)tt) { }
        }
        __syncthreads();
        __threadfence();

        float acc[4][4][4] = {};
        mma_tile_pipe<true>(g_histH, g_histL, g_WfcH, g_WfcL,
                            m0, n0, Hsz, Hsz, 0, Hsz, acc, sm_u);

        const int lane = tid & 31, warp = tid >> 5;
        const int wm = warp >> 2, wn = warp & 3;
        const int grp = lane >> 2, tig = lane & 3;
#pragma unroll
        for (int mt = 0; mt < 4; mt++)
#pragma unroll
            for (int nt = 0; nt < 4; nt++) {
                int row = m0 + wm * 64 + mt * 16 + grp;
                int col = n0 + wn * 32 + nt * 8 + tig * 2;
                float* a = acc[mt][nt];
                if (col < Vsz) {
                    int b0r = row & 255, tt0 = row >> 8;
                    int b1r = (row + 8) & 255, tt1 = (row + 8) >> 8;
                    bool act0 = lengths[b0r] > tt0;
                    bool act1 = lengths[b1r] > tt1;
                    float* p0 = out + ((size_t)b0r * STEPS + tt0) * Vsz;
                    float* p1 = out + ((size_t)b1r * STEPS + tt1) * Vsz;
                    p0[col]     = act0 ? (a[0] + bfc[col])     : 0.f;
                    p0[col + 1] = act0 ? (a[1] + bfc[col + 1]) : 0.f;
                    p1[col]     = act1 ? (a[2] + bfc[col])     : 0.f;
                    p1[col + 1] = act1 ? (a[3] + bfc[col + 1]) : 0.f;
                }
            }
    }
}

// ---------------------------------------------------------------------------
// Host HMMA GEMM (precompute). EPI: 0 = +bias, 3 = tanh(+bias)
// ---------------------------------------------------------------------------
template <int EPI>
__global__ __launch_bounds__(256) void mma_gemm(
    const h16* __restrict__ Ah, const h16* __restrict__ Al,
    const h16* __restrict__ Bh,
    const float* __restrict__ bias, float* __restrict__ C,
    int M, int N, int lda, int ldb, int kspl)
{
    const int m0 = blockIdx.y * 128;
    const int n0 = blockIdx.x * 128;
    const int tid = threadIdx.x;

    extern __shared__ __align__(16) char dsm[];
    unsigned sm_u = (unsigned)__cvta_generic_to_shared(dsm);

    const int lane = tid & 31, warp = tid >> 5;
    const int wm = warp >> 2, wn = warp & 3;
    const int grp = lane >> 2, tig = lane & 3;

    float acc[4][4][4] = {};
    mma_tile_pipe<false>(Ah, Al, Bh, nullptr, m0, n0, lda, ldb, 0, kspl, acc, sm_u);

#pragma unroll
    for (int mt = 0; mt < 4; mt++)
#pragma unroll
        for (int nt = 0; nt < 4; nt++) {
            int row = m0 + wm * 64 + mt * 16 + grp;
            int col = n0 + wn * 32 + nt * 8 + tig * 2;
            float* a = acc[mt][nt];
            if (EPI == 0) {
                C[(size_t)row * N + col]           = a[0] + bias[col];
                C[(size_t)row * N + col + 1]       = a[1] + bias[col + 1];
                C[(size_t)(row + 8) * N + col]     = a[2] + bias[col];
                C[(size_t)(row + 8) * N + col + 1] = a[3] + bias[col + 1];
            } else {
                C[(size_t)row * N + col]           = tanhf(a[0] + bias[col]);
                C[(size_t)row * N + col + 1]       = tanhf(a[1] + bias[col + 1]);
                C[(size_t)(row + 8) * N + col]     = tanhf(a[2] + bias[col]);
                C[(size_t)(row + 8) * N + col + 1] = tanhf(a[3] + bias[col + 1]);
            }
        }
}

// ---------------------------------------------------------------------------
// Merged conversion kernel: all weight tensors in one launch
// ---------------------------------------------------------------------------
__global__ void convert_weights(
    const float* __restrict__ Wf, const float* __restrict__ Wh,
    const float* __restrict__ Wih, const float* __restrict__ Whh,
    const float* __restrict__ Wi_h, const float* __restrict__ Wi_c,
    const float* __restrict__ bi_h, const float* __restrict__ bi_c,
    const float* __restrict__ Wfc,
    const float* __restrict__ embW, const int* __restrict__ ids)
{
    const int stride = gridDim.x * blockDim.x;
    const int tid0 = blockIdx.x * blockDim.x + threadIdx.x;

    for (int i = tid0; i < Asz * Fsz; i += stride)
        g_WfH[i] = __float2half_rn(Wf[i]);
    for (int i = tid0; i < Asz * Hsz; i += stride)
        g_WhH[i] = __float2half_rn(Wh[i]);
    for (int i = tid0; i < G4 * GK2; i += stride) {
        int r = i / GK2, cc = i - r * GK2;
        float v = (cc < Fsz) ? Wih[(size_t)r * (Esz + Fsz) + Esz + cc]
                             : Whh[(size_t)r * Hsz + cc - Fsz];
        g_Wg2H[i] = __float2half_rn(v);
    }
    for (int i = tid0; i < G4 * Esz; i += stride) {
        int r = i >> 8, cc = i & 255;
        g_WihEH[i] = __float2half_rn(Wih[(size_t)r * (Esz + Fsz) + cc]);
    }
    for (int i = tid0; i < 1024 * Fsz; i += stride) {
        int r = i / Fsz, cc = i - r * Fsz;
        float v = (r < Hsz) ? Wi_h[(size_t)r * Fsz + cc] : Wi_c[(size_t)(r - Hsz) * Fsz + cc];
        g_WiH[i] = __float2half_rn(v);
    }
    for (int i = tid0; i < 1024; i += stride)
        g_bi[i] = (i < Hsz) ? bi_h[i] : bi_c[i - Hsz];
    for (int i = tid0; i < VPAD * Hsz; i += stride) {
        int r = i >> 9;
        float v = (r < Vsz) ? Wfc[i] : 0.f;
        split2(v, g_WfcH[i], g_WfcL[i]);
    }
    for (int i = tid0; i < MROWS * Esz; i += stride) {
        int r = i >> 8, e = i & 255;
        int tt = r >> 8, b = r & 255;
        int id = ids[b * Lsz + tt];
        split2(embW[(size_t)id * Esz + e], g_embAH[i], g_embAL[i]);
    }
}

// merged: mean + feats hi/lo split (single feats pass)
__global__ void mean_split_feats(const float* __restrict__ feats)
{
    int b = blockIdx.x;
    for (int f = threadIdx.x; f < Fsz; f += blockDim.x) {
        float s = 0.f;
        for (int r = 0; r < Rsz; r++) {
            size_t idx = (size_t)(b * Rsz + r) * Fsz + f;
            float v = feats[idx];
            s += v;
            split2(v, g_featH[idx], g_featL[idx]);
        }
        split2(s * (1.0f / Rsz), g_meanH[b * Fsz + f], g_meanL[b * Fsz + f]);
    }
}

__global__ void init_state()
{
    int idx = blockIdx.x * blockDim.x + threadIdx.x;
    int b = idx >> 9, j = idx & 511;
    float h = g_h0c0[b * 1024 + j];
    float c = g_h0c0[b * 1024 + 512 + j];
    g_c[idx] = c;
    split2(h, g_xhH[b * GK2 + Fsz + j], g_xhL[b * GK2 + Fsz + j]);
    if (idx == 0) {
        g_step_done = 0;
        g_ticket = 0;
    }
    if (idx < 32) g_emb_done[idx] = 0;
}

// ---------------------------------------------------------------------------
extern "C" void kernel_launch(void* const* d_in, const int* in_sizes, int n_in,
                              void* d_out, int out_size)
{
    const float* feats   = (const float*)d_in[0];
    const int*   ids     = (const int*)  d_in[1];
    const int*   lengths = (const int*)  d_in[2];
    const float* embW    = (const float*)d_in[3];
    const float* Wf      = (const float*)d_in[4];
    const float* bf      = (const float*)d_in[5];
    const float* Wh      = (const float*)d_in[6];
    const float* bh      = (const float*)d_in[7];
    const float* Ws      = (const float*)d_in[8];
    const float* bs      = (const float*)d_in[9];
    const float* W_ih    = (const float*)d_in[10];
    const float* b_ih    = (const float*)d_in[11];
    const float* W_hh    = (const float*)d_in[12];
    const float* b_hh    = (const float*)d_in[13];
    const float* Wfc     = (const float*)d_in[14];
    const float* bfc     = (const float*)d_in[15];
    const float* Wi_h    = (const float*)d_in[16];
    const float* bi_h    = (const float*)d_in[17];
    const float* Wi_c    = (const float*)d_in[18];
    const float* bi_c    = (const float*)d_in[19];
    float* out = (float*)d_out;

    void *pv;
    cudaGetSymbolAddress(&pv, g_featH);  h16* featH = (h16*)pv;
    cudaGetSymbolAddress(&pv, g_featL);  h16* featL = (h16*)pv;
    cudaGetSymbolAddress(&pv, g_meanH);  h16* meanH = (h16*)pv;
    cudaGetSymbolAddress(&pv, g_meanL);  h16* meanL = (h16*)pv;
    cudaGetSymbolAddress(&pv, g_WfH);    h16* WfH = (h16*)pv;
    cudaGetSymbolAddress(&pv, g_WiH);    h16* WiH = (h16*)pv;
    cudaGetSymbolAddress(&pv, g_bi);     float* bi = (float*)pv;
    cudaGetSymbolAddress(&pv, g_h0c0);   float* h0c0 = (float*)pv;
    cudaGetSymbolAddress(&pv, g_fproj);  float* fproj = (float*)pv;

    cudaFuncSetAttribute(mma_gemm<0>, cudaFuncAttributeMaxDynamicSharedMemorySize, SMEM_DYN);
    cudaFuncSetAttribute(mma_gemm<3>, cudaFuncAttributeMaxDynamicSharedMemorySize, SMEM_DYN);
    cudaFuncSetAttribute(decoder_loop, cudaFuncAttributeMaxDynamicSharedMemorySize, SMEM_DYN);

    // ---- conversions (2 launches) ----
    mean_split_feats<<<Bsz, 256>>>(feats);
    convert_weights<<<592, 256>>>(Wf, Wh, W_ih, W_hh, Wi_h, Wi_c, bi_h, bi_c,
                                  Wfc, embW, ids);

    // ---- init state ----
    mma_gemm<3><<<dim3(8, 2, 1), 256, SMEM_DYN>>>(meanH, meanL, WiH, bi, h0c0,
                                                  Bsz, 1024, Fsz, Fsz, Fsz);
    init_state<<<(Bsz * Hsz) / 256, 256>>>();

    // ---- f_proj = feats @ Wf^T + bf ----
    mma_gemm<0><<<dim3(4, 98, 1), 256, SMEM_DYN>>>(featH, featL, WfH, bf, fproj,
                                                   Bsz * Rsz, Asz, Fsz, Fsz, Fsz);

    // ---- persistent recurrence + overlapped embproj & final FC ----
    decoder_loop<<<PALL, 256, SMEM_DYN>>>(feats, Ws, bs, bh, b_ih, b_hh, bfc,
                                          lengths, out);
}

// round 15
// speedup vs baseline: 2.3380x; 1.0974x over previous
#include <cuda_runtime.h>
#include <cuda_fp16.h>
#include <cstdint>
#include <math.h>

#define Bsz 256
#define Lsz 24
#define Rsz 49
#define Fsz 2048
#define Esz 256
#define Hsz 512
#define Asz 512
#define Vsz 10000
#define STEPS 23
#define G4 2048
#define GK2 2560
#define VPAD 10112
#define MROWS (STEPS * Bsz)
#define NFEAT (Bsz * Rsz * Fsz)

#define LOOPC 128
#define PALL 148
#define FCM 46
#define FCN 79
#define FCT (FCM * FCN)
#define EMBT (STEPS * 32)

// BK = 64: per-array stage = 128 rows x 72 half = 18432 B
#define SST 18432
#define SMEM_DYN 147456   // 2 stages x 4 arrays (FC worst case)

typedef __half h16;

// ---------------- scratch ----------------
__device__ h16   g_fproj[Bsz * Rsz * Asz];
__device__ h16   g_featH[NFEAT], g_featL[NFEAT];
__device__ h16   g_meanH[Bsz * Fsz], g_meanL[Bsz * Fsz];
__device__ h16   g_WfH[Asz * Fsz];
__device__ h16   g_WhH[Asz * Hsz];
__device__ h16   g_Wg2H[G4 * GK2];
__device__ h16   g_WihEH[G4 * Esz];
__device__ h16   g_WiH[1024 * Fsz];
__device__ float g_bi[1024];
__device__ h16   g_WfcH[VPAD * Hsz], g_WfcL[VPAD * Hsz];
__device__ float g_h0c0[Bsz * 1024];
__device__ float g_c[Bsz * Hsz];
__device__ h16   g_xhH[Bsz * GK2], g_xhL[Bsz * GK2];
__device__ h16   g_embAH[MROWS * Esz], g_embAL[MROWS * Esz];
__device__ float g_embproj[MROWS * G4];
__device__ h16   g_histH[MROWS * Hsz], g_histL[MROWS * Hsz];
__device__ float g_gpart[4 * Bsz * G4];
__device__ float g_hppart[4 * Bsz * Asz];

// tree barrier state (128 participants: 8 leaves x 16)
__device__ unsigned g_bar_leaf[8 * 32];
__device__ unsigned g_bar_root = 0;
__device__ unsigned g_bar_gen = 0;
// overlap state
__device__ unsigned g_step_done = 0;
__device__ unsigned g_ticket = 0;
__device__ unsigned g_emb_done[32];

__device__ __forceinline__ void split2(float x, h16& h, h16& l) {
    h = __float2half_rn(x);
    l = __float2half_rn(x - __half2float(h));
}

__device__ __forceinline__ void mma_f16(float* c, const unsigned* a, const unsigned* b) {
    asm volatile(
        "mma.sync.aligned.m16n8k16.row.col.f32.f16.f16.f32 "
        "{%0,%1,%2,%3},{%4,%5,%6,%7},{%8,%9},{%0,%1,%2,%3};\n"
        : "+f"(c[0]), "+f"(c[1]), "+f"(c[2]), "+f"(c[3])
        : "r"(a[0]), "r"(a[1]), "r"(a[2]), "r"(a[3]), "r"(b[0]), "r"(b[1]));
}

__device__ __forceinline__ void ldsm_x4(unsigned& r0, unsigned& r1, unsigned& r2, unsigned& r3,
                                        unsigned addr) {
    asm volatile("ldmatrix.sync.aligned.m8n8.x4.shared.b16 {%0,%1,%2,%3},[%4];"
                 : "=r"(r0), "=r"(r1), "=r"(r2), "=r"(r3) : "r"(addr));
}
__device__ __forceinline__ void ldsm_x2(unsigned& r0, unsigned& r1, unsigned addr) {
    asm volatile("ldmatrix.sync.aligned.m8n8.x2.shared.b16 {%0,%1},[%2];"
                 : "=r"(r0), "=r"(r1) : "r"(addr));
}

__device__ __forceinline__ void cpa16(unsigned dst, const h16* src) {
    asm volatile("cp.async.cg.shared.global [%0], [%1], 16;" :: "r"(dst), "l"(src));
}
__device__ __forceinline__ void cpcommit() { asm volatile("cp.async.commit_group;"); }
template <int N> __device__ __forceinline__ void cpwait() {
    asm volatile("cp.async.wait_group %0;" :: "n"(N));
}

// grid tree barrier among the first LOOPC CTAs only
__device__ __forceinline__ void gsync() {
    __syncthreads();
    if (threadIdx.x == 0) {
        __threadfence();
        unsigned gen = *((volatile unsigned*)&g_bar_gen);
        int leaf = (blockIdx.x >> 4) & 7;
        if (atomicAdd(&g_bar_leaf[leaf * 32], 1u) == 15u) {
            atomicExch(&g_bar_leaf[leaf * 32], 0u);
            if (atomicAdd(&g_bar_root, 1u) == 7u) {
                atomicExch(&g_bar_root, 0u);
                __threadfence();
                atomicAdd(&g_bar_gen, 1u);
            } else {
                while (*((volatile unsigned*)&g_bar_gen) == gen) { }
            }
        } else {
            while (*((volatile unsigned*)&g_bar_gen) == gen) { }
        }
        __threadfence();
    }
    __syncthreads();
}

// ---------------------------------------------------------------------------
// HMMA pipelined tile (128x128, BK=64, 2-stage cp.async).
// T3=false: 2-term (AhBh + AlBh), 3 smem arrays.
// T3=true : 3-term (+ AhBl), 4 smem arrays (final FC only).
// ---------------------------------------------------------------------------
template <bool T3>
__device__ __forceinline__ void load_chunk(
    unsigned sb, const h16* __restrict__ Ah, const h16* __restrict__ Al,
    const h16* __restrict__ Bh, const h16* __restrict__ Bl,
    int m0, int n0, int lda, int ldb, int kg)
{
    const int tid = threadIdx.x;
    const int rr = tid >> 3;
    const int c8 = tid & 7;
#pragma unroll
    for (int i = 0; i < 4; i++) {
        int r = rr + i * 32;
        size_t ga = (size_t)(m0 + r) * lda + kg + c8 * 8;
        size_t gb = (size_t)(n0 + r) * ldb + kg + c8 * 8;
        unsigned off = (unsigned)(r * 144 + c8 * 16);
        cpa16(sb + off,           Ah + ga);
        cpa16(sb + SST + off,     Al + ga);
        cpa16(sb + 2 * SST + off, Bh + gb);
        if (T3) cpa16(sb + 3 * SST + off, Bl + gb);
    }
}

template <bool T3>
__device__ __forceinline__ void mma_chunk(unsigned sb, float acc[4][4][4])
{
    const int lane = threadIdx.x & 31, warp = threadIdx.x >> 5;
    const int wm = warp >> 2, wn = warp & 3;
#pragma unroll
    for (int k16 = 0; k16 < 4; k16++) {
        const int aro = wm * 64 + (lane & 15);
        const int aco = k16 * 16 + ((lane >> 4) << 3);
        const int bro = wn * 32 + (lane & 7);
        const int bco = k16 * 16 + (((lane >> 3) & 1) << 3);
        unsigned ah[4][4], al[4][4], bh2[4][2], bl2[4][2];
#pragma unroll
        for (int mt = 0; mt < 4; mt++) {
            unsigned off = (unsigned)(((aro + mt * 16) * 72 + aco) * 2);
            ldsm_x4(ah[mt][0], ah[mt][1], ah[mt][2], ah[mt][3], sb + off);
            ldsm_x4(al[mt][0], al[mt][1], al[mt][2], al[mt][3], sb + SST + off);
        }
#pragma unroll
        for (int nt = 0; nt < 4; nt++) {
            unsigned off = (unsigned)(((bro + nt * 8) * 72 + bco) * 2);
            ldsm_x2(bh2[nt][0], bh2[nt][1], sb + 2 * SST + off);
            if (T3) ldsm_x2(bl2[nt][0], bl2[nt][1], sb + 3 * SST + off);
        }
#pragma unroll
        for (int nt = 0; nt < 4; nt++)
#pragma unroll
            for (int mt = 0; mt < 4; mt++) {
                mma_f16(acc[mt][nt], ah[mt], bh2[nt]);
                mma_f16(acc[mt][nt], al[mt], bh2[nt]);
                if (T3) mma_f16(acc[mt][nt], ah[mt], bl2[nt]);
            }
    }
}

template <bool T3>
__device__ __forceinline__ void mma_tile_pipe(
    const h16* __restrict__ Ah, const h16* __restrict__ Al,
    const h16* __restrict__ Bh, const h16* __restrict__ Bl,
    int m0, int n0, int lda, int ldb, int kbase, int kcnt,
    float acc[4][4][4], unsigned sm_u)
{
    const unsigned STG = (T3 ? 4 : 3) * SST;
    const int nch = kcnt >> 6;
    load_chunk<T3>(sm_u, Ah, Al, Bh, Bl, m0, n0, lda, ldb, kbase);
    cpcommit();
    for (int ic = 0; ic < nch; ic++) {
        if (ic + 1 < nch) {
            load_chunk<T3>(sm_u + ((ic + 1) & 1) * STG, Ah, Al, Bh, Bl,
                           m0, n0, lda, ldb, kbase + (ic + 1) * 64);
            cpcommit();
            cpwait<1>();
        } else {
            cpwait<0>();
        }
        __syncthreads();
        mma_chunk<T3>(sm_u + (ic & 1) * STG, acc);
        __syncthreads();
    }
}

__device__ void mma_tile_raw(
    const h16* __restrict__ Ah, const h16* __restrict__ Al,
    const h16* __restrict__ Bh,
    int m0, int n0, int lda, int ldb, int kbase, int kcnt,
    float* __restrict__ C, int N, unsigned sm_u)
{
    float acc[4][4][4] = {};
    mma_tile_pipe<false>(Ah, Al, Bh, nullptr, m0, n0, lda, ldb, kbase, kcnt, acc, sm_u);
    const int lane = threadIdx.x & 31, warp = threadIdx.x >> 5;
    const int wm = warp >> 2, wn = warp & 3;
    const int grp = lane >> 2, tig = lane & 3;
#pragma unroll
    for (int mt = 0; mt < 4; mt++)
#pragma unroll
        for (int nt = 0; nt < 4; nt++) {
            int row = m0 + wm * 64 + mt * 16 + grp;
            int col = n0 + wn * 32 + nt * 8 + tig * 2;
            float* a = acc[mt][nt];
            C[(size_t)row * N + col]           = a[0];
            C[(size_t)row * N + col + 1]       = a[1];
            C[(size_t)(row + 8) * N + col]     = a[2];
            C[(size_t)(row + 8) * N + col + 1] = a[3];
        }
}

// ---------------------------------------------------------------------------
// Attention body: scores from h16 fproj, ctx from h16 featH (8-half loads)
// ---------------------------------------------------------------------------
__device__ void attn_one(int b, int t,
                         const float* __restrict__ Ws, const float* __restrict__ bs,
                         const float* __restrict__ bh, const int* __restrict__ lengths,
                         float* sbuf)
{
    if (lengths[b] <= t) return;

    float* hp_s = sbuf;
    float* ws_s = sbuf + 512;
    float* sc_s = sbuf + 1024;
    int tid = threadIdx.x;
#pragma unroll
    for (int i = 0; i < 2; i++) {
        int a = tid + i * 256;
        float s = bh[a];
#pragma unroll
        for (int p = 0; p < 4; p++) s += g_hppart[(size_t)p * Bsz * Asz + b * Asz + a];
        hp_s[a] = s;
        ws_s[a] = Ws[a];
    }
    __syncthreads();

    int warp = tid >> 5, lane = tid & 31;
    for (int r = warp; r < Rsz; r += 8) {
        const h16* fp = &g_fproj[(size_t)(b * Rsz + r) * Asz];
        float s = 0.f;
        for (int a = lane; a < Asz; a += 32)
            s += tanhf(__half2float(fp[a]) + hp_s[a]) * ws_s[a];
#pragma unroll
        for (int o = 16; o; o >>= 1) s += __shfl_down_sync(0xffffffffu, s, o);
        if (lane == 0) sc_s[r] = s + bs[0];
    }
    __syncthreads();

    if (warp == 0) {
        float v1 = (lane < Rsz) ? sc_s[lane] : -INFINITY;
        float v2 = (lane + 32 < Rsz) ? sc_s[lane + 32] : -INFINITY;
        float mx = fmaxf(v1, v2);
#pragma unroll
        for (int o = 16; o; o >>= 1) mx = fmaxf(mx, __shfl_xor_sync(0xffffffffu, mx, o));
        float e1 = (lane < Rsz) ? expf(v1 - mx) : 0.f;
        float e2 = (lane + 32 < Rsz) ? expf(v2 - mx) : 0.f;
        float sm2 = e1 + e2;
#pragma unroll
        for (int o = 16; o; o >>= 1) sm2 += __shfl_xor_sync(0xffffffffu, sm2, o);
        float inv = 1.f / sm2;
        if (lane < Rsz) sc_s[lane] = e1 * inv;
        if (lane + 32 < Rsz) sc_s[lane + 32] = e2 * inv;
    }
    __syncthreads();

    // ctx from fp16 feats: 8 halves (16B) per thread per iter; Fsz/8 = 256
    const uint4* f8 = reinterpret_cast<const uint4*>(g_featH);
    {
        int f = tid;                       // one iteration (Fsz/8 == 256)
        float acc[8] = {};
#pragma unroll 7
        for (int r = 0; r < Rsz; r++) {
            uint4 v = f8[(size_t)(b * Rsz + r) * (Fsz / 8) + f];
            float al = sc_s[r];
            float2 p0 = __half22float2(*(__half2*)&v.x);
            float2 p1 = __half22float2(*(__half2*)&v.y);
            float2 p2 = __half22float2(*(__half2*)&v.z);
            float2 p3 = __half22float2(*(__half2*)&v.w);
            acc[0] = fmaf(al, p0.x, acc[0]); acc[1] = fmaf(al, p0.y, acc[1]);
            acc[2] = fmaf(al, p1.x, acc[2]); acc[3] = fmaf(al, p1.y, acc[3]);
            acc[4] = fmaf(al, p2.x, acc[4]); acc[5] = fmaf(al, p2.y, acc[5]);
            acc[6] = fmaf(al, p3.x, acc[6]); acc[7] = fmaf(al, p3.y, acc[7]);
        }
        int fb = f * 8;
#pragma unroll
        for (int q = 0; q < 8; q++)
            split2(acc[q], g_xhH[b * GK2 + fb + q], g_xhL[b * GK2 + fb + q]);
    }
    __syncthreads();
}

// ---------------------------------------------------------------------------
// Persistent kernel: step loop (CTAs 0..127) + overlap workers (128..147).
// ---------------------------------------------------------------------------
__global__ __launch_bounds__(256, 1) void decoder_loop(
    const float* __restrict__ Ws,
    const float* __restrict__ bs, const float* __restrict__ bh,
    const float* __restrict__ bih, const float* __restrict__ bhh,
    const float* __restrict__ bfc, const int* __restrict__ lengths,
    float* __restrict__ out)
{
    extern __shared__ __align__(16) char dsm[];
    unsigned sm_u = (unsigned)__cvta_generic_to_shared(dsm);
    const int cta = blockIdx.x;
    const int tid = threadIdx.x;
    __shared__ int s_tk;

    if (cta < LOOPC) {
        for (int t = 0; t < STEPS; t++) {
            // Phase 1: hp partials = h @ Wh^T  (2m x 4n x 4 split-K = 32 CTAs)
            if (cta < 32) {
                int kp = cta & 3, tile = cta >> 2;
                int m = tile & 1, n = tile >> 1;
                if (lengths[m * 128] > t)
                    mma_tile_raw(g_xhH + Fsz, g_xhL + Fsz, g_WhH,
                                 m * 128, n * 128, GK2, Hsz, kp * 128, 128,
                                 g_hppart + (size_t)kp * Bsz * Asz, Asz, sm_u);
            }
            gsync();

            // Phase 2: attention
            for (int b = cta; b < Bsz; b += LOOPC)
                attn_one(b, t, Ws, bs, bh, lengths, (float*)dsm);
            gsync();

            // Phase 3: gates partials (2m x 16n x 4 split-K = 128 CTAs)
            {
                int kp = cta & 3, tile = cta >> 2;
                int m = tile & 1, n = tile >> 1;
                if (lengths[m * 128] > t)
                    mma_tile_raw(g_xhH, g_xhL, g_Wg2H,
                                 m * 128, n * 128, GK2, GK2, kp * 640, 640,
                                 g_gpart + (size_t)kp * Bsz * G4, G4, sm_u);
            }
            gsync();

            // wait for this step's embproj tiles
            if (tid == 0) {
                while (*((volatile unsigned*)&g_emb_done[t]) < 32u) { }
            }
            __syncthreads();

            // Phase 4: LSTM pointwise
            for (int idx = cta * 256 + tid; idx < Bsz * Hsz; idx += LOOPC * 256) {
                int b = idx >> 9, j = idx & 511;
                if (lengths[b] > t) {
                    const int MN = Bsz * G4;
                    int base = b * G4;
                    const float* ep = &g_embproj[(size_t)(t * Bsz + b) * G4];
                    float gv[4];
#pragma unroll
                    for (int q = 0; q < 4; q++) {
                        int jj = q * 512 + j;
                        gv[q] = g_gpart[base + jj] + g_gpart[MN + base + jj]
                              + g_gpart[2 * MN + base + jj] + g_gpart[3 * MN + base + jj]
                              + ep[jj] + bih[jj] + bhh[jj];
                    }
                    float ig = 1.f / (1.f + expf(-gv[0]));
                    float fg = 1.f / (1.f + expf(-gv[1]));
                    float gg = tanhf(gv[2]);
                    float og = 1.f / (1.f + expf(-gv[3]));
                    float cn = fg * g_c[idx] + ig * gg;
                    float hn = og * tanhf(cn);
                    g_c[idx] = cn;
                    split2(hn, g_xhH[b * GK2 + Fsz + j], g_xhL[b * GK2 + Fsz + j]);
                    split2(hn, g_histH[(size_t)(t * Bsz + b) * Hsz + j],
                               g_histL[(size_t)(t * Bsz + b) * Hsz + j]);
                }
            }
            gsync();
            if (cta == 0 && tid == 0)
                atomicExch(&g_step_done, (unsigned)(t + 1));
        }
    }

    // ---- ticket drain: embproj tiles then FC tiles ----
    for (;;) {
        if (tid == 0) s_tk = (int)atomicAdd(&g_ticket, 1u);
        __syncthreads();
        int tk = s_tk;
        __syncthreads();
        if (tk >= EMBT + FCT) break;

        if (tk < EMBT) {
            int step = tk >> 5, unit = tk & 31;
            int m2 = unit & 1, n = unit >> 1;
            int m0 = step * 256 + m2 * 128, n0 = n * 128;
            mma_tile_raw(g_embAH, g_embAL, g_WihEH,
                         m0, n0, Esz, Esz, 0, Esz, g_embproj, G4, sm_u);
            if (tid == 0) {
                __threadfence();
                atomicAdd(&g_emb_done[step], 1u);
            }
            continue;
        }

        int ftk = tk - EMBT;
        int my = ftk / FCN, nx = ftk - my * FCN;
        int m0 = my * 128, n0 = nx * 128;
        int tt = m0 >> 8, b0 = m0 & 255;

        if (lengths[b0] <= tt) {
            for (int i = tid; i < 128 * 128; i += 256) {
                int r = i >> 7, cc = i & 127;
                int n = n0 + cc;
                if (n < Vsz)
                    out[((size_t)(b0 + r) * STEPS + tt) * Vsz + n] = 0.f;
            }
            continue;
        }

        if (tid == 0) {
            while (*((volatile unsigned*)&g_step_done) <= (unsigned)tt) { }
        }
        __syncthreads();
        __threadfence();

        float acc[4][4][4] = {};
        mma_tile_pipe<true>(g_histH, g_histL, g_WfcH, g_WfcL,
                            m0, n0, Hsz, Hsz, 0, Hsz, acc, sm_u);

        const int lane = tid & 31, warp = tid >> 5;
        const int wm = warp >> 2, wn = warp & 3;
        const int grp = lane >> 2, tig = lane & 3;
#pragma unroll
        for (int mt = 0; mt < 4; mt++)
#pragma unroll
            for (int nt = 0; nt < 4; nt++) {
                int row = m0 + wm * 64 + mt * 16 + grp;
                int col = n0 + wn * 32 + nt * 8 + tig * 2;
                float* a = acc[mt][nt];
                if (col < Vsz) {
                    int b0r = row & 255, tt0 = row >> 8;
                    int b1r = (row + 8) & 255, tt1 = (row + 8) >> 8;
                    bool act0 = lengths[b0r] > tt0;
                    bool act1 = lengths[b1r] > tt1;
                    float* p0 = out + ((size_t)b0r * STEPS + tt0) * Vsz;
                    float* p1 = out + ((size_t)b1r * STEPS + tt1) * Vsz;
                    p0[col]     = act0 ? (a[0] + bfc[col])     : 0.f;
                    p0[col + 1] = act0 ? (a[1] + bfc[col + 1]) : 0.f;
                    p1[col]     = act1 ? (a[2] + bfc[col])     : 0.f;
                    p1[col + 1] = act1 ? (a[3] + bfc[col + 1]) : 0.f;
                }
            }
    }
}

// ---------------------------------------------------------------------------
// Host HMMA GEMM (precompute). EPI: 3 = tanh(+bias) fp32 out, 4 = +bias h16 out
// ---------------------------------------------------------------------------
template <int EPI>
__global__ __launch_bounds__(256) void mma_gemm(
    const h16* __restrict__ Ah, const h16* __restrict__ Al,
    const h16* __restrict__ Bh,
    const float* __restrict__ bias, void* __restrict__ Cv,
    int M, int N, int lda, int ldb, int kspl)
{
    const int m0 = blockIdx.y * 128;
    const int n0 = blockIdx.x * 128;
    const int tid = threadIdx.x;

    extern __shared__ __align__(16) char dsm[];
    unsigned sm_u = (unsigned)__cvta_generic_to_shared(dsm);

    const int lane = tid & 31, warp = tid >> 5;
    const int wm = warp >> 2, wn = warp & 3;
    const int grp = lane >> 2, tig = lane & 3;

    float acc[4][4][4] = {};
    mma_tile_pipe<false>(Ah, Al, Bh, nullptr, m0, n0, lda, ldb, 0, kspl, acc, sm_u);

#pragma unroll
    for (int mt = 0; mt < 4; mt++)
#pragma unroll
        for (int nt = 0; nt < 4; nt++) {
            int row = m0 + wm * 64 + mt * 16 + grp;
            int col = n0 + wn * 32 + nt * 8 + tig * 2;
            float* a = acc[mt][nt];
            if (EPI == 3) {
                float* C = (float*)Cv;
                C[(size_t)row * N + col]           = tanhf(a[0] + bias[col]);
                C[(size_t)row * N + col + 1]       = tanhf(a[1] + bias[col + 1]);
                C[(size_t)(row + 8) * N + col]     = tanhf(a[2] + bias[col]);
                C[(size_t)(row + 8) * N + col + 1] = tanhf(a[3] + bias[col + 1]);
            } else {
                h16* C = (h16*)Cv;
                C[(size_t)row * N + col]           = __float2half_rn(a[0] + bias[col]);
                C[(size_t)row * N + col + 1]       = __float2half_rn(a[1] + bias[col + 1]);
                C[(size_t)(row + 8) * N + col]     = __float2half_rn(a[2] + bias[col]);
                C[(size_t)(row + 8) * N + col + 1] = __float2half_rn(a[3] + bias[col + 1]);
            }
        }
}

// ---------------------------------------------------------------------------
// Merged conversion kernel
// ---------------------------------------------------------------------------
__global__ void convert_weights(
    const float* __restrict__ Wf, const float* __restrict__ Wh,
    const float* __restrict__ Wih, const float* __restrict__ Whh,
    const float* __restrict__ Wi_h, const float* __restrict__ Wi_c,
    const float* __restrict__ bi_h, const float* __restrict__ bi_c,
    const float* __restrict__ Wfc,
    const float* __restrict__ embW, const int* __restrict__ ids)
{
    const int stride = gridDim.x * blockDim.x;
    const int tid0 = blockIdx.x * blockDim.x + threadIdx.x;

    for (int i = tid0; i < Asz * Fsz; i += stride)
        g_WfH[i] = __float2half_rn(Wf[i]);
    for (int i = tid0; i < Asz * Hsz; i += stride)
        g_WhH[i] = __float2half_rn(Wh[i]);
    for (int i = tid0; i < G4 * GK2; i += stride) {
        int r = i / GK2, cc = i - r * GK2;
        float v = (cc < Fsz) ? Wih[(size_t)r * (Esz + Fsz) + Esz + cc]
                             : Whh[(size_t)r * Hsz + cc - Fsz];
        g_Wg2H[i] = __float2half_rn(v);
    }
    for (int i = tid0; i < G4 * Esz; i += stride) {
        int r = i >> 8, cc = i & 255;
        g_WihEH[i] = __float2half_rn(Wih[(size_t)r * (Esz + Fsz) + cc]);
    }
    for (int i = tid0; i < 1024 * Fsz; i += stride) {
        int r = i / Fsz, cc = i - r * Fsz;
        float v = (r < Hsz) ? Wi_h[(size_t)r * Fsz + cc] : Wi_c[(size_t)(r - Hsz) * Fsz + cc];
        g_WiH[i] = __float2half_rn(v);
    }
    for (int i = tid0; i < 1024; i += stride)
        g_bi[i] = (i < Hsz) ? bi_h[i] : bi_c[i - Hsz];
    for (int i = tid0; i < VPAD * Hsz; i += stride) {
        int r = i >> 9;
        float v = (r < Vsz) ? Wfc[i] : 0.f;
        split2(v, g_WfcH[i], g_WfcL[i]);
    }
    for (int i = tid0; i < MROWS * Esz; i += stride) {
        int r = i >> 8, e = i & 255;
        int tt = r >> 8, b = r & 255;
        int id = ids[b * Lsz + tt];
        split2(embW[(size_t)id * Esz + e], g_embAH[i], g_embAL[i]);
    }
}

// merged: mean + feats hi/lo split (single feats pass)
__global__ void mean_split_feats(const float* __restrict__ feats)
{
    int b = blockIdx.x;
    for (int f = threadIdx.x; f < Fsz; f += blockDim.x) {
        float s = 0.f;
        for (int r = 0; r < Rsz; r++) {
            size_t idx = (size_t)(b * Rsz + r) * Fsz + f;
            float v = feats[idx];
            s += v;
            split2(v, g_featH[idx], g_featL[idx]);
        }
        split2(s * (1.0f / Rsz), g_meanH[b * Fsz + f], g_meanL[b * Fsz + f]);
    }
}

__global__ void init_state()
{
    int idx = blockIdx.x * blockDim.x + threadIdx.x;
    int b = idx >> 9, j = idx & 511;
    float h = g_h0c0[b * 1024 + j];
    float c = g_h0c0[b * 1024 + 512 + j];
    g_c[idx] = c;
    split2(h, g_xhH[b * GK2 + Fsz + j], g_xhL[b * GK2 + Fsz + j]);
    if (idx == 0) {
        g_step_done = 0;
        g_ticket = 0;
    }
    if (idx < 32) g_emb_done[idx] = 0;
}

// ---------------------------------------------------------------------------
extern "C" void kernel_launch(void* const* d_in, const int* in_sizes, int n_in,
                              void* d_out, int out_size)
{
    const float* feats   = (const float*)d_in[0];
    const int*   ids     = (const int*)  d_in[1];
    const int*   lengths = (const int*)  d_in[2];
    const float* embW    = (const float*)d_in[3];
    const float* Wf      = (const float*)d_in[4];
    const float* bf      = (const float*)d_in[5];
    const float* Wh      = (const float*)d_in[6];
    const float* bh      = (const float*)d_in[7];
    const float* Ws      = (const float*)d_in[8];
    const float* bs      = (const float*)d_in[9];
    const float* W_ih    = (const float*)d_in[10];
    const float* b_ih    = (const float*)d_in[11];
    const float* W_hh    = (const float*)d_in[12];
    const float* b_hh    = (const float*)d_in[13];
    const float* Wfc     = (const float*)d_in[14];
    const float* bfc     = (const float*)d_in[15];
    const float* Wi_h    = (const float*)d_in[16];
    const float* bi_h    = (const float*)d_in[17];
    const float* Wi_c    = (const float*)d_in[18];
    const float* bi_c    = (const float*)d_in[19];
    float* out = (float*)d_out;

    void *pv;
    cudaGetSymbolAddress(&pv, g_featH);  h16* featH = (h16*)pv;
    cudaGetSymbolAddress(&pv, g_featL);  h16* featL = (h16*)pv;
    cudaGetSymbolAddress(&pv, g_meanH);  h16* meanH = (h16*)pv;
    cudaGetSymbolAddress(&pv, g_meanL);  h16* meanL = (h16*)pv;
    cudaGetSymbolAddress(&pv, g_WfH);    h16* WfH = (h16*)pv;
    cudaGetSymbolAddress(&pv, g_WiH);    h16* WiH = (h16*)pv;
    cudaGetSymbolAddress(&pv, g_bi);     float* bi = (float*)pv;
    cudaGetSymbolAddress(&pv, g_h0c0);   float* h0c0 = (float*)pv;
    cudaGetSymbolAddress(&pv, g_fproj);  h16* fproj = (h16*)pv;

    cudaFuncSetAttribute(mma_gemm<3>, cudaFuncAttributeMaxDynamicSharedMemorySize, SMEM_DYN);
    cudaFuncSetAttribute(mma_gemm<4>, cudaFuncAttributeMaxDynamicSharedMemorySize, SMEM_DYN);
    cudaFuncSetAttribute(decoder_loop, cudaFuncAttributeMaxDynamicSharedMemorySize, SMEM_DYN);

    // ---- conversions ----
    mean_split_feats<<<Bsz, 256>>>(feats);
    convert_weights<<<592, 256>>>(Wf, Wh, W_ih, W_hh, Wi_h, Wi_c, bi_h, bi_c,
                                  Wfc, embW, ids);

    // ---- init state ----
    mma_gemm<3><<<dim3(8, 2, 1), 256, SMEM_DYN>>>(meanH, meanL, WiH, bi, h0c0,
                                                  Bsz, 1024, Fsz, Fsz, Fsz);
    init_state<<<(Bsz * Hsz) / 256, 256>>>();

    // ---- f_proj = feats @ Wf^T + bf (h16 output) ----
    mma_gemm<4><<<dim3(4, 98, 1), 256, SMEM_DYN>>>(featH, featL, WfH, bf, fproj,
                                                   Bsz * Rsz, Asz, Fsz, Fsz, Fsz);

    // ---- persistent recurrence + overlapped embproj & final FC ----
    decoder_loop<<<PALL, 256, SMEM_DYN>>>(Ws, bs, bh, b_ih, b_hh, bfc,
                                          lengths, out);
}

// round 16
// speedup vs baseline: 2.3548x; 1.0072x over previous
#include <cuda_runtime.h>
#include <cuda_fp16.h>
#include <cstdint>
#include <math.h>

#define Bsz 256
#define Lsz 24
#define Rsz 49
#define Fsz 2048
#define Esz 256
#define Hsz 512
#define Asz 512
#define Vsz 10000
#define STEPS 23
#define G4 2048
#define GK2 2560
#define VPAD 10112
#define MROWS (STEPS * Bsz)
#define NFEAT (Bsz * Rsz * Fsz)

#define LOOPC 128
#define PALL 148
#define FCM 46
#define FCN 79
#define FCT (FCM * FCN)
#define EMBT (STEPS * 32)

// BK = 64: per-array stage = 128 rows x 72 half = 18432 B
#define SST 18432
#define SMEM_DYN 147456   // 2 stages x 4 arrays (FC worst case)

typedef __half h16;

// ---------------- scratch ----------------
__device__ h16   g_fproj[Bsz * Rsz * Asz];
__device__ h16   g_featH[NFEAT], g_featL[NFEAT];
__device__ h16   g_meanH[Bsz * Fsz], g_meanL[Bsz * Fsz];
__device__ h16   g_WfH[Asz * Fsz];
__device__ h16   g_WhH[Asz * Hsz];
__device__ h16   g_Wg2H[G4 * GK2];
__device__ h16   g_WihEH[G4 * Esz];
__device__ h16   g_WiH[1024 * Fsz];
__device__ float g_bi[1024];
__device__ h16   g_WfcH[VPAD * Hsz], g_WfcL[VPAD * Hsz];
__device__ float g_h0c0[Bsz * 1024];
__device__ float g_c[Bsz * Hsz];
__device__ h16   g_xhH[Bsz * GK2], g_xhL[Bsz * GK2];
__device__ h16   g_embAH[MROWS * Esz], g_embAL[MROWS * Esz];
__device__ float g_embproj[MROWS * G4];
__device__ h16   g_histH[MROWS * Hsz], g_histL[MROWS * Hsz];
__device__ float g_gpart[7 * Bsz * G4];   // [0..3] ctx-part, [4..6] h-part
__device__ float g_hppart[4 * Bsz * Asz];

// tree barrier state (128 participants: 8 leaves x 16)
__device__ unsigned g_bar_leaf[8 * 32];
__device__ unsigned g_bar_root = 0;
__device__ unsigned g_bar_gen = 0;
// overlap state
__device__ unsigned g_step_done = 0;
__device__ unsigned g_ticket = 0;
__device__ unsigned g_emb_done[32];

__device__ __forceinline__ void split2(float x, h16& h, h16& l) {
    h = __float2half_rn(x);
    l = __float2half_rn(x - __half2float(h));
}

__device__ __forceinline__ void mma_f16(float* c, const unsigned* a, const unsigned* b) {
    asm volatile(
        "mma.sync.aligned.m16n8k16.row.col.f32.f16.f16.f32 "
        "{%0,%1,%2,%3},{%4,%5,%6,%7},{%8,%9},{%0,%1,%2,%3};\n"
        : "+f"(c[0]), "+f"(c[1]), "+f"(c[2]), "+f"(c[3])
        : "r"(a[0]), "r"(a[1]), "r"(a[2]), "r"(a[3]), "r"(b[0]), "r"(b[1]));
}

__device__ __forceinline__ void ldsm_x4(unsigned& r0, unsigned& r1, unsigned& r2, unsigned& r3,
                                        unsigned addr) {
    asm volatile("ldmatrix.sync.aligned.m8n8.x4.shared.b16 {%0,%1,%2,%3},[%4];"
                 : "=r"(r0), "=r"(r1), "=r"(r2), "=r"(r3) : "r"(addr));
}
__device__ __forceinline__ void ldsm_x2(unsigned& r0, unsigned& r1, unsigned addr) {
    asm volatile("ldmatrix.sync.aligned.m8n8.x2.shared.b16 {%0,%1},[%2];"
                 : "=r"(r0), "=r"(r1) : "r"(addr));
}

__device__ __forceinline__ void cpa16(unsigned dst, const h16* src) {
    asm volatile("cp.async.cg.shared.global [%0], [%1], 16;" :: "r"(dst), "l"(src));
}
__device__ __forceinline__ void cpcommit() { asm volatile("cp.async.commit_group;"); }
template <int N> __device__ __forceinline__ void cpwait() {
    asm volatile("cp.async.wait_group %0;" :: "n"(N));
}

// grid tree barrier among the first LOOPC CTAs only
__device__ __forceinline__ void gsync() {
    __syncthreads();
    if (threadIdx.x == 0) {
        __threadfence();
        unsigned gen = *((volatile unsigned*)&g_bar_gen);
        int leaf = (blockIdx.x >> 4) & 7;
        if (atomicAdd(&g_bar_leaf[leaf * 32], 1u) == 15u) {
            atomicExch(&g_bar_leaf[leaf * 32], 0u);
            if (atomicAdd(&g_bar_root, 1u) == 7u) {
                atomicExch(&g_bar_root, 0u);
                __threadfence();
                atomicAdd(&g_bar_gen, 1u);
            } else {
                while (*((volatile unsigned*)&g_bar_gen) == gen) { }
            }
        } else {
            while (*((volatile unsigned*)&g_bar_gen) == gen) { }
        }
        __threadfence();
    }
    __syncthreads();
}

// ---------------------------------------------------------------------------
// HMMA pipelined tile (128x128, BK=64, 2-stage cp.async).
// ---------------------------------------------------------------------------
template <bool T3>
__device__ __forceinline__ void load_chunk(
    unsigned sb, const h16* __restrict__ Ah, const h16* __restrict__ Al,
    const h16* __restrict__ Bh, const h16* __restrict__ Bl,
    int m0, int n0, int lda, int ldb, int kg)
{
    const int tid = threadIdx.x;
    const int rr = tid >> 3;
    const int c8 = tid & 7;
#pragma unroll
    for (int i = 0; i < 4; i++) {
        int r = rr + i * 32;
        size_t ga = (size_t)(m0 + r) * lda + kg + c8 * 8;
        size_t gb = (size_t)(n0 + r) * ldb + kg + c8 * 8;
        unsigned off = (unsigned)(r * 144 + c8 * 16);
        cpa16(sb + off,           Ah + ga);
        cpa16(sb + SST + off,     Al + ga);
        cpa16(sb + 2 * SST + off, Bh + gb);
        if (T3) cpa16(sb + 3 * SST + off, Bl + gb);
    }
}

template <bool T3>
__device__ __forceinline__ void mma_chunk(unsigned sb, float acc[4][4][4])
{
    const int lane = threadIdx.x & 31, warp = threadIdx.x >> 5;
    const int wm = warp >> 2, wn = warp & 3;
#pragma unroll
    for (int k16 = 0; k16 < 4; k16++) {
        const int aro = wm * 64 + (lane & 15);
        const int aco = k16 * 16 + ((lane >> 4) << 3);
        const int bro = wn * 32 + (lane & 7);
        const int bco = k16 * 16 + (((lane >> 3) & 1) << 3);
        unsigned ah[4][4], al[4][4], bh2[4][2], bl2[4][2];
#pragma unroll
        for (int mt = 0; mt < 4; mt++) {
            unsigned off = (unsigned)(((aro + mt * 16) * 72 + aco) * 2);
            ldsm_x4(ah[mt][0], ah[mt][1], ah[mt][2], ah[mt][3], sb + off);
            ldsm_x4(al[mt][0], al[mt][1], al[mt][2], al[mt][3], sb + SST + off);
        }
#pragma unroll
        for (int nt = 0; nt < 4; nt++) {
            unsigned off = (unsigned)(((bro + nt * 8) * 72 + bco) * 2);
            ldsm_x2(bh2[nt][0], bh2[nt][1], sb + 2 * SST + off);
            if (T3) ldsm_x2(bl2[nt][0], bl2[nt][1], sb + 3 * SST + off);
        }
#pragma unroll
        for (int nt = 0; nt < 4; nt++)
#pragma unroll
            for (int mt = 0; mt < 4; mt++) {
                mma_f16(acc[mt][nt], ah[mt], bh2[nt]);
                mma_f16(acc[mt][nt], al[mt], bh2[nt]);
                if (T3) mma_f16(acc[mt][nt], ah[mt], bl2[nt]);
            }
    }
}

template <bool T3>
__device__ __forceinline__ void mma_tile_pipe(
    const h16* __restrict__ Ah, const h16* __restrict__ Al,
    const h16* __restrict__ Bh, const h16* __restrict__ Bl,
    int m0, int n0, int lda, int ldb, int kbase, int kcnt,
    float acc[4][4][4], unsigned sm_u)
{
    const unsigned STG = (T3 ? 4 : 3) * SST;
    const int nch = kcnt >> 6;
    load_chunk<T3>(sm_u, Ah, Al, Bh, Bl, m0, n0, lda, ldb, kbase);
    cpcommit();
    for (int ic = 0; ic < nch; ic++) {
        if (ic + 1 < nch) {
            load_chunk<T3>(sm_u + ((ic + 1) & 1) * STG, Ah, Al, Bh, Bl,
                           m0, n0, lda, ldb, kbase + (ic + 1) * 64);
            cpcommit();
            cpwait<1>();
        } else {
            cpwait<0>();
        }
        __syncthreads();
        mma_chunk<T3>(sm_u + (ic & 1) * STG, acc);
        __syncthreads();
    }
}

__device__ void mma_tile_raw(
    const h16* __restrict__ Ah, const h16* __restrict__ Al,
    const h16* __restrict__ Bh,
    int m0, int n0, int lda, int ldb, int kbase, int kcnt,
    float* __restrict__ C, int N, unsigned sm_u)
{
    float acc[4][4][4] = {};
    mma_tile_pipe<false>(Ah, Al, Bh, nullptr, m0, n0, lda, ldb, kbase, kcnt, acc, sm_u);
    const int lane = threadIdx.x & 31, warp = threadIdx.x >> 5;
    const int wm = warp >> 2, wn = warp & 3;
    const int grp = lane >> 2, tig = lane & 3;
#pragma unroll
    for (int mt = 0; mt < 4; mt++)
#pragma unroll
        for (int nt = 0; nt < 4; nt++) {
            int row = m0 + wm * 64 + mt * 16 + grp;
            int col = n0 + wn * 32 + nt * 8 + tig * 2;
            float* a = acc[mt][nt];
            C[(size_t)row * N + col]           = a[0];
            C[(size_t)row * N + col + 1]       = a[1];
            C[(size_t)(row + 8) * N + col]     = a[2];
            C[(size_t)(row + 8) * N + col + 1] = a[3];
        }
}

// ---------------------------------------------------------------------------
// Attention body
// ---------------------------------------------------------------------------
__device__ void attn_one(int b, int t,
                         const float* __restrict__ Ws, const float* __restrict__ bs,
                         const float* __restrict__ bh, const int* __restrict__ lengths,
                         float* sbuf)
{
    if (lengths[b] <= t) return;

    float* hp_s = sbuf;
    float* ws_s = sbuf + 512;
    float* sc_s = sbuf + 1024;
    int tid = threadIdx.x;
#pragma unroll
    for (int i = 0; i < 2; i++) {
        int a = tid + i * 256;
        float s = bh[a];
#pragma unroll
        for (int p = 0; p < 4; p++) s += g_hppart[(size_t)p * Bsz * Asz + b * Asz + a];
        hp_s[a] = s;
        ws_s[a] = Ws[a];
    }
    __syncthreads();

    int warp = tid >> 5, lane = tid & 31;
    for (int r = warp; r < Rsz; r += 8) {
        const h16* fp = &g_fproj[(size_t)(b * Rsz + r) * Asz];
        float s = 0.f;
        for (int a = lane; a < Asz; a += 32)
            s += tanhf(__half2float(fp[a]) + hp_s[a]) * ws_s[a];
#pragma unroll
        for (int o = 16; o; o >>= 1) s += __shfl_down_sync(0xffffffffu, s, o);
        if (lane == 0) sc_s[r] = s + bs[0];
    }
    __syncthreads();

    if (warp == 0) {
        float v1 = (lane < Rsz) ? sc_s[lane] : -INFINITY;
        float v2 = (lane + 32 < Rsz) ? sc_s[lane + 32] : -INFINITY;
        float mx = fmaxf(v1, v2);
#pragma unroll
        for (int o = 16; o; o >>= 1) mx = fmaxf(mx, __shfl_xor_sync(0xffffffffu, mx, o));
        float e1 = (lane < Rsz) ? expf(v1 - mx) : 0.f;
        float e2 = (lane + 32 < Rsz) ? expf(v2 - mx) : 0.f;
        float sm2 = e1 + e2;
#pragma unroll
        for (int o = 16; o; o >>= 1) sm2 += __shfl_xor_sync(0xffffffffu, sm2, o);
        float inv = 1.f / sm2;
        if (lane < Rsz) sc_s[lane] = e1 * inv;
        if (lane + 32 < Rsz) sc_s[lane + 32] = e2 * inv;
    }
    __syncthreads();

    const uint4* f8 = reinterpret_cast<const uint4*>(g_featH);
    {
        int f = tid;
        float acc[8] = {};
#pragma unroll 7
        for (int r = 0; r < Rsz; r++) {
            uint4 v = f8[(size_t)(b * Rsz + r) * (Fsz / 8) + f];
            float al = sc_s[r];
            float2 p0 = __half22float2(*(__half2*)&v.x);
            float2 p1 = __half22float2(*(__half2*)&v.y);
            float2 p2 = __half22float2(*(__half2*)&v.z);
            float2 p3 = __half22float2(*(__half2*)&v.w);
            acc[0] = fmaf(al, p0.x, acc[0]); acc[1] = fmaf(al, p0.y, acc[1]);
            acc[2] = fmaf(al, p1.x, acc[2]); acc[3] = fmaf(al, p1.y, acc[3]);
            acc[4] = fmaf(al, p2.x, acc[4]); acc[5] = fmaf(al, p2.y, acc[5]);
            acc[6] = fmaf(al, p3.x, acc[6]); acc[7] = fmaf(al, p3.y, acc[7]);
        }
        int fb = f * 8;
#pragma unroll
        for (int q = 0; q < 8; q++)
            split2(acc[q], g_xhH[b * GK2 + fb + q], g_xhL[b * GK2 + fb + q]);
    }
    __syncthreads();
}

// ---------------------------------------------------------------------------
// Persistent kernel: step loop (CTAs 0..127) + overlap workers (128..147).
// ---------------------------------------------------------------------------
__global__ __launch_bounds__(256, 1) void decoder_loop(
    const float* __restrict__ Ws,
    const float* __restrict__ bs, const float* __restrict__ bh,
    const float* __restrict__ bih, const float* __restrict__ bhh,
    const float* __restrict__ bfc, const int* __restrict__ lengths,
    float* __restrict__ out)
{
    extern __shared__ __align__(16) char dsm[];
    unsigned sm_u = (unsigned)__cvta_generic_to_shared(dsm);
    const int cta = blockIdx.x;
    const int tid = threadIdx.x;
    __shared__ int s_tk;

    if (cta < LOOPC) {
        for (int t = 0; t < STEPS; t++) {
            // ---- Phase A: hp (CTAs 0..31) + gates-h slice (CTAs 32..127) ----
            if (cta < 32) {
                int kp = cta & 3, tile = cta >> 2;
                int m = tile & 1, n = tile >> 1;
                if (lengths[m * 128] > t)
                    mma_tile_raw(g_xhH + Fsz, g_xhL + Fsz, g_WhH,
                                 m * 128, n * 128, GK2, Hsz, kp * 128, 128,
                                 g_hppart + (size_t)kp * Bsz * Asz, Asz, sm_u);
            } else {
                int w = cta - 32;               // 0..95
                int kp = w % 3, tile = w / 3;   // 32 tiles x 3 split-K
                int m = tile & 1, n = tile >> 1;
                int kb = Fsz + kp * 192;
                int kc = (kp == 2) ? 128 : 192;
                if (lengths[m * 128] > t)
                    mma_tile_raw(g_xhH, g_xhL, g_Wg2H,
                                 m * 128, n * 128, GK2, GK2, kb, kc,
                                 g_gpart + (size_t)(4 + kp) * Bsz * G4, G4, sm_u);
            }
            gsync();

            // ---- Phase B: attention ----
            for (int b = cta; b < Bsz; b += LOOPC)
                attn_one(b, t, Ws, bs, bh, lengths, (float*)dsm);
            gsync();

            // ---- Phase C: gates ctx slice (2m x 16n x 4 split-K of 512) ----
            {
                int kp = cta & 3, tile = cta >> 2;
                int m = tile & 1, n = tile >> 1;
                if (lengths[m * 128] > t)
                    mma_tile_raw(g_xhH, g_xhL, g_Wg2H,
                                 m * 128, n * 128, GK2, GK2, kp * 512, 512,
                                 g_gpart + (size_t)kp * Bsz * G4, G4, sm_u);
            }
            gsync();

            // wait for this step's embproj tiles
            if (tid == 0) {
                while (*((volatile unsigned*)&g_emb_done[t]) < 32u) { }
            }
            __syncthreads();

            // ---- Phase D: LSTM pointwise (7 partials + embproj) ----
            for (int idx = cta * 256 + tid; idx < Bsz * Hsz; idx += LOOPC * 256) {
                int b = idx >> 9, j = idx & 511;
                if (lengths[b] > t) {
                    const int MN = Bsz * G4;
                    int base = b * G4;
                    const float* ep = &g_embproj[(size_t)(t * Bsz + b) * G4];
                    float gv[4];
#pragma unroll
                    for (int q = 0; q < 4; q++) {
                        int jj = q * 512 + j;
                        float s = ep[jj] + bih[jj] + bhh[jj];
#pragma unroll
                        for (int p = 0; p < 7; p++)
                            s += g_gpart[(size_t)p * MN + base + jj];
                        gv[q] = s;
                    }
                    float ig = 1.f / (1.f + expf(-gv[0]));
                    float fg = 1.f / (1.f + expf(-gv[1]));
                    float gg = tanhf(gv[2]);
                    float og = 1.f / (1.f + expf(-gv[3]));
                    float cn = fg * g_c[idx] + ig * gg;
                    float hn = og * tanhf(cn);
                    g_c[idx] = cn;
                    split2(hn, g_xhH[b * GK2 + Fsz + j], g_xhL[b * GK2 + Fsz + j]);
                    split2(hn, g_histH[(size_t)(t * Bsz + b) * Hsz + j],
                               g_histL[(size_t)(t * Bsz + b) * Hsz + j]);
                }
            }
            gsync();
            if (cta == 0 && tid == 0)
                atomicExch(&g_step_done, (unsigned)(t + 1));
        }
    }

    // ---- ticket drain: embproj tiles then FC tiles ----
    for (;;) {
        if (tid == 0) s_tk = (int)atomicAdd(&g_ticket, 1u);
        __syncthreads();
        int tk = s_tk;
        __syncthreads();
        if (tk >= EMBT + FCT) break;

        if (tk < EMBT) {
            int step = tk >> 5, unit = tk & 31;
            int m2 = unit & 1, n = unit >> 1;
            int m0 = step * 256 + m2 * 128, n0 = n * 128;
            mma_tile_raw(g_embAH, g_embAL, g_WihEH,
                         m0, n0, Esz, Esz, 0, Esz, g_embproj, G4, sm_u);
            if (tid == 0) {
                __threadfence();
                atomicAdd(&g_emb_done[step], 1u);
            }
            continue;
        }

        int ftk = tk - EMBT;
        int my = ftk / FCN, nx = ftk - my * FCN;
        int m0 = my * 128, n0 = nx * 128;
        int tt = m0 >> 8, b0 = m0 & 255;

        if (lengths[b0] <= tt) {
            for (int i = tid; i < 128 * 128; i += 256) {
                int r = i >> 7, cc = i & 127;
                int n = n0 + cc;
                if (n < Vsz)
                    out[((size_t)(b0 + r) * STEPS + tt) * Vsz + n] = 0.f;
            }
            continue;
        }

        if (tid == 0) {
            while (*((volatile unsigned*)&g_step_done) <= (unsigned)tt) { }
        }
        __syncthreads();
        __threadfence();

        float acc[4][4][4] = {};
        mma_tile_pipe<true>(g_histH, g_histL, g_WfcH, g_WfcL,
                            m0, n0, Hsz, Hsz, 0, Hsz, acc, sm_u);

        const int lane = tid & 31, warp = tid >> 5;
        const int wm = warp >> 2, wn = warp & 3;
        const int grp = lane >> 2, tig = lane & 3;
#pragma unroll
        for (int mt = 0; mt < 4; mt++)
#pragma unroll
            for (int nt = 0; nt < 4; nt++) {
                int row = m0 + wm * 64 + mt * 16 + grp;
                int col = n0 + wn * 32 + nt * 8 + tig * 2;
                float* a = acc[mt][nt];
                if (col < Vsz) {
                    int b0r = row & 255, tt0 = row >> 8;
                    int b1r = (row + 8) & 255, tt1 = (row + 8) >> 8;
                    bool act0 = lengths[b0r] > tt0;
                    bool act1 = lengths[b1r] > tt1;
                    float* p0 = out + ((size_t)b0r * STEPS + tt0) * Vsz;
                    float* p1 = out + ((size_t)b1r * STEPS + tt1) * Vsz;
                    p0[col]     = act0 ? (a[0] + bfc[col])     : 0.f;
                    p0[col + 1] = act0 ? (a[1] + bfc[col + 1]) : 0.f;
                    p1[col]     = act1 ? (a[2] + bfc[col])     : 0.f;
                    p1[col + 1] = act1 ? (a[3] + bfc[col + 1]) : 0.f;
                }
            }
    }
}

// ---------------------------------------------------------------------------
// Host HMMA GEMM (precompute). EPI: 3 = tanh(+bias) fp32 out, 4 = +bias h16 out
// ---------------------------------------------------------------------------
template <int EPI>
__global__ __launch_bounds__(256) void mma_gemm(
    const h16* __restrict__ Ah, const h16* __restrict__ Al,
    const h16* __restrict__ Bh,
    const float* __restrict__ bias, void* __restrict__ Cv,
    int M, int N, int lda, int ldb, int kspl)
{
    const int m0 = blockIdx.y * 128;
    const int n0 = blockIdx.x * 128;
    const int tid = threadIdx.x;

    extern __shared__ __align__(16) char dsm[];
    unsigned sm_u = (unsigned)__cvta_generic_to_shared(dsm);

    const int lane = tid & 31, warp = tid >> 5;
    const int wm = warp >> 2, wn = warp & 3;
    const int grp = lane >> 2, tig = lane & 3;

    float acc[4][4][4] = {};
    mma_tile_pipe<false>(Ah, Al, Bh, nullptr, m0, n0, lda, ldb, 0, kspl, acc, sm_u);

#pragma unroll
    for (int mt = 0; mt < 4; mt++)
#pragma unroll
        for (int nt = 0; nt < 4; nt++) {
            int row = m0 + wm * 64 + mt * 16 + grp;
            int col = n0 + wn * 32 + nt * 8 + tig * 2;
            float* a = acc[mt][nt];
            if (EPI == 3) {
                float* C = (float*)Cv;
                C[(size_t)row * N + col]           = tanhf(a[0] + bias[col]);
                C[(size_t)row * N + col + 1]       = tanhf(a[1] + bias[col + 1]);
                C[(size_t)(row + 8) * N + col]     = tanhf(a[2] + bias[col]);
                C[(size_t)(row + 8) * N + col + 1] = tanhf(a[3] + bias[col + 1]);
            } else {
                h16* C = (h16*)Cv;
                C[(size_t)row * N + col]           = __float2half_rn(a[0] + bias[col]);
                C[(size_t)row * N + col + 1]       = __float2half_rn(a[1] + bias[col + 1]);
                C[(size_t)(row + 8) * N + col]     = __float2half_rn(a[2] + bias[col]);
                C[(size_t)(row + 8) * N + col + 1] = __float2half_rn(a[3] + bias[col + 1]);
            }
        }
}

// ---------------------------------------------------------------------------
// Merged conversion kernel
// ---------------------------------------------------------------------------
__global__ void convert_weights(
    const float* __restrict__ Wf, const float* __restrict__ Wh,
    const float* __restrict__ Wih, const float* __restrict__ Whh,
    const float* __restrict__ Wi_h, const float* __restrict__ Wi_c,
    const float* __restrict__ bi_h, const float* __restrict__ bi_c,
    const float* __restrict__ Wfc,
    const float* __restrict__ embW, const int* __restrict__ ids)
{
    const int stride = gridDim.x * blockDim.x;
    const int tid0 = blockIdx.x * blockDim.x + threadIdx.x;

    for (int i = tid0; i < Asz * Fsz; i += stride)
        g_WfH[i] = __float2half_rn(Wf[i]);
    for (int i = tid0; i < Asz * Hsz; i += stride)
        g_WhH[i] = __float2half_rn(Wh[i]);
    for (int i = tid0; i < G4 * GK2; i += stride) {
        int r = i / GK2, cc = i - r * GK2;
        float v = (cc < Fsz) ? Wih[(size_t)r * (Esz + Fsz) + Esz + cc]
                             : Whh[(size_t)r * Hsz + cc - Fsz];
        g_Wg2H[i] = __float2half_rn(v);
    }
    for (int i = tid0; i < G4 * Esz; i += stride) {
        int r = i >> 8, cc = i & 255;
        g_WihEH[i] = __float2half_rn(Wih[(size_t)r * (Esz + Fsz) + cc]);
    }
    for (int i = tid0; i < 1024 * Fsz; i += stride) {
        int r = i / Fsz, cc = i - r * Fsz;
        float v = (r < Hsz) ? Wi_h[(size_t)r * Fsz + cc] : Wi_c[(size_t)(r - Hsz) * Fsz + cc];
        g_WiH[i] = __float2half_rn(v);
    }
    for (int i = tid0; i < 1024; i += stride)
        g_bi[i] = (i < Hsz) ? bi_h[i] : bi_c[i - Hsz];
    for (int i = tid0; i < VPAD * Hsz; i += stride) {
        int r = i >> 9;
        float v = (r < Vsz) ? Wfc[i] : 0.f;
        split2(v, g_WfcH[i], g_WfcL[i]);
    }
    for (int i = tid0; i < MROWS * Esz; i += stride) {
        int r = i >> 8, e = i & 255;
        int tt = r >> 8, b = r & 255;
        int id = ids[b * Lsz + tt];
        split2(embW[(size_t)id * Esz + e], g_embAH[i], g_embAL[i]);
    }
}

// merged: mean + feats split (single feats pass)
__global__ void mean_split_feats(const float* __restrict__ feats)
{
    int b = blockIdx.x;
    for (int f = threadIdx.x; f < Fsz; f += blockDim.x) {
        float s = 0.f;
        for (int r = 0; r < Rsz; r++) {
            size_t idx = (size_t)(b * Rsz + r) * Fsz + f;
            float v = feats[idx];
            s += v;
            split2(v, g_featH[idx], g_featL[idx]);
        }
        split2(s * (1.0f / Rsz), g_meanH[b * Fsz + f], g_meanL[b * Fsz + f]);
    }
}

__global__ void init_state()
{
    int idx = blockIdx.x * blockDim.x + threadIdx.x;
    int b = idx >> 9, j = idx & 511;
    float h = g_h0c0[b * 1024 + j];
    float c = g_h0c0[b * 1024 + 512 + j];
    g_c[idx] = c;
    split2(h, g_xhH[b * GK2 + Fsz + j], g_xhL[b * GK2 + Fsz + j]);
    if (idx == 0) {
        g_step_done = 0;
        g_ticket = 0;
    }
    if (idx < 32) g_emb_done[idx] = 0;
}

// ---------------------------------------------------------------------------
extern "C" void kernel_launch(void* const* d_in, const int* in_sizes, int n_in,
                              void* d_out, int out_size)
{
    const float* feats   = (const float*)d_in[0];
    const int*   ids     = (const int*)  d_in[1];
    const int*   lengths = (const int*)  d_in[2];
    const float* embW    = (const float*)d_in[3];
    const float* Wf      = (const float*)d_in[4];
    const float* bf      = (const float*)d_in[5];
    const float* Wh      = (const float*)d_in[6];
    const float* bh      = (const float*)d_in[7];
    const float* Ws      = (const float*)d_in[8];
    const float* bs      = (const float*)d_in[9];
    const float* W_ih    = (const float*)d_in[10];
    const float* b_ih    = (const float*)d_in[11];
    const float* W_hh    = (const float*)d_in[12];
    const float* b_hh    = (const float*)d_in[13];
    const float* Wfc     = (const float*)d_in[14];
    const float* bfc     = (const float*)d_in[15];
    const float* Wi_h    = (const float*)d_in[16];
    const float* bi_h    = (const float*)d_in[17];
    const float* Wi_c    = (const float*)d_in[18];
    const float* bi_c    = (const float*)d_in[19];
    float* out = (float*)d_out;

    void *pv;
    cudaGetSymbolAddress(&pv, g_featH);  h16* featH = (h16*)pv;
    cudaGetSymbolAddress(&pv, g_featL);  h16* featL = (h16*)pv;
    cudaGetSymbolAddress(&pv, g_meanH);  h16* meanH = (h16*)pv;
    cudaGetSymbolAddress(&pv, g_meanL);  h16* meanL = (h16*)pv;
    cudaGetSymbolAddress(&pv, g_WfH);    h16* WfH = (h16*)pv;
    cudaGetSymbolAddress(&pv, g_WiH);    h16* WiH = (h16*)pv;
    cudaGetSymbolAddress(&pv, g_bi);     float* bi = (float*)pv;
    cudaGetSymbolAddress(&pv, g_h0c0);   float* h0c0 = (float*)pv;
    cudaGetSymbolAddress(&pv, g_fproj);  h16* fproj = (h16*)pv;

    cudaFuncSetAttribute(mma_gemm<3>, cudaFuncAttributeMaxDynamicSharedMemorySize, SMEM_DYN);
    cudaFuncSetAttribute(mma_gemm<4>, cudaFuncAttributeMaxDynamicSharedMemorySize, SMEM_DYN);
    cudaFuncSetAttribute(decoder_loop, cudaFuncAttributeMaxDynamicSharedMemorySize, SMEM_DYN);

    // ---- conversions ----
    mean_split_feats<<<Bsz, 256>>>(feats);
    convert_weights<<<592, 256>>>(Wf, Wh, W_ih, W_hh, Wi_h, Wi_c, bi_h, bi_c,
                                  Wfc, embW, ids);

    // ---- init state ----
    mma_gemm<3><<<dim3(8, 2, 1), 256, SMEM_DYN>>>(meanH, meanL, WiH, bi, h0c0,
                                                  Bsz, 1024, Fsz, Fsz, Fsz);
    init_state<<<(Bsz * Hsz) / 256, 256>>>();

    // ---- f_proj = feats @ Wf^T + bf (h16 output) ----
    mma_gemm<4><<<dim3(4, 98, 1), 256, SMEM_DYN>>>(featH, featL, WfH, bf, fproj,
                                                   Bsz * Rsz, Asz, Fsz, Fsz, Fsz);

    // ---- persistent recurrence + overlapped embproj & final FC ----
    decoder_loop<<<PALL, 256, SMEM_DYN>>>(Ws, bs, bh, b_ih, b_hh, bfc,
                                          lengths, out);
}

// round 17
// speedup vs baseline: 2.3763x; 1.0091x over previous
#include <cuda_runtime.h>
#include <cuda_fp16.h>
#include <cstdint>
#include <math.h>

#define Bsz 256
#define Lsz 24
#define Rsz 49
#define Fsz 2048
#define Esz 256
#define Hsz 512
#define Asz 512
#define Vsz 10000
#define STEPS 23
#define G4 2048
#define GK2 2560
#define VPAD 10112
#define MROWS (STEPS * Bsz)
#define NFEAT (Bsz * Rsz * Fsz)

#define LOOPC 128
#define PALL 148
#define FCM 46
#define FCN 79
#define FCT (FCM * FCN)
#define EMBT (STEPS * 32)

// BK = 64: per-array stage = 128 rows x 72 half = 18432 B
#define SST 18432
#define SMEM_DYN 147456   // 2 stages x 4 arrays (FC worst case)

typedef __half h16;

// ---------------- scratch ----------------
__device__ h16   g_fproj[Bsz * Rsz * Asz];
__device__ h16   g_featH[NFEAT], g_featL[NFEAT];
__device__ h16   g_meanH[Bsz * Fsz], g_meanL[Bsz * Fsz];
__device__ h16   g_WfH[Asz * Fsz];
__device__ h16   g_WhH[Asz * Hsz];
__device__ h16   g_Wg2H[G4 * GK2];
__device__ h16   g_WihEH[G4 * Esz];
__device__ h16   g_WiH[1024 * Fsz];
__device__ float g_bi[1024];
__device__ h16   g_WfcH[VPAD * Hsz], g_WfcL[VPAD * Hsz];
__device__ float g_h0c0[Bsz * 1024];
__device__ float g_c[Bsz * Hsz];
__device__ h16   g_xhH[Bsz * GK2], g_xhL[Bsz * GK2];
__device__ h16   g_embAH[MROWS * Esz], g_embAL[MROWS * Esz];
__device__ float g_embproj[MROWS * G4];
__device__ h16   g_histH[MROWS * Hsz], g_histL[MROWS * Hsz];
__device__ float g_gpart[7 * Bsz * G4];   // [0..3] ctx-part, [4..6] h-part
__device__ float g_hppart[4 * Bsz * Asz];

// tree barrier state (128 participants: 8 leaves x 16)
__device__ unsigned g_bar_leaf[8 * 32];
__device__ unsigned g_bar_root = 0;
__device__ unsigned g_bar_gen = 0;
// overlap state
__device__ unsigned g_step_done = 0;
__device__ unsigned g_ticket = 0;
__device__ unsigned g_emb_done[32];

__device__ __forceinline__ void split2(float x, h16& h, h16& l) {
    h = __float2half_rn(x);
    l = __float2half_rn(x - __half2float(h));
}

// ------------- acquire/release primitives -------------
__device__ __forceinline__ unsigned atom_add_acqrel(unsigned* p, unsigned v) {
    unsigned old;
    asm volatile("atom.add.acq_rel.gpu.u32 %0, [%1], %2;"
                 : "=r"(old) : "l"(p), "r"(v) : "memory");
    return old;
}
__device__ __forceinline__ void red_add_release(unsigned* p, unsigned v) {
    asm volatile("red.add.release.gpu.u32 [%0], %1;" :: "l"(p), "r"(v) : "memory");
}
__device__ __forceinline__ unsigned ld_acq(const unsigned* p) {
    unsigned v;
    asm volatile("ld.acquire.gpu.u32 %0, [%1];" : "=r"(v) : "l"(p) : "memory");
    return v;
}
__device__ __forceinline__ void st_relax(unsigned* p, unsigned v) {
    asm volatile("st.relaxed.gpu.u32 [%0], %1;" :: "l"(p), "r"(v) : "memory");
}

__device__ __forceinline__ void mma_f16(float* c, const unsigned* a, const unsigned* b) {
    asm volatile(
        "mma.sync.aligned.m16n8k16.row.col.f32.f16.f16.f32 "
        "{%0,%1,%2,%3},{%4,%5,%6,%7},{%8,%9},{%0,%1,%2,%3};\n"
        : "+f"(c[0]), "+f"(c[1]), "+f"(c[2]), "+f"(c[3])
        : "r"(a[0]), "r"(a[1]), "r"(a[2]), "r"(a[3]), "r"(b[0]), "r"(b[1]));
}

__device__ __forceinline__ void ldsm_x4(unsigned& r0, unsigned& r1, unsigned& r2, unsigned& r3,
                                        unsigned addr) {
    asm volatile("ldmatrix.sync.aligned.m8n8.x4.shared.b16 {%0,%1,%2,%3},[%4];"
                 : "=r"(r0), "=r"(r1), "=r"(r2), "=r"(r3) : "r"(addr));
}
__device__ __forceinline__ void ldsm_x2(unsigned& r0, unsigned& r1, unsigned addr) {
    asm volatile("ldmatrix.sync.aligned.m8n8.x2.shared.b16 {%0,%1},[%2];"
                 : "=r"(r0), "=r"(r1) : "r"(addr));
}

__device__ __forceinline__ void cpa16(unsigned dst, const h16* src) {
    asm volatile("cp.async.cg.shared.global [%0], [%1], 16;" :: "r"(dst), "l"(src));
}
__device__ __forceinline__ void cpcommit() { asm volatile("cp.async.commit_group;"); }
template <int N> __device__ __forceinline__ void cpwait() {
    asm volatile("cp.async.wait_group %0;" :: "n"(N));
}

// grid tree barrier among the first LOOPC CTAs (acq/rel, no membar)
__device__ __forceinline__ void gsync() {
    __syncthreads();
    if (threadIdx.x == 0) {
        unsigned gen = *((volatile unsigned*)&g_bar_gen);   // same-loc monotonic
        int leaf = (blockIdx.x >> 4) & 7;
        if (atom_add_acqrel(&g_bar_leaf[leaf * 32], 1u) == 15u) {
            st_relax(&g_bar_leaf[leaf * 32], 0u);
            if (atom_add_acqrel(&g_bar_root, 1u) == 7u) {
                st_relax(&g_bar_root, 0u);
                red_add_release(&g_bar_gen, 1u);
            } else {
                while (ld_acq(&g_bar_gen) == gen) { }
            }
        } else {
            while (ld_acq(&g_bar_gen) == gen) { }
        }
    }
    __syncthreads();
}

// ---------------------------------------------------------------------------
// HMMA pipelined tile (128x128, BK=64, 2 stages, ONE sync per chunk).
// Loop body: wait(chunk ic) -> sync -> issue load(ic+1) -> compute(ic).
// ---------------------------------------------------------------------------
template <bool T3>
__device__ __forceinline__ void load_chunk(
    unsigned sb, const h16* __restrict__ Ah, const h16* __restrict__ Al,
    const h16* __restrict__ Bh, const h16* __restrict__ Bl,
    int m0, int n0, int lda, int ldb, int kg)
{
    const int tid = threadIdx.x;
    const int rr = tid >> 3;
    const int c8 = tid & 7;
#pragma unroll
    for (int i = 0; i < 4; i++) {
        int r = rr + i * 32;
        size_t ga = (size_t)(m0 + r) * lda + kg + c8 * 8;
        size_t gb = (size_t)(n0 + r) * ldb + kg + c8 * 8;
        unsigned off = (unsigned)(r * 144 + c8 * 16);
        cpa16(sb + off,           Ah + ga);
        cpa16(sb + SST + off,     Al + ga);
        cpa16(sb + 2 * SST + off, Bh + gb);
        if (T3) cpa16(sb + 3 * SST + off, Bl + gb);
    }
}

template <bool T3>
__device__ __forceinline__ void mma_chunk(unsigned sb, float acc[4][4][4])
{
    const int lane = threadIdx.x & 31, warp = threadIdx.x >> 5;
    const int wm = warp >> 2, wn = warp & 3;
#pragma unroll
    for (int k16 = 0; k16 < 4; k16++) {
        const int aro = wm * 64 + (lane & 15);
        const int aco = k16 * 16 + ((lane >> 4) << 3);
        const int bro = wn * 32 + (lane & 7);
        const int bco = k16 * 16 + (((lane >> 3) & 1) << 3);
        unsigned ah[4][4], al[4][4], bh2[4][2], bl2[4][2];
#pragma unroll
        for (int mt = 0; mt < 4; mt++) {
            unsigned off = (unsigned)(((aro + mt * 16) * 72 + aco) * 2);
            ldsm_x4(ah[mt][0], ah[mt][1], ah[mt][2], ah[mt][3], sb + off);
            ldsm_x4(al[mt][0], al[mt][1], al[mt][2], al[mt][3], sb + SST + off);
        }
#pragma unroll
        for (int nt = 0; nt < 4; nt++) {
            unsigned off = (unsigned)(((bro + nt * 8) * 72 + bco) * 2);
            ldsm_x2(bh2[nt][0], bh2[nt][1], sb + 2 * SST + off);
            if (T3) ldsm_x2(bl2[nt][0], bl2[nt][1], sb + 3 * SST + off);
        }
#pragma unroll
        for (int nt = 0; nt < 4; nt++)
#pragma unroll
            for (int mt = 0; mt < 4; mt++) {
                mma_f16(acc[mt][nt], ah[mt], bh2[nt]);
                mma_f16(acc[mt][nt], al[mt], bh2[nt]);
                if (T3) mma_f16(acc[mt][nt], ah[mt], bl2[nt]);
            }
    }
}

template <bool T3>
__device__ __forceinline__ void mma_tile_pipe(
    const h16* __restrict__ Ah, const h16* __restrict__ Al,
    const h16* __restrict__ Bh, const h16* __restrict__ Bl,
    int m0, int n0, int lda, int ldb, int kbase, int kcnt,
    float acc[4][4][4], unsigned sm_u)
{
    const unsigned STG = (T3 ? 4 : 3) * SST;
    const int nch = kcnt >> 6;
    load_chunk<T3>(sm_u, Ah, Al, Bh, Bl, m0, n0, lda, ldb, kbase);
    cpcommit();
    for (int ic = 0; ic < nch; ic++) {
        cpwait<0>();                  // chunk ic landed
        __syncthreads();              // visible to all; prev compute finished
        if (ic + 1 < nch) {
            load_chunk<T3>(sm_u + ((ic + 1) & 1) * STG, Ah, Al, Bh, Bl,
                           m0, n0, lda, ldb, kbase + (ic + 1) * 64);
            cpcommit();
        }
        mma_chunk<T3>(sm_u + (ic & 1) * STG, acc);
    }
}

__device__ void mma_tile_raw(
    const h16* __restrict__ Ah, const h16* __restrict__ Al,
    const h16* __restrict__ Bh,
    int m0, int n0, int lda, int ldb, int kbase, int kcnt,
    float* __restrict__ C, int N, unsigned sm_u)
{
    float acc[4][4][4] = {};
    mma_tile_pipe<false>(Ah, Al, Bh, nullptr, m0, n0, lda, ldb, kbase, kcnt, acc, sm_u);
    const int lane = threadIdx.x & 31, warp = threadIdx.x >> 5;
    const int wm = warp >> 2, wn = warp & 3;
    const int grp = lane >> 2, tig = lane & 3;
#pragma unroll
    for (int mt = 0; mt < 4; mt++)
#pragma unroll
        for (int nt = 0; nt < 4; nt++) {
            int row = m0 + wm * 64 + mt * 16 + grp;
            int col = n0 + wn * 32 + nt * 8 + tig * 2;
            float* a = acc[mt][nt];
            C[(size_t)row * N + col]           = a[0];
            C[(size_t)row * N + col + 1]       = a[1];
            C[(size_t)(row + 8) * N + col]     = a[2];
            C[(size_t)(row + 8) * N + col + 1] = a[3];
        }
}

// ---------------------------------------------------------------------------
// Attention body
// ---------------------------------------------------------------------------
__device__ void attn_one(int b, int t,
                         const float* __restrict__ Ws, const float* __restrict__ bs,
                         const float* __restrict__ bh, const int* __restrict__ lengths,
                         float* sbuf)
{
    if (lengths[b] <= t) return;

    float* hp_s = sbuf;
    float* ws_s = sbuf + 512;
    float* sc_s = sbuf + 1024;
    int tid = threadIdx.x;
#pragma unroll
    for (int i = 0; i < 2; i++) {
        int a = tid + i * 256;
        float s = bh[a];
#pragma unroll
        for (int p = 0; p < 4; p++) s += g_hppart[(size_t)p * Bsz * Asz + b * Asz + a];
        hp_s[a] = s;
        ws_s[a] = Ws[a];
    }
    __syncthreads();

    int warp = tid >> 5, lane = tid & 31;
    for (int r = warp; r < Rsz; r += 8) {
        const h16* fp = &g_fproj[(size_t)(b * Rsz + r) * Asz];
        float s = 0.f;
        for (int a = lane; a < Asz; a += 32)
            s += tanhf(__half2float(fp[a]) + hp_s[a]) * ws_s[a];
#pragma unroll
        for (int o = 16; o; o >>= 1) s += __shfl_down_sync(0xffffffffu, s, o);
        if (lane == 0) sc_s[r] = s + bs[0];
    }
    __syncthreads();

    if (warp == 0) {
        float v1 = (lane < Rsz) ? sc_s[lane] : -INFINITY;
        float v2 = (lane + 32 < Rsz) ? sc_s[lane + 32] : -INFINITY;
        float mx = fmaxf(v1, v2);
#pragma unroll
        for (int o = 16; o; o >>= 1) mx = fmaxf(mx, __shfl_xor_sync(0xffffffffu, mx, o));
        float e1 = (lane < Rsz) ? expf(v1 - mx) : 0.f;
        float e2 = (lane + 32 < Rsz) ? expf(v2 - mx) : 0.f;
        float sm2 = e1 + e2;
#pragma unroll
        for (int o = 16; o; o >>= 1) sm2 += __shfl_xor_sync(0xffffffffu, sm2, o);
        float inv = 1.f / sm2;
        if (lane < Rsz) sc_s[lane] = e1 * inv;
        if (lane + 32 < Rsz) sc_s[lane + 32] = e2 * inv;
    }
    __syncthreads();

    const uint4* f8 = reinterpret_cast<const uint4*>(g_featH);
    {
        int f = tid;
        float acc[8] = {};
#pragma unroll 7
        for (int r = 0; r < Rsz; r++) {
            uint4 v = f8[(size_t)(b * Rsz + r) * (Fsz / 8) + f];
            float al = sc_s[r];
            float2 p0 = __half22float2(*(__half2*)&v.x);
            float2 p1 = __half22float2(*(__half2*)&v.y);
            float2 p2 = __half22float2(*(__half2*)&v.z);
            float2 p3 = __half22float2(*(__half2*)&v.w);
            acc[0] = fmaf(al, p0.x, acc[0]); acc[1] = fmaf(al, p0.y, acc[1]);
            acc[2] = fmaf(al, p1.x, acc[2]); acc[3] = fmaf(al, p1.y, acc[3]);
            acc[4] = fmaf(al, p2.x, acc[4]); acc[5] = fmaf(al, p2.y, acc[5]);
            acc[6] = fmaf(al, p3.x, acc[6]); acc[7] = fmaf(al, p3.y, acc[7]);
        }
        int fb = f * 8;
#pragma unroll
        for (int q = 0; q < 8; q++)
            split2(acc[q], g_xhH[b * GK2 + fb + q], g_xhL[b * GK2 + fb + q]);
    }
    __syncthreads();
}

// ---------------------------------------------------------------------------
// Persistent kernel: step loop (CTAs 0..127) + overlap workers (128..147).
// ---------------------------------------------------------------------------
__global__ __launch_bounds__(256, 1) void decoder_loop(
    const float* __restrict__ Ws,
    const float* __restrict__ bs, const float* __restrict__ bh,
    const float* __restrict__ bih, const float* __restrict__ bhh,
    const float* __restrict__ bfc, const int* __restrict__ lengths,
    float* __restrict__ out)
{
    extern __shared__ __align__(16) char dsm[];
    unsigned sm_u = (unsigned)__cvta_generic_to_shared(dsm);
    const int cta = blockIdx.x;
    const int tid = threadIdx.x;
    __shared__ int s_tk;

    if (cta < LOOPC) {
        for (int t = 0; t < STEPS; t++) {
            // ---- Phase A: hp (CTAs 0..31) + gates-h slice (CTAs 32..127) ----
            if (cta < 32) {
                int kp = cta & 3, tile = cta >> 2;
                int m = tile & 1, n = tile >> 1;
                if (lengths[m * 128] > t)
                    mma_tile_raw(g_xhH + Fsz, g_xhL + Fsz, g_WhH,
                                 m * 128, n * 128, GK2, Hsz, kp * 128, 128,
                                 g_hppart + (size_t)kp * Bsz * Asz, Asz, sm_u);
            } else {
                int w = cta - 32;               // 0..95
                int kp = w % 3, tile = w / 3;   // 32 tiles x 3 split-K
                int m = tile & 1, n = tile >> 1;
                int kb = Fsz + kp * 192;
                int kc = (kp == 2) ? 128 : 192;
                if (lengths[m * 128] > t)
                    mma_tile_raw(g_xhH, g_xhL, g_Wg2H,
                                 m * 128, n * 128, GK2, GK2, kb, kc,
                                 g_gpart + (size_t)(4 + kp) * Bsz * G4, G4, sm_u);
            }
            gsync();

            // ---- Phase B: attention ----
            for (int b = cta; b < Bsz; b += LOOPC)
                attn_one(b, t, Ws, bs, bh, lengths, (float*)dsm);
            gsync();

            // ---- Phase C: gates ctx slice (2m x 16n x 4 split-K of 512) ----
            {
                int kp = cta & 3, tile = cta >> 2;
                int m = tile & 1, n = tile >> 1;
                if (lengths[m * 128] > t)
                    mma_tile_raw(g_xhH, g_xhL, g_Wg2H,
                                 m * 128, n * 128, GK2, GK2, kp * 512, 512,
                                 g_gpart + (size_t)kp * Bsz * G4, G4, sm_u);
            }
            gsync();

            // wait for this step's embproj tiles
            if (tid == 0) {
                while (ld_acq(&g_emb_done[t]) < 32u) { __nanosleep(64); }
            }
            __syncthreads();

            // ---- Phase D: LSTM pointwise (7 partials + embproj) ----
            for (int idx = cta * 256 + tid; idx < Bsz * Hsz; idx += LOOPC * 256) {
                int b = idx >> 9, j = idx & 511;
                if (lengths[b] > t) {
                    const int MN = Bsz * G4;
                    int base = b * G4;
                    const float* ep = &g_embproj[(size_t)(t * Bsz + b) * G4];
                    float gv[4];
#pragma unroll
                    for (int q = 0; q < 4; q++) {
                        int jj = q * 512 + j;
                        float s = ep[jj] + bih[jj] + bhh[jj];
#pragma unroll
                        for (int p = 0; p < 7; p++)
                            s += g_gpart[(size_t)p * MN + base + jj];
                        gv[q] = s;
                    }
                    float ig = 1.f / (1.f + expf(-gv[0]));
                    float fg = 1.f / (1.f + expf(-gv[1]));
                    float gg = tanhf(gv[2]);
                    float og = 1.f / (1.f + expf(-gv[3]));
                    float cn = fg * g_c[idx] + ig * gg;
                    float hn = og * tanhf(cn);
                    g_c[idx] = cn;
                    split2(hn, g_xhH[b * GK2 + Fsz + j], g_xhL[b * GK2 + Fsz + j]);
                    split2(hn, g_histH[(size_t)(t * Bsz + b) * Hsz + j],
                               g_histL[(size_t)(t * Bsz + b) * Hsz + j]);
                }
            }
            gsync();
            if (cta == 0 && tid == 0)
                red_add_release(&g_step_done, 1u);
        }
    }

    // ---- ticket drain: embproj tiles then FC tiles ----
    for (;;) {
        if (tid == 0) s_tk = (int)atomicAdd(&g_ticket, 1u);
        __syncthreads();
        int tk = s_tk;
        __syncthreads();
        if (tk >= EMBT + FCT) break;

        if (tk < EMBT) {
            int step = tk >> 5, unit = tk & 31;
            int m2 = unit & 1, n = unit >> 1;
            int m0 = step * 256 + m2 * 128, n0 = n * 128;
            mma_tile_raw(g_embAH, g_embAL, g_WihEH,
                         m0, n0, Esz, Esz, 0, Esz, g_embproj, G4, sm_u);
            __syncthreads();                 // all stores of this CTA done
            if (tid == 0)
                red_add_release(&g_emb_done[step], 1u);
            continue;
        }

        int ftk = tk - EMBT;
        int my = ftk / FCN, nx = ftk - my * FCN;
        int m0 = my * 128, n0 = nx * 128;
        int tt = m0 >> 8, b0 = m0 & 255;

        if (lengths[b0] <= tt) {
            for (int i = tid; i < 128 * 128; i += 256) {
                int r = i >> 7, cc = i & 127;
                int n = n0 + cc;
                if (n < Vsz)
                    out[((size_t)(b0 + r) * STEPS + tt) * Vsz + n] = 0.f;
            }
            continue;
        }

        if (tid == 0) {
            while (ld_acq(&g_step_done) <= (unsigned)tt) { __nanosleep(64); }
        }
        __syncthreads();

        float acc[4][4][4] = {};
        mma_tile_pipe<true>(g_histH, g_histL, g_WfcH, g_WfcL,
                            m0, n0, Hsz, Hsz, 0, Hsz, acc, sm_u);

        const int lane = tid & 31, warp = tid >> 5;
        const int wm = warp >> 2, wn = warp & 3;
        const int grp = lane >> 2, tig = lane & 3;
#pragma unroll
        for (int mt = 0; mt < 4; mt++)
#pragma unroll
            for (int nt = 0; nt < 4; nt++) {
                int row = m0 + wm * 64 + mt * 16 + grp;
                int col = n0 + wn * 32 + nt * 8 + tig * 2;
                float* a = acc[mt][nt];
                if (col < Vsz) {
                    int b0r = row & 255, tt0 = row >> 8;
                    int b1r = (row + 8) & 255, tt1 = (row + 8) >> 8;
                    bool act0 = lengths[b0r] > tt0;
                    bool act1 = lengths[b1r] > tt1;
                    float* p0 = out + ((size_t)b0r * STEPS + tt0) * Vsz;
                    float* p1 = out + ((size_t)b1r * STEPS + tt1) * Vsz;
                    p0[col]     = act0 ? (a[0] + bfc[col])     : 0.f;
                    p0[col + 1] = act0 ? (a[1] + bfc[col + 1]) : 0.f;
                    p1[col]     = act1 ? (a[2] + bfc[col])     : 0.f;
                    p1[col + 1] = act1 ? (a[3] + bfc[col + 1]) : 0.f;
                }
            }
    }
}

// ---------------------------------------------------------------------------
// Host HMMA GEMM (precompute). EPI: 3 = tanh(+bias) fp32 out, 4 = +bias h16 out
// ---------------------------------------------------------------------------
template <int EPI>
__global__ __launch_bounds__(256) void mma_gemm(
    const h16* __restrict__ Ah, const h16* __restrict__ Al,
    const h16* __restrict__ Bh,
    const float* __restrict__ bias, void* __restrict__ Cv,
    int M, int N, int lda, int ldb, int kspl)
{
    const int m0 = blockIdx.y * 128;
    const int n0 = blockIdx.x * 128;
    const int tid = threadIdx.x;

    extern __shared__ __align__(16) char dsm[];
    unsigned sm_u = (unsigned)__cvta_generic_to_shared(dsm);

    const int lane = tid & 31, warp = tid >> 5;
    const int wm = warp >> 2, wn = warp & 3;
    const int grp = lane >> 2, tig = lane & 3;

    float acc[4][4][4] = {};
    mma_tile_pipe<false>(Ah, Al, Bh, nullptr, m0, n0, lda, ldb, 0, kspl, acc, sm_u);

#pragma unroll
    for (int mt = 0; mt < 4; mt++)
#pragma unroll
        for (int nt = 0; nt < 4; nt++) {
            int row = m0 + wm * 64 + mt * 16 + grp;
            int col = n0 + wn * 32 + nt * 8 + tig * 2;
            float* a = acc[mt][nt];
            if (EPI == 3) {
                float* C = (float*)Cv;
                C[(size_t)row * N + col]           = tanhf(a[0] + bias[col]);
                C[(size_t)row * N + col + 1]       = tanhf(a[1] + bias[col + 1]);
                C[(size_t)(row + 8) * N + col]     = tanhf(a[2] + bias[col]);
                C[(size_t)(row + 8) * N + col + 1] = tanhf(a[3] + bias[col + 1]);
            } else {
                h16* C = (h16*)Cv;
                C[(size_t)row * N + col]           = __float2half_rn(a[0] + bias[col]);
                C[(size_t)row * N + col + 1]       = __float2half_rn(a[1] + bias[col + 1]);
                C[(size_t)(row + 8) * N + col]     = __float2half_rn(a[2] + bias[col]);
                C[(size_t)(row + 8) * N + col + 1] = __float2half_rn(a[3] + bias[col + 1]);
            }
        }
}

// ---------------------------------------------------------------------------
// Merged conversion kernel
// ---------------------------------------------------------------------------
__global__ void convert_weights(
    const float* __restrict__ Wf, const float* __restrict__ Wh,
    const float* __restrict__ Wih, const float* __restrict__ Whh,
    const float* __restrict__ Wi_h, const float* __restrict__ Wi_c,
    const float* __restrict__ bi_h, const float* __restrict__ bi_c,
    const float* __restrict__ Wfc,
    const float* __restrict__ embW, const int* __restrict__ ids)
{
    const int stride = gridDim.x * blockDim.x;
    const int tid0 = blockIdx.x * blockDim.x + threadIdx.x;

    for (int i = tid0; i < Asz * Fsz; i += stride)
        g_WfH[i] = __float2half_rn(Wf[i]);
    for (int i = tid0; i < Asz * Hsz; i += stride)
        g_WhH[i] = __float2half_rn(Wh[i]);
    for (int i = tid0; i < G4 * GK2; i += stride) {
        int r = i / GK2, cc = i - r * GK2;
        float v = (cc < Fsz) ? Wih[(size_t)r * (Esz + Fsz) + Esz + cc]
                             : Whh[(size_t)r * Hsz + cc - Fsz];
        g_Wg2H[i] = __float2half_rn(v);
    }
    for (int i = tid0; i < G4 * Esz; i += stride) {
        int r = i >> 8, cc = i & 255;
        g_WihEH[i] = __float2half_rn(Wih[(size_t)r * (Esz + Fsz) + cc]);
    }
    for (int i = tid0; i < 1024 * Fsz; i += stride) {
        int r = i / Fsz, cc = i - r * Fsz;
        float v = (r < Hsz) ? Wi_h[(size_t)r * Fsz + cc] : Wi_c[(size_t)(r - Hsz) * Fsz + cc];
        g_WiH[i] = __float2half_rn(v);
    }
    for (int i = tid0; i < 1024; i += stride)
        g_bi[i] = (i < Hsz) ? bi_h[i] : bi_c[i - Hsz];
    for (int i = tid0; i < VPAD * Hsz; i += stride) {
        int r = i >> 9;
        float v = (r < Vsz) ? Wfc[i] : 0.f;
        split2(v, g_WfcH[i], g_WfcL[i]);
    }
    for (int i = tid0; i < MROWS * Esz; i += stride) {
        int r = i >> 8, e = i & 255;
        int tt = r >> 8, b = r & 255;
        int id = ids[b * Lsz + tt];
        split2(embW[(size_t)id * Esz + e], g_embAH[i], g_embAL[i]);
    }
}

// merged: mean + feats split (single feats pass)
__global__ void mean_split_feats(const float* __restrict__ feats)
{
    int b = blockIdx.x;
    for (int f = threadIdx.x; f < Fsz; f += blockDim.x) {
        float s = 0.f;
        for (int r = 0; r < Rsz; r++) {
            size_t idx = (size_t)(b * Rsz + r) * Fsz + f;
            float v = feats[idx];
            s += v;
            split2(v, g_featH[idx], g_featL[idx]);
        }
        split2(s * (1.0f / Rsz), g_meanH[b * Fsz + f], g_meanL[b * Fsz + f]);
    }
}

__global__ void init_state()
{
    int idx = blockIdx.x * blockDim.x + threadIdx.x;
    int b = idx >> 9, j = idx & 511;
    float h = g_h0c0[b * 1024 + j];
    float c = g_h0c0[b * 1024 + 512 + j];
    g_c[idx] = c;
    split2(h, g_xhH[b * GK2 + Fsz + j], g_xhL[b * GK2 + Fsz + j]);
    if (idx == 0) {
        g_step_done = 0;
        g_ticket = 0;
    }
    if (idx < 32) g_emb_done[idx] = 0;
}

// ---------------------------------------------------------------------------
extern "C" void kernel_launch(void* const* d_in, const int* in_sizes, int n_in,
                              void* d_out, int out_size)
{
    const float* feats   = (const float*)d_in[0];
    const int*   ids     = (const int*)  d_in[1];
    const int*   lengths = (const int*)  d_in[2];
    const float* embW    = (const float*)d_in[3];
    const float* Wf      = (const float*)d_in[4];
    const float* bf      = (const float*)d_in[5];
    const float* Wh      = (const float*)d_in[6];
    const float* bh      = (const float*)d_in[7];
    const float* Ws      = (const float*)d_in[8];
    const float* bs      = (const float*)d_in[9];
    const float* W_ih    = (const float*)d_in[10];
    const float* b_ih    = (const float*)d_in[11];
    const float* W_hh    = (const float*)d_in[12];
    const float* b_hh    = (const float*)d_in[13];
    const float* Wfc     = (const float*)d_in[14];
    const float* bfc     = (const float*)d_in[15];
    const float* Wi_h    = (const float*)d_in[16];
    const float* bi_h    = (const float*)d_in[17];
    const float* Wi_c    = (const float*)d_in[18];
    const float* bi_c    = (const float*)d_in[19];
    float* out = (float*)d_out;

    void *pv;
    cudaGetSymbolAddress(&pv, g_featH);  h16* featH = (h16*)pv;
    cudaGetSymbolAddress(&pv, g_featL);  h16* featL = (h16*)pv;
    cudaGetSymbolAddress(&pv, g_meanH);  h16* meanH = (h16*)pv;
    cudaGetSymbolAddress(&pv, g_meanL);  h16* meanL = (h16*)pv;
    cudaGetSymbolAddress(&pv, g_WfH);    h16* WfH = (h16*)pv;
    cudaGetSymbolAddress(&pv, g_WiH);    h16* WiH = (h16*)pv;
    cudaGetSymbolAddress(&pv, g_bi);     float* bi = (float*)pv;
    cudaGetSymbolAddress(&pv, g_h0c0);   float* h0c0 = (float*)pv;
    cudaGetSymbolAddress(&pv, g_fproj);  h16* fproj = (h16*)pv;

    cudaFuncSetAttribute(mma_gemm<3>, cudaFuncAttributeMaxDynamicSharedMemorySize, SMEM_DYN);
    cudaFuncSetAttribute(mma_gemm<4>, cudaFuncAttributeMaxDynamicSharedMemorySize, SMEM_DYN);
    cudaFuncSetAttribute(decoder_loop, cudaFuncAttributeMaxDynamicSharedMemorySize, SMEM_DYN);

    // ---- conversions ----
    mean_split_feats<<<Bsz, 256>>>(feats);
    convert_weights<<<592, 256>>>(Wf, Wh, W_ih, W_hh, Wi_h, Wi_c, bi_h, bi_c,
                                  Wfc, embW, ids);

    // ---- init state ----
    mma_gemm<3><<<dim3(8, 2, 1), 256, SMEM_DYN>>>(meanH, meanL, WiH, bi, h0c0,
                                                  Bsz, 1024, Fsz, Fsz, Fsz);
    init_state<<<(Bsz * Hsz) / 256, 256>>>();

    // ---- f_proj = feats @ Wf^T + bf (h16 output) ----
    mma_gemm<4><<<dim3(4, 98, 1), 256, SMEM_DYN>>>(featH, featL, WfH, bf, fproj,
                                                   Bsz * Rsz, Asz, Fsz, Fsz, Fsz);

    // ---- persistent recurrence + overlapped embproj & final FC ----
    decoder_loop<<<PALL, 256, SMEM_DYN>>>(Ws, bs, bh, b_ih, b_hh, bfc,
                                          lengths, out);
}